// round 1
// baseline (speedup 1.0000x reference)
#include <cuda_runtime.h>
#include <cuda_bf16.h>
#include <cstdint>

// Problem constants
#define BATCH 8
#define SEQ 1024
#define DIM 768
#define NHEAD 12
#define HDIM 64
#define MROWS (BATCH * SEQ)          // 8192
#define QKV_N (3 * DIM)              // 2304

// Scratch (allocation-free rule: __device__ globals)
__device__ float g_q[BATCH * NHEAD * SEQ * HDIM];    // [b,h,n,d]
__device__ float g_k[BATCH * NHEAD * SEQ * HDIM];
__device__ float g_v[BATCH * NHEAD * SEQ * HDIM];
__device__ float g_att[MROWS * DIM];                 // [b,n,h*d]

// ---------------------------------------------------------------------------
// Fast exp on the FMA pipe (avoids MUFU throughput wall: 100M exps in softmax).
// exp(x) = 2^(x*log2e); round-to-nearest split, degree-5 poly on [-0.5,0.5].
// Max rel err ~2e-6. Safe for x in [-inf, 0] (clamped at -87 -> no denormals).
// ---------------------------------------------------------------------------
__device__ __forceinline__ float fexp(float x) {
    x = fmaxf(x, -87.0f);
    float t = x * 1.4426950408889634f;
    int   ei = __float2int_rn(t);
    float f  = t - (float)ei;
    float p = 1.3333558e-3f;
    p = fmaf(p, f, 9.6181291e-3f);
    p = fmaf(p, f, 5.5504109e-2f);
    p = fmaf(p, f, 2.4022651e-1f);
    p = fmaf(p, f, 6.9314718e-1f);
    p = fmaf(p, f, 1.0f);
    return __int_as_float(__float_as_int(p) + (ei << 23));
}

// ---------------------------------------------------------------------------
// GEMM: C[m,o] = sum_k A[m,k] * B[o,k] (+ bias[o]) — both operands K-contiguous.
// 128x128 block tile, BK=16, 256 threads, 8x8 register microtile.
// ---------------------------------------------------------------------------
#define BM 128
#define BN 128
#define BK 16

struct GemmFrag { float acc[8][8]; int bm, bn, tx, ty; };

__device__ __forceinline__ void gemm_mainloop(
    const float* __restrict__ A, const float* __restrict__ B, int K,
    GemmFrag& fr)
{
    __shared__ float As[BK][BM + 4];
    __shared__ float Bs[BK][BN + 4];
    int tid = threadIdx.x;
    fr.tx = tid & 15;
    fr.ty = tid >> 4;
    fr.bm = blockIdx.y * BM;
    fr.bn = blockIdx.x * BN;
    #pragma unroll
    for (int i = 0; i < 8; i++)
        #pragma unroll
        for (int j = 0; j < 8; j++) fr.acc[i][j] = 0.f;

    for (int k0 = 0; k0 < K; k0 += BK) {
        #pragma unroll
        for (int i = 0; i < 2; i++) {
            int idx = tid + i * 256;          // 512 float4s per operand tile
            int row = idx >> 2;
            int kc  = (idx & 3) * 4;
            float4 a = *(const float4*)(A + (size_t)(fr.bm + row) * K + k0 + kc);
            As[kc + 0][row] = a.x; As[kc + 1][row] = a.y;
            As[kc + 2][row] = a.z; As[kc + 3][row] = a.w;
            float4 b = *(const float4*)(B + (size_t)(fr.bn + row) * K + k0 + kc);
            Bs[kc + 0][row] = b.x; Bs[kc + 1][row] = b.y;
            Bs[kc + 2][row] = b.z; Bs[kc + 3][row] = b.w;
        }
        __syncthreads();
        #pragma unroll
        for (int k = 0; k < BK; k++) {
            float4 a0 = *(const float4*)&As[k][fr.ty * 8];
            float4 a1 = *(const float4*)&As[k][fr.ty * 8 + 4];
            float4 b0 = *(const float4*)&Bs[k][fr.tx * 8];
            float4 b1 = *(const float4*)&Bs[k][fr.tx * 8 + 4];
            float ar[8] = {a0.x, a0.y, a0.z, a0.w, a1.x, a1.y, a1.z, a1.w};
            float br[8] = {b0.x, b0.y, b0.z, b0.w, b1.x, b1.y, b1.z, b1.w};
            #pragma unroll
            for (int i = 0; i < 8; i++)
                #pragma unroll
                for (int j = 0; j < 8; j++)
                    fr.acc[i][j] = fmaf(ar[i], br[j], fr.acc[i][j]);
        }
        __syncthreads();
    }
}

// GEMM 1: qkv = x @ w_qkv^T + b_qkv, scattered to g_q/g_k/g_v in [b,h,n,d]
__global__ __launch_bounds__(256)
void gemm_qkv_kernel(const float* __restrict__ x,
                     const float* __restrict__ w,
                     const float* __restrict__ bias)
{
    GemmFrag fr;
    gemm_mainloop(x, w, DIM, fr);
    #pragma unroll
    for (int i = 0; i < 8; i++) {
        int m  = fr.bm + fr.ty * 8 + i;
        int bb = m >> 10;
        int nn = m & 1023;
        #pragma unroll
        for (int j = 0; j < 8; j += 4) {
            int o = fr.bn + fr.tx * 8 + j;
            float4 v;
            v.x = fr.acc[i][j + 0] + bias[o + 0];
            v.y = fr.acc[i][j + 1] + bias[o + 1];
            v.z = fr.acc[i][j + 2] + bias[o + 2];
            v.w = fr.acc[i][j + 3] + bias[o + 3];
            int s = o / DIM;                 // 0=q, 1=k, 2=v
            int r = o - s * DIM;
            int h = r >> 6;
            int d = r & 63;
            float* dst = (s == 0) ? g_q : (s == 1) ? g_k : g_v;
            *(float4*)&dst[(((bb * NHEAD + h) << 10) + nn) * HDIM + d] = v;
        }
    }
}

// GEMM 2: out = att @ w_proj^T + b_proj
__global__ __launch_bounds__(256)
void gemm_proj_kernel(const float* __restrict__ w,
                      const float* __restrict__ bias,
                      float* __restrict__ out)
{
    GemmFrag fr;
    gemm_mainloop(g_att, w, DIM, fr);
    #pragma unroll
    for (int i = 0; i < 8; i++) {
        int m = fr.bm + fr.ty * 8 + i;
        #pragma unroll
        for (int j = 0; j < 8; j += 4) {
            int o = fr.bn + fr.tx * 8 + j;
            float4 v;
            v.x = fr.acc[i][j + 0] + bias[o + 0];
            v.y = fr.acc[i][j + 1] + bias[o + 1];
            v.z = fr.acc[i][j + 2] + bias[o + 2];
            v.w = fr.acc[i][j + 3] + bias[o + 3];
            *(float4*)&out[(size_t)m * DIM + o] = v;
        }
    }
}

// ---------------------------------------------------------------------------
// Flash-style attention: grid (b*h=96, seq/128=8), 128 threads.
// One thread per query row; q[64] and o[64] in registers; K/V tiles (64x64)
// staged in smem; online softmax with rare-branch max rescale.
// ---------------------------------------------------------------------------
#define AT_BC 64

__global__ __launch_bounds__(128)
void attn_kernel()
{
    __shared__ float sm[2 * AT_BC * HDIM];   // 8192 floats: Ks | Vs
    float* Ks = sm;
    float* Vs = sm + AT_BC * HDIM;

    int bh  = blockIdx.x;                    // b*NHEAD + h
    int bb  = bh / NHEAD;
    int h   = bh - bb * NHEAD;
    int tid = threadIdx.x;
    int qn  = blockIdx.y * 128 + tid;        // token index of this thread's row

    const float* qbase = g_q + (size_t)bh * SEQ * HDIM;
    const float* kbase = g_k + (size_t)bh * SEQ * HDIM;
    const float* vbase = g_v + (size_t)bh * SEQ * HDIM;

    // Stage this block's 128x64 Q tile through smem (coalesced), grab own row.
    {
        const float4* src = (const float4*)(qbase + (size_t)blockIdx.y * 128 * HDIM);
        float4* dst = (float4*)sm;
        #pragma unroll
        for (int i = 0; i < 16; i++) dst[tid + i * 128] = src[tid + i * 128];
    }
    __syncthreads();
    float q[HDIM];
    #pragma unroll
    for (int d = 0; d < HDIM; d++) q[d] = sm[tid * HDIM + d];
    __syncthreads();

    float o[HDIM];
    #pragma unroll
    for (int d = 0; d < HDIM; d++) o[d] = 0.f;
    float mrow = -1e30f, l = 0.f;

    for (int t = 0; t < SEQ / AT_BC; t++) {
        // K/V tiles are contiguous 4096-float blocks in [b,h,n,d] layout
        const float4* ksrc = (const float4*)(kbase + t * AT_BC * HDIM);
        const float4* vsrc = (const float4*)(vbase + t * AT_BC * HDIM);
        float4* kdst = (float4*)Ks;
        float4* vdst = (float4*)Vs;
        #pragma unroll
        for (int i = 0; i < 8; i++) {
            kdst[tid + i * 128] = ksrc[tid + i * 128];
            vdst[tid + i * 128] = vsrc[tid + i * 128];
        }
        __syncthreads();

        #pragma unroll 1
        for (int c = 0; c < AT_BC; c++) {
            const float4* kc = (const float4*)(Ks + c * HDIM);
            float s = 0.f;
            #pragma unroll
            for (int j = 0; j < 16; j++) {
                float4 kk = kc[j];
                s = fmaf(q[4 * j + 0], kk.x, s);
                s = fmaf(q[4 * j + 1], kk.y, s);
                s = fmaf(q[4 * j + 2], kk.z, s);
                s = fmaf(q[4 * j + 3], kk.w, s);
            }
            s *= 0.125f;                     // HEAD_DIM^-0.5
            if (s > mrow) {                  // rare after warmup (~H_n times)
                float corr = fexp(mrow - s);
                l *= corr;
                #pragma unroll
                for (int d = 0; d < HDIM; d++) o[d] *= corr;
                mrow = s;
            }
            float p = fexp(s - mrow);
            l += p;
            const float4* vc = (const float4*)(Vs + c * HDIM);
            #pragma unroll
            for (int j = 0; j < 16; j++) {
                float4 vv = vc[j];
                o[4 * j + 0] = fmaf(p, vv.x, o[4 * j + 0]);
                o[4 * j + 1] = fmaf(p, vv.y, o[4 * j + 1]);
                o[4 * j + 2] = fmaf(p, vv.z, o[4 * j + 2]);
                o[4 * j + 3] = fmaf(p, vv.w, o[4 * j + 3]);
            }
        }
        __syncthreads();
    }

    float inv = 1.0f / l;
    float* dst = g_att + ((size_t)bb * SEQ + qn) * DIM + h * HDIM;
    #pragma unroll
    for (int d = 0; d < HDIM; d += 4) {
        float4 v;
        v.x = o[d + 0] * inv;
        v.y = o[d + 1] * inv;
        v.z = o[d + 2] * inv;
        v.w = o[d + 3] * inv;
        *(float4*)&dst[d] = v;
    }
}

// ---------------------------------------------------------------------------
extern "C" void kernel_launch(void* const* d_in, const int* in_sizes, int n_in,
                              void* d_out, int out_size)
{
    const float* x      = (const float*)d_in[0];
    const float* w_qkv  = (const float*)d_in[1];
    const float* b_qkv  = (const float*)d_in[2];
    const float* w_proj = (const float*)d_in[3];
    const float* b_proj = (const float*)d_in[4];
    float* out = (float*)d_out;

    gemm_qkv_kernel<<<dim3(QKV_N / BN, MROWS / BM), 256>>>(x, w_qkv, b_qkv);
    attn_kernel<<<dim3(BATCH * NHEAD, SEQ / 128), 128>>>();
    gemm_proj_kernel<<<dim3(DIM / BN, MROWS / BM), 256>>>(w_proj, b_proj, out);
}

// round 3
// speedup vs baseline: 1.2830x; 1.2830x over previous
#include <cuda_runtime.h>
#include <cuda_bf16.h>
#include <cstdint>

// Problem constants
#define BATCH 8
#define SEQ 1024
#define DIM 768
#define NHEAD 12
#define HDIM 64
#define MROWS (BATCH * SEQ)          // 8192
#define QKV_N (3 * DIM)              // 2304

// Scratch (allocation-free rule: __device__ globals)
__device__ float g_q[BATCH * NHEAD * SEQ * HDIM];    // [b,h,n,d]
__device__ float g_k[BATCH * NHEAD * SEQ * HDIM];
__device__ float g_v[BATCH * NHEAD * SEQ * HDIM];
__device__ float g_att[MROWS * DIM];                 // [b,n,h*d]

// ---------------------------------------------------------------------------
// PTX helpers: warp-level tensor core path (baseline PTX, compiles for sm_103
// WITHOUT the 'a' feature suffix — tcgen05 is rejected by this toolchain).
// ---------------------------------------------------------------------------
__device__ __forceinline__ uint32_t smem_to_u32(const void* p) {
    uint32_t a;
    asm("{ .reg .u64 t; cvta.to.shared.u64 t, %1; cvt.u32.u64 %0, t; }"
        : "=r"(a) : "l"(p));
    return a;
}

// cvt two fp32 -> packed bf16x2 (low half = first arg)
#define CVT_BF16X2_F32(result, a, b) \
    asm("cvt.rn.bf16x2.f32 %0, %1, %2;" : "=r"(result) : "f"(b), "f"(a))

#define LDSM_X4(r0, r1, r2, r3, addr) \
    asm volatile("ldmatrix.sync.aligned.m8n8.x4.shared.b16 {%0,%1,%2,%3}, [%4];" \
        : "=r"(r0), "=r"(r1), "=r"(r2), "=r"(r3) : "r"(addr))
#define LDSM_X2(r0, r1, addr) \
    asm volatile("ldmatrix.sync.aligned.m8n8.x2.shared.b16 {%0,%1}, [%2];" \
        : "=r"(r0), "=r"(r1) : "r"(addr))

#define MMA16816(d, a0, a1, a2, a3, b0, b1) \
    asm volatile("mma.sync.aligned.m16n8k16.row.col.f32.bf16.bf16.f32 " \
        "{%0,%1,%2,%3}, {%4,%5,%6,%7}, {%8,%9}, {%0,%1,%2,%3};" \
        : "+f"((d)[0]), "+f"((d)[1]), "+f"((d)[2]), "+f"((d)[3]) \
        : "r"(a0), "r"(a1), "r"(a2), "r"(a3), "r"(b0), "r"(b1))

// ---------------------------------------------------------------------------
// Split-bf16 mma.sync GEMM: C[m,o] = sum_k A[m,k]*B[o,k] (+bias)
// fp32 -> (hi, lo) bf16; hh + hl + lh MMAs into fp32 acc (lo*lo dropped,
// ~1.5e-5 rel). CTA tile 128x128, 8 warps (64x32 each), BK=32 fp32 per chunk.
// Smem rows padded to 40 bf16 (80 B) -> conflict-free ldmatrix.
// ---------------------------------------------------------------------------
#define BKF 32                        // fp32 K elements per chunk
#define NCH (DIM / BKF)               // 24 chunks (K=768)
#define LDB 80                        // smem row stride in BYTES (40 bf16)
#define TILE_B (128 * LDB)            // 10240 bytes per operand tile
#define SOFF_AH 0
#define SOFF_AL (1 * TILE_B)
#define SOFF_BH (2 * TILE_B)
#define SOFF_BL (3 * TILE_B)
#define GEMM_SMEM_BYTES (4 * TILE_B)  // 40960 (< 48KB static limit)

// Convert float4 -> hi uint2 / lo uint2 (4 bf16 each)
__device__ __forceinline__ void split4(float4 x, uint2& hi, uint2& lo) {
    uint32_t h01, h23;
    CVT_BF16X2_F32(h01, x.x, x.y);
    CVT_BF16X2_F32(h23, x.z, x.w);
    float l0 = x.x - __uint_as_float(h01 << 16);
    float l1 = x.y - __uint_as_float(h01 & 0xffff0000u);
    float l2 = x.z - __uint_as_float(h23 << 16);
    float l3 = x.w - __uint_as_float(h23 & 0xffff0000u);
    uint32_t q01, q23;
    CVT_BF16X2_F32(q01, l0, l1);
    CVT_BF16X2_F32(q23, l2, l3);
    hi = make_uint2(h01, h23);
    lo = make_uint2(q01, q23);
}

// Mainloop: fills acc[mi][nj][4] for this thread's warp tile.
__device__ __forceinline__ void mma_mainloop(
    const float* __restrict__ A, const float* __restrict__ B,
    int bm, int bn, char* smem, float acc[4][4][4])
{
    const int tid  = threadIdx.x;
    const int lane = tid & 31;
    const int wid  = tid >> 5;
    const int wm   = (wid >> 2) * 64;   // warp row offset within CTA tile
    const int wn   = (wid & 3) * 32;    // warp col offset
    const uint32_t sb = smem_to_u32(smem);

    #pragma unroll
    for (int mi = 0; mi < 4; mi++)
        #pragma unroll
        for (int nj = 0; nj < 4; nj++)
            #pragma unroll
            for (int r = 0; r < 4; r++) acc[mi][nj][r] = 0.f;

    // ldmatrix source addresses (fixed per thread, advance by k16*32 bytes)
    const uint32_t a_row = (lane & 7) + ((lane >> 3) & 1) * 8;  // within 16-row block
    const uint32_t a_kb  = ((lane >> 4) & 1) * 16;              // 0 or 16 bytes
    const uint32_t b_row = lane & 7;
    const uint32_t b_kb  = ((lane >> 3) & 1) * 16;

    for (int ch = 0; ch < NCH; ch++) {
        // Stage: global fp32 -> registers -> hi/lo bf16 smem tiles.
        float4 av[4], bv[4];
        int rowv[4], c4v[4];
        #pragma unroll
        for (int i = 0; i < 4; i++) {
            int idx = tid + i * 256;        // 1024 float4 per operand tile
            rowv[i] = idx >> 3;             // 8 float4 per 32-float row
            c4v[i]  = idx & 7;
            av[i] = *(const float4*)(A + (size_t)(bm + rowv[i]) * DIM + ch * BKF + c4v[i] * 4);
            bv[i] = *(const float4*)(B + (size_t)(bn + rowv[i]) * DIM + ch * BKF + c4v[i] * 4);
        }
        __syncthreads();   // previous chunk's ldmatrix reads complete
        #pragma unroll
        for (int i = 0; i < 4; i++) {
            uint2 hi, lo;
            uint32_t boff = (uint32_t)(rowv[i] * LDB + c4v[i] * 8);
            split4(av[i], hi, lo);
            *(uint2*)(smem + SOFF_AH + boff) = hi;
            *(uint2*)(smem + SOFF_AL + boff) = lo;
            split4(bv[i], hi, lo);
            *(uint2*)(smem + SOFF_BH + boff) = hi;
            *(uint2*)(smem + SOFF_BL + boff) = lo;
        }
        __syncthreads();

        #pragma unroll
        for (int k16 = 0; k16 < 2; k16++) {
            const uint32_t kb = k16 * 32;
            uint32_t ah[4][4], al[4][4], bh[4][2], bl[4][2];
            #pragma unroll
            for (int mi = 0; mi < 4; mi++) {
                uint32_t ad = sb + SOFF_AH + (wm + mi * 16 + a_row) * LDB + kb + a_kb;
                LDSM_X4(ah[mi][0], ah[mi][1], ah[mi][2], ah[mi][3], ad);
                LDSM_X4(al[mi][0], al[mi][1], al[mi][2], al[mi][3], ad + TILE_B);
            }
            #pragma unroll
            for (int nj = 0; nj < 4; nj++) {
                uint32_t bd = sb + SOFF_BH + (wn + nj * 8 + b_row) * LDB + kb + b_kb;
                LDSM_X2(bh[nj][0], bh[nj][1], bd);
                LDSM_X2(bl[nj][0], bl[nj][1], bd + TILE_B);
            }
            #pragma unroll
            for (int mi = 0; mi < 4; mi++)
                #pragma unroll
                for (int nj = 0; nj < 4; nj++) {
                    MMA16816(acc[mi][nj], ah[mi][0], ah[mi][1], ah[mi][2], ah[mi][3],
                             bh[nj][0], bh[nj][1]);
                    MMA16816(acc[mi][nj], ah[mi][0], ah[mi][1], ah[mi][2], ah[mi][3],
                             bl[nj][0], bl[nj][1]);
                    MMA16816(acc[mi][nj], al[mi][0], al[mi][1], al[mi][2], al[mi][3],
                             bh[nj][0], bh[nj][1]);
                }
        }
    }
}

// GEMM 1: qkv = x @ w_qkv^T + b_qkv, scattered to g_q/g_k/g_v in [b,h,n,d]
__global__ __launch_bounds__(256, 1)
void gemm_qkv_mma(const float* __restrict__ x,
                  const float* __restrict__ w,
                  const float* __restrict__ bias)
{
    __shared__ __align__(128) char smem[GEMM_SMEM_BYTES];
    const int bm = blockIdx.y * 128, bn = blockIdx.x * 128;
    float acc[4][4][4];
    mma_mainloop(x, w, bm, bn, smem, acc);

    const int lane = threadIdx.x & 31;
    const int wid  = threadIdx.x >> 5;
    const int wm   = (wid >> 2) * 64;
    const int wn   = (wid & 3) * 32;
    const int s = blockIdx.x / 6;                 // 6 N-tiles per 768 -> q/k/v
    float* dstbase = (s == 0) ? g_q : (s == 1) ? g_k : g_v;

    #pragma unroll
    for (int mi = 0; mi < 4; mi++) {
        int m0 = bm + wm + mi * 16 + (lane >> 2);
        #pragma unroll
        for (int nj = 0; nj < 4; nj++) {
            int o  = bn + wn + nj * 8 + (lane & 3) * 2;
            int rl = o - s * DIM;
            int h = rl >> 6, d = rl & 63;
            float b0 = bias[o], b1 = bias[o + 1];
            #pragma unroll
            for (int rr = 0; rr < 2; rr++) {
                int m  = m0 + rr * 8;
                int bb = m >> 10, nn = m & 1023;
                float2 v = make_float2(acc[mi][nj][rr * 2 + 0] + b0,
                                       acc[mi][nj][rr * 2 + 1] + b1);
                *(float2*)&dstbase[((size_t)(bb * NHEAD + h) * SEQ + nn) * HDIM + d] = v;
            }
        }
    }
}

// GEMM 2: out = g_att @ w_proj^T + b_proj
__global__ __launch_bounds__(256, 1)
void gemm_proj_mma(const float* __restrict__ w,
                   const float* __restrict__ bias,
                   float* __restrict__ out)
{
    __shared__ __align__(128) char smem[GEMM_SMEM_BYTES];
    const int bm = blockIdx.y * 128, bn = blockIdx.x * 128;
    float acc[4][4][4];
    mma_mainloop(g_att, w, bm, bn, smem, acc);

    const int lane = threadIdx.x & 31;
    const int wid  = threadIdx.x >> 5;
    const int wm   = (wid >> 2) * 64;
    const int wn   = (wid & 3) * 32;

    #pragma unroll
    for (int mi = 0; mi < 4; mi++) {
        int m0 = bm + wm + mi * 16 + (lane >> 2);
        #pragma unroll
        for (int nj = 0; nj < 4; nj++) {
            int o = bn + wn + nj * 8 + (lane & 3) * 2;
            float b0 = bias[o], b1 = bias[o + 1];
            #pragma unroll
            for (int rr = 0; rr < 2; rr++) {
                int m = m0 + rr * 8;
                float2 v = make_float2(acc[mi][nj][rr * 2 + 0] + b0,
                                       acc[mi][nj][rr * 2 + 1] + b1);
                *(float2*)&out[(size_t)m * DIM + o] = v;
            }
        }
    }
}

// ---------------------------------------------------------------------------
// Fast exp on the FMA pipe (avoids MUFU throughput wall in softmax).
// ---------------------------------------------------------------------------
__device__ __forceinline__ float fexp(float x) {
    x = fmaxf(x, -87.0f);
    float t = x * 1.4426950408889634f;
    int   ei = __float2int_rn(t);
    float f  = t - (float)ei;
    float p = 1.3333558e-3f;
    p = fmaf(p, f, 9.6181291e-3f);
    p = fmaf(p, f, 5.5504109e-2f);
    p = fmaf(p, f, 2.4022651e-1f);
    p = fmaf(p, f, 6.9314718e-1f);
    p = fmaf(p, f, 1.0f);
    return __int_as_float(__float_as_int(p) + (ei << 23));
}

// ---------------------------------------------------------------------------
// Flash-style attention: grid (b*h=96, seq/128=8), 128 threads.
// One thread per query row; q[64] and o[64] in registers; K/V tiles (64x64)
// staged in smem; online softmax with rare-branch max rescale.
// ---------------------------------------------------------------------------
#define AT_BC 64

__global__ __launch_bounds__(128)
void attn_kernel()
{
    __shared__ float sm[2 * AT_BC * HDIM];   // 8192 floats: Ks | Vs
    float* Ks = sm;
    float* Vs = sm + AT_BC * HDIM;

    int bh  = blockIdx.x;                    // b*NHEAD + h
    int bb  = bh / NHEAD;
    int h   = bh - bb * NHEAD;
    int tid = threadIdx.x;
    int qn  = blockIdx.y * 128 + tid;

    const float* qbase = g_q + (size_t)bh * SEQ * HDIM;
    const float* kbase = g_k + (size_t)bh * SEQ * HDIM;
    const float* vbase = g_v + (size_t)bh * SEQ * HDIM;

    {
        const float4* src = (const float4*)(qbase + (size_t)blockIdx.y * 128 * HDIM);
        float4* dst = (float4*)sm;
        #pragma unroll
        for (int i = 0; i < 16; i++) dst[tid + i * 128] = src[tid + i * 128];
    }
    __syncthreads();
    float q[HDIM];
    #pragma unroll
    for (int d = 0; d < HDIM; d++) q[d] = sm[tid * HDIM + d];
    __syncthreads();

    float o[HDIM];
    #pragma unroll
    for (int d = 0; d < HDIM; d++) o[d] = 0.f;
    float mrow = -1e30f, l = 0.f;

    for (int t = 0; t < SEQ / AT_BC; t++) {
        const float4* ksrc = (const float4*)(kbase + t * AT_BC * HDIM);
        const float4* vsrc = (const float4*)(vbase + t * AT_BC * HDIM);
        float4* kdst = (float4*)Ks;
        float4* vdst = (float4*)Vs;
        #pragma unroll
        for (int i = 0; i < 8; i++) {
            kdst[tid + i * 128] = ksrc[tid + i * 128];
            vdst[tid + i * 128] = vsrc[tid + i * 128];
        }
        __syncthreads();

        #pragma unroll 1
        for (int c = 0; c < AT_BC; c++) {
            const float4* kc = (const float4*)(Ks + c * HDIM);
            float s = 0.f;
            #pragma unroll
            for (int j = 0; j < 16; j++) {
                float4 kk = kc[j];
                s = fmaf(q[4 * j + 0], kk.x, s);
                s = fmaf(q[4 * j + 1], kk.y, s);
                s = fmaf(q[4 * j + 2], kk.z, s);
                s = fmaf(q[4 * j + 3], kk.w, s);
            }
            s *= 0.125f;
            if (s > mrow) {
                float corr = fexp(mrow - s);
                l *= corr;
                #pragma unroll
                for (int d = 0; d < HDIM; d++) o[d] *= corr;
                mrow = s;
            }
            float p = fexp(s - mrow);
            l += p;
            const float4* vc = (const float4*)(Vs + c * HDIM);
            #pragma unroll
            for (int j = 0; j < 16; j++) {
                float4 vv = vc[j];
                o[4 * j + 0] = fmaf(p, vv.x, o[4 * j + 0]);
                o[4 * j + 1] = fmaf(p, vv.y, o[4 * j + 1]);
                o[4 * j + 2] = fmaf(p, vv.z, o[4 * j + 2]);
                o[4 * j + 3] = fmaf(p, vv.w, o[4 * j + 3]);
            }
        }
        __syncthreads();
    }

    float inv = 1.0f / l;
    float* dst = g_att + ((size_t)bb * SEQ + qn) * DIM + h * HDIM;
    #pragma unroll
    for (int d = 0; d < HDIM; d += 4) {
        float4 v;
        v.x = o[d + 0] * inv;
        v.y = o[d + 1] * inv;
        v.z = o[d + 2] * inv;
        v.w = o[d + 3] * inv;
        *(float4*)&dst[d] = v;
    }
}

// ---------------------------------------------------------------------------
extern "C" void kernel_launch(void* const* d_in, const int* in_sizes, int n_in,
                              void* d_out, int out_size)
{
    const float* x      = (const float*)d_in[0];
    const float* w_qkv  = (const float*)d_in[1];
    const float* b_qkv  = (const float*)d_in[2];
    const float* w_proj = (const float*)d_in[3];
    const float* b_proj = (const float*)d_in[4];
    float* out = (float*)d_out;

    gemm_qkv_mma<<<dim3(QKV_N / 128, MROWS / 128), 256>>>(x, w_qkv, b_qkv);
    attn_kernel<<<dim3(BATCH * NHEAD, SEQ / 128), 128>>>();
    gemm_proj_mma<<<dim3(DIM / 128, MROWS / 128), 256>>>(w_proj, b_proj, out);
}

// round 4
// speedup vs baseline: 2.3451x; 1.8278x over previous
#include <cuda_runtime.h>
#include <cuda_bf16.h>
#include <cstdint>

// Problem constants
#define BATCH 8
#define SEQ 1024
#define DIM 768
#define NHEAD 12
#define HDIM 64
#define MROWS (BATCH * SEQ)          // 8192
#define QKV_N (3 * DIM)              // 2304
#define QKV_ELEMS (BATCH * NHEAD * SEQ * HDIM)

// Scratch (allocation-free rule: __device__ globals).
// Q/K/V stored as split bf16 hi/lo pairs, [b,h,n,d]; Q pre-scaled by 0.125.
__device__ __nv_bfloat16 g_qh[QKV_ELEMS], g_ql[QKV_ELEMS];
__device__ __nv_bfloat16 g_kh[QKV_ELEMS], g_kl[QKV_ELEMS];
__device__ __nv_bfloat16 g_vh[QKV_ELEMS], g_vl[QKV_ELEMS];
__device__ float g_att[MROWS * DIM];                 // [b,n,h*d]

// ---------------------------------------------------------------------------
// PTX helpers (baseline PTX only — tcgen05 rejected by this toolchain's sm_103)
// ---------------------------------------------------------------------------
__device__ __forceinline__ uint32_t smem_to_u32(const void* p) {
    uint32_t a;
    asm("{ .reg .u64 t; cvta.to.shared.u64 t, %1; cvt.u32.u64 %0, t; }"
        : "=r"(a) : "l"(p));
    return a;
}

// packs: result = {lo half: a, hi half: b}
#define CVT_BF16X2_F32(result, a, b) \
    asm("cvt.rn.bf16x2.f32 %0, %1, %2;" : "=r"(result) : "f"(b), "f"(a))

#define LDSM_X4(r0, r1, r2, r3, addr) \
    asm volatile("ldmatrix.sync.aligned.m8n8.x4.shared.b16 {%0,%1,%2,%3}, [%4];" \
        : "=r"(r0), "=r"(r1), "=r"(r2), "=r"(r3) : "r"(addr))
#define LDSM_X2(r0, r1, addr) \
    asm volatile("ldmatrix.sync.aligned.m8n8.x2.shared.b16 {%0,%1}, [%2];" \
        : "=r"(r0), "=r"(r1) : "r"(addr))
#define LDSM_X2_T(r0, r1, addr) \
    asm volatile("ldmatrix.sync.aligned.m8n8.x2.trans.shared.b16 {%0,%1}, [%2];" \
        : "=r"(r0), "=r"(r1) : "r"(addr))

#define MMA16816(d, a0, a1, a2, a3, b0, b1) \
    asm volatile("mma.sync.aligned.m16n8k16.row.col.f32.bf16.bf16.f32 " \
        "{%0,%1,%2,%3}, {%4,%5,%6,%7}, {%8,%9}, {%0,%1,%2,%3};" \
        : "+f"((d)[0]), "+f"((d)[1]), "+f"((d)[2]), "+f"((d)[3]) \
        : "r"(a0), "r"(a1), "r"(a2), "r"(a3), "r"(b0), "r"(b1))

// split two fp32 into bf16 hi pair + lo (residual) pair
__device__ __forceinline__ void pack_split(float a, float b,
                                           uint32_t& hi, uint32_t& lo) {
    CVT_BF16X2_F32(hi, a, b);
    float ra = a - __uint_as_float(hi << 16);
    float rb = b - __uint_as_float(hi & 0xffff0000u);
    CVT_BF16X2_F32(lo, ra, rb);
}

// ---------------------------------------------------------------------------
// Fast exp on the FMA pipe.
// ---------------------------------------------------------------------------
__device__ __forceinline__ float fexp(float x) {
    x = fmaxf(x, -87.0f);
    float t = x * 1.4426950408889634f;
    int   ei = __float2int_rn(t);
    float f  = t - (float)ei;
    float p = 1.3333558e-3f;
    p = fmaf(p, f, 9.6181291e-3f);
    p = fmaf(p, f, 5.5504109e-2f);
    p = fmaf(p, f, 2.4022651e-1f);
    p = fmaf(p, f, 6.9314718e-1f);
    p = fmaf(p, f, 1.0f);
    return __int_as_float(__float_as_int(p) + (ei << 23));
}

// ---------------------------------------------------------------------------
// Split-bf16 mma.sync GEMM (unchanged mainloop from R3)
// ---------------------------------------------------------------------------
#define BKF 32
#define NCH (DIM / BKF)
#define LDB 80
#define TILE_B (128 * LDB)
#define SOFF_AH 0
#define SOFF_AL (1 * TILE_B)
#define SOFF_BH (2 * TILE_B)
#define SOFF_BL (3 * TILE_B)
#define GEMM_SMEM_BYTES (4 * TILE_B)

__device__ __forceinline__ void split4(float4 x, uint2& hi, uint2& lo) {
    uint32_t h01, h23;
    CVT_BF16X2_F32(h01, x.x, x.y);
    CVT_BF16X2_F32(h23, x.z, x.w);
    float l0 = x.x - __uint_as_float(h01 << 16);
    float l1 = x.y - __uint_as_float(h01 & 0xffff0000u);
    float l2 = x.z - __uint_as_float(h23 << 16);
    float l3 = x.w - __uint_as_float(h23 & 0xffff0000u);
    uint32_t q01, q23;
    CVT_BF16X2_F32(q01, l0, l1);
    CVT_BF16X2_F32(q23, l2, l3);
    hi = make_uint2(h01, h23);
    lo = make_uint2(q01, q23);
}

__device__ __forceinline__ void mma_mainloop(
    const float* __restrict__ A, const float* __restrict__ B,
    int bm, int bn, char* smem, float acc[4][4][4])
{
    const int tid  = threadIdx.x;
    const int lane = tid & 31;
    const int wid  = tid >> 5;
    const int wm   = (wid >> 2) * 64;
    const int wn   = (wid & 3) * 32;
    const uint32_t sb = smem_to_u32(smem);

    #pragma unroll
    for (int mi = 0; mi < 4; mi++)
        #pragma unroll
        for (int nj = 0; nj < 4; nj++)
            #pragma unroll
            for (int r = 0; r < 4; r++) acc[mi][nj][r] = 0.f;

    const uint32_t a_row = (lane & 7) + ((lane >> 3) & 1) * 8;
    const uint32_t a_kb  = ((lane >> 4) & 1) * 16;
    const uint32_t b_row = lane & 7;
    const uint32_t b_kb  = ((lane >> 3) & 1) * 16;

    for (int ch = 0; ch < NCH; ch++) {
        float4 av[4], bv[4];
        int rowv[4], c4v[4];
        #pragma unroll
        for (int i = 0; i < 4; i++) {
            int idx = tid + i * 256;
            rowv[i] = idx >> 3;
            c4v[i]  = idx & 7;
            av[i] = *(const float4*)(A + (size_t)(bm + rowv[i]) * DIM + ch * BKF + c4v[i] * 4);
            bv[i] = *(const float4*)(B + (size_t)(bn + rowv[i]) * DIM + ch * BKF + c4v[i] * 4);
        }
        __syncthreads();
        #pragma unroll
        for (int i = 0; i < 4; i++) {
            uint2 hi, lo;
            uint32_t boff = (uint32_t)(rowv[i] * LDB + c4v[i] * 8);
            split4(av[i], hi, lo);
            *(uint2*)(smem + SOFF_AH + boff) = hi;
            *(uint2*)(smem + SOFF_AL + boff) = lo;
            split4(bv[i], hi, lo);
            *(uint2*)(smem + SOFF_BH + boff) = hi;
            *(uint2*)(smem + SOFF_BL + boff) = lo;
        }
        __syncthreads();

        #pragma unroll
        for (int k16 = 0; k16 < 2; k16++) {
            const uint32_t kb = k16 * 32;
            uint32_t ah[4][4], al[4][4], bh2[4][2], bl2[4][2];
            #pragma unroll
            for (int mi = 0; mi < 4; mi++) {
                uint32_t ad = sb + SOFF_AH + (wm + mi * 16 + a_row) * LDB + kb + a_kb;
                LDSM_X4(ah[mi][0], ah[mi][1], ah[mi][2], ah[mi][3], ad);
                LDSM_X4(al[mi][0], al[mi][1], al[mi][2], al[mi][3], ad + TILE_B);
            }
            #pragma unroll
            for (int nj = 0; nj < 4; nj++) {
                uint32_t bd = sb + SOFF_BH + (wn + nj * 8 + b_row) * LDB + kb + b_kb;
                LDSM_X2(bh2[nj][0], bh2[nj][1], bd);
                LDSM_X2(bl2[nj][0], bl2[nj][1], bd + TILE_B);
            }
            #pragma unroll
            for (int mi = 0; mi < 4; mi++)
                #pragma unroll
                for (int nj = 0; nj < 4; nj++) {
                    MMA16816(acc[mi][nj], ah[mi][0], ah[mi][1], ah[mi][2], ah[mi][3],
                             bh2[nj][0], bh2[nj][1]);
                    MMA16816(acc[mi][nj], ah[mi][0], ah[mi][1], ah[mi][2], ah[mi][3],
                             bl2[nj][0], bl2[nj][1]);
                    MMA16816(acc[mi][nj], al[mi][0], al[mi][1], al[mi][2], al[mi][3],
                             bh2[nj][0], bh2[nj][1]);
                }
        }
    }
}

// GEMM 1: qkv = x @ w_qkv^T + b_qkv -> split bf16 hi/lo in [b,h,n,d]; Q *= 0.125
__global__ __launch_bounds__(256, 1)
void gemm_qkv_mma(const float* __restrict__ x,
                  const float* __restrict__ w,
                  const float* __restrict__ bias)
{
    __shared__ __align__(128) char smem[GEMM_SMEM_BYTES];
    const int bm = blockIdx.y * 128, bn = blockIdx.x * 128;
    float acc[4][4][4];
    mma_mainloop(x, w, bm, bn, smem, acc);

    const int lane = threadIdx.x & 31;
    const int wid  = threadIdx.x >> 5;
    const int wm   = (wid >> 2) * 64;
    const int wn   = (wid & 3) * 32;
    const int s = blockIdx.x / 6;                 // 0=q, 1=k, 2=v
    __nv_bfloat16* hb = (s == 0) ? g_qh : (s == 1) ? g_kh : g_vh;
    __nv_bfloat16* lb = (s == 0) ? g_ql : (s == 1) ? g_kl : g_vl;
    const float sc = (s == 0) ? 0.125f : 1.0f;    // fold score scale into Q

    #pragma unroll
    for (int mi = 0; mi < 4; mi++) {
        int m0 = bm + wm + mi * 16 + (lane >> 2);
        #pragma unroll
        for (int nj = 0; nj < 4; nj++) {
            int o  = bn + wn + nj * 8 + (lane & 3) * 2;
            int rl = o - s * DIM;
            int h = rl >> 6, d = rl & 63;
            float b0 = bias[o], b1 = bias[o + 1];
            #pragma unroll
            for (int rr = 0; rr < 2; rr++) {
                int m  = m0 + rr * 8;
                int bb = m >> 10, nn = m & 1023;
                float v0 = (acc[mi][nj][rr * 2 + 0] + b0) * sc;
                float v1 = (acc[mi][nj][rr * 2 + 1] + b1) * sc;
                uint32_t hi, lo;
                pack_split(v0, v1, hi, lo);
                size_t idx = ((size_t)(bb * NHEAD + h) * SEQ + nn) * HDIM + d;
                *(uint32_t*)&hb[idx] = hi;
                *(uint32_t*)&lb[idx] = lo;
            }
        }
    }
}

// GEMM 2: out = g_att @ w_proj^T + b_proj
__global__ __launch_bounds__(256, 1)
void gemm_proj_mma(const float* __restrict__ w,
                   const float* __restrict__ bias,
                   float* __restrict__ out)
{
    __shared__ __align__(128) char smem[GEMM_SMEM_BYTES];
    const int bm = blockIdx.y * 128, bn = blockIdx.x * 128;
    float acc[4][4][4];
    mma_mainloop(g_att, w, bm, bn, smem, acc);

    const int lane = threadIdx.x & 31;
    const int wid  = threadIdx.x >> 5;
    const int wm   = (wid >> 2) * 64;
    const int wn   = (wid & 3) * 32;

    #pragma unroll
    for (int mi = 0; mi < 4; mi++) {
        int m0 = bm + wm + mi * 16 + (lane >> 2);
        #pragma unroll
        for (int nj = 0; nj < 4; nj++) {
            int o = bn + wn + nj * 8 + (lane & 3) * 2;
            float b0 = bias[o], b1 = bias[o + 1];
            #pragma unroll
            for (int rr = 0; rr < 2; rr++) {
                int m = m0 + rr * 8;
                float2 v = make_float2(acc[mi][nj][rr * 2 + 0] + b0,
                                       acc[mi][nj][rr * 2 + 1] + b1);
                *(float2*)&out[(size_t)m * DIM + o] = v;
            }
        }
    }
}

// ---------------------------------------------------------------------------
// Flash attention on mma.sync, split-bf16. grid (b*h=96, seq/128=8), 256 thr.
// 8 warps x 16 q-rows. Q frags in registers; K/V hi/lo staged per 64-kv block
// (144B row stride -> conflict-free ldmatrix, incl. .trans for V). Online
// softmax in register C-layout; P repacked to A-frags in registers.
// ---------------------------------------------------------------------------
#define KB 64
#define ATLDB 144
#define AT_TILE (KB * ATLDB)          // 9216 bytes per tile

__global__ __launch_bounds__(256)
void attn_mma()
{
    __shared__ __align__(128) char smem[4 * AT_TILE];   // Kh|Kl|Vh|Vl (36864 B)
    const uint32_t sb = smem_to_u32(smem);
    const int tid  = threadIdx.x;
    const int lane = tid & 31;
    const int wid  = tid >> 5;
    const int wm   = wid * 16;                          // warp's q-row offset
    const int bh   = blockIdx.x;
    const int bb   = bh / NHEAD;
    const int h    = bh - bb * NHEAD;
    const int qb   = blockIdx.y;

    const size_t headoff = (size_t)bh * SEQ * HDIM;
    const size_t qoff    = headoff + (size_t)qb * 128 * HDIM;

    // ---- Stage Q (128x64) hi into tiles 0-1 area, lo into tiles 2-3 area ----
    {
        const uint4* qh4 = (const uint4*)(g_qh + qoff);
        const uint4* ql4 = (const uint4*)(g_ql + qoff);
        #pragma unroll
        for (int i = 0; i < 4; i++) {
            int idx = tid + i * 256;                     // 1024 uint4
            int row = idx >> 3, c = idx & 7;
            *(uint4*)(smem + row * ATLDB + c * 16)             = qh4[idx];
            *(uint4*)(smem + 2 * AT_TILE + row * ATLDB + c * 16) = ql4[idx];
        }
    }
    __syncthreads();

    const uint32_t a_row = (lane & 7) + ((lane >> 3) & 1) * 8;
    const uint32_t a_kb  = ((lane >> 4) & 1) * 16;
    const uint32_t b_row = lane & 7;
    const uint32_t b_kb  = ((lane >> 3) & 1) * 16;

    uint32_t Qh[4][4], Ql[4][4];
    #pragma unroll
    for (int k = 0; k < 4; k++) {
        uint32_t ad = sb + (wm + a_row) * ATLDB + k * 32 + a_kb;
        LDSM_X4(Qh[k][0], Qh[k][1], Qh[k][2], Qh[k][3], ad);
        LDSM_X4(Ql[k][0], Ql[k][1], Ql[k][2], Ql[k][3], ad + 2 * AT_TILE);
    }
    __syncthreads();            // Q area about to be overwritten by K/V

    float O[8][4];
    #pragma unroll
    for (int nj = 0; nj < 8; nj++)
        #pragma unroll
        for (int r = 0; r < 4; r++) O[nj][r] = 0.f;
    float m0 = -1e30f, m1 = -1e30f, l0 = 0.f, l1 = 0.f;

    const uint4* kh4 = (const uint4*)(g_kh + headoff);
    const uint4* kl4 = (const uint4*)(g_kl + headoff);
    const uint4* vh4 = (const uint4*)(g_vh + headoff);
    const uint4* vl4 = (const uint4*)(g_vl + headoff);

    // software-pipelined K/V staging registers (2 uint4 per tile per thread)
    uint4 pk0[2], pk1[2], pv0[2], pv1[2];
    int srow[2], scol[2];
    #pragma unroll
    for (int i = 0; i < 2; i++) {
        int idx = tid + i * 256;
        srow[i] = idx >> 3; scol[i] = idx & 7;
        pk0[i] = kh4[idx]; pk1[i] = kl4[idx];
        pv0[i] = vh4[idx]; pv1[i] = vl4[idx];
    }

    for (int tb = 0; tb < SEQ / KB; tb++) {
        // store staged block
        #pragma unroll
        for (int i = 0; i < 2; i++) {
            uint32_t boff = srow[i] * ATLDB + scol[i] * 16;
            *(uint4*)(smem + 0 * AT_TILE + boff) = pk0[i];
            *(uint4*)(smem + 1 * AT_TILE + boff) = pk1[i];
            *(uint4*)(smem + 2 * AT_TILE + boff) = pv0[i];
            *(uint4*)(smem + 3 * AT_TILE + boff) = pv1[i];
        }
        __syncthreads();
        // prefetch next block
        if (tb + 1 < SEQ / KB) {
            size_t nb = (size_t)(tb + 1) * KB * HDIM / 8;
            #pragma unroll
            for (int i = 0; i < 2; i++) {
                int idx = tid + i * 256;
                pk0[i] = kh4[nb + idx]; pk1[i] = kl4[nb + idx];
                pv0[i] = vh4[nb + idx]; pv1[i] = vl4[nb + idx];
            }
        }

        // ---- S = Q K^T (scaled; scale folded into Q) ----
        float S[8][4];
        #pragma unroll
        for (int nj = 0; nj < 8; nj++)
            #pragma unroll
            for (int r = 0; r < 4; r++) S[nj][r] = 0.f;

        #pragma unroll
        for (int k = 0; k < 4; k++) {
            #pragma unroll
            for (int nj = 0; nj < 8; nj++) {
                uint32_t bd = sb + (nj * 8 + b_row) * ATLDB + k * 32 + b_kb;
                uint32_t kh0, kh1, kl0, kl1;
                LDSM_X2(kh0, kh1, bd);
                LDSM_X2(kl0, kl1, bd + AT_TILE);
                MMA16816(S[nj], Qh[k][0], Qh[k][1], Qh[k][2], Qh[k][3], kh0, kh1);
                MMA16816(S[nj], Qh[k][0], Qh[k][1], Qh[k][2], Qh[k][3], kl0, kl1);
                MMA16816(S[nj], Ql[k][0], Ql[k][1], Ql[k][2], Ql[k][3], kh0, kh1);
            }
        }

        // ---- online softmax (rows r=lane>>2 and r+8) ----
        float bm0 = S[0][0], bm1 = S[0][2];
        #pragma unroll
        for (int nj = 0; nj < 8; nj++) {
            bm0 = fmaxf(bm0, fmaxf(S[nj][0], S[nj][1]));
            bm1 = fmaxf(bm1, fmaxf(S[nj][2], S[nj][3]));
        }
        bm0 = fmaxf(bm0, __shfl_xor_sync(0xffffffffu, bm0, 1));
        bm0 = fmaxf(bm0, __shfl_xor_sync(0xffffffffu, bm0, 2));
        bm1 = fmaxf(bm1, __shfl_xor_sync(0xffffffffu, bm1, 1));
        bm1 = fmaxf(bm1, __shfl_xor_sync(0xffffffffu, bm1, 2));
        float nm0 = fmaxf(m0, bm0), nm1 = fmaxf(m1, bm1);
        float c0 = fexp(m0 - nm0),  c1 = fexp(m1 - nm1);
        m0 = nm0; m1 = nm1;

        float rs0 = 0.f, rs1 = 0.f;
        #pragma unroll
        for (int nj = 0; nj < 8; nj++) {
            S[nj][0] = fexp(S[nj][0] - m0);
            S[nj][1] = fexp(S[nj][1] - m0);
            S[nj][2] = fexp(S[nj][2] - m1);
            S[nj][3] = fexp(S[nj][3] - m1);
            rs0 += S[nj][0] + S[nj][1];
            rs1 += S[nj][2] + S[nj][3];
        }
        rs0 += __shfl_xor_sync(0xffffffffu, rs0, 1);
        rs0 += __shfl_xor_sync(0xffffffffu, rs0, 2);
        rs1 += __shfl_xor_sync(0xffffffffu, rs1, 1);
        rs1 += __shfl_xor_sync(0xffffffffu, rs1, 2);
        l0 = l0 * c0 + rs0;
        l1 = l1 * c1 + rs1;
        #pragma unroll
        for (int nj = 0; nj < 8; nj++) {
            O[nj][0] *= c0; O[nj][1] *= c0;
            O[nj][2] *= c1; O[nj][3] *= c1;
        }

        // ---- P (C-layout) -> A-frags hi/lo, purely in registers ----
        uint32_t Ph[4][4], Pl[4][4];
        #pragma unroll
        for (int t = 0; t < 4; t++) {
            pack_split(S[2 * t][0],     S[2 * t][1],     Ph[t][0], Pl[t][0]);
            pack_split(S[2 * t][2],     S[2 * t][3],     Ph[t][1], Pl[t][1]);
            pack_split(S[2 * t + 1][0], S[2 * t + 1][1], Ph[t][2], Pl[t][2]);
            pack_split(S[2 * t + 1][2], S[2 * t + 1][3], Ph[t][3], Pl[t][3]);
        }

        // ---- O += P V (V via ldmatrix.trans) ----
        #pragma unroll
        for (int t = 0; t < 4; t++) {
            #pragma unroll
            for (int nj = 0; nj < 8; nj++) {
                uint32_t vaddr = sb + 2 * AT_TILE + (t * 16 + (lane & 15)) * ATLDB + nj * 16;
                uint32_t vh0, vh1, vl0, vl1;
                LDSM_X2_T(vh0, vh1, vaddr);
                LDSM_X2_T(vl0, vl1, vaddr + AT_TILE);
                MMA16816(O[nj], Ph[t][0], Ph[t][1], Ph[t][2], Ph[t][3], vh0, vh1);
                MMA16816(O[nj], Ph[t][0], Ph[t][1], Ph[t][2], Ph[t][3], vl0, vl1);
                MMA16816(O[nj], Pl[t][0], Pl[t][1], Pl[t][2], Pl[t][3], vh0, vh1);
            }
        }
        __syncthreads();           // smem reads done before next store
    }

    // ---- epilogue: normalize, write g_att [b, n, h*64+d] ----
    float inv0 = 1.0f / l0, inv1 = 1.0f / l1;
    int row0 = qb * 128 + wm + (lane >> 2);
    int row1 = row0 + 8;
    float* d0 = g_att + ((size_t)bb * SEQ + row0) * DIM + h * HDIM;
    float* d1 = g_att + ((size_t)bb * SEQ + row1) * DIM + h * HDIM;
    #pragma unroll
    for (int nj = 0; nj < 8; nj++) {
        int col = nj * 8 + (lane & 3) * 2;
        *(float2*)&d0[col] = make_float2(O[nj][0] * inv0, O[nj][1] * inv0);
        *(float2*)&d1[col] = make_float2(O[nj][2] * inv1, O[nj][3] * inv1);
    }
}

// ---------------------------------------------------------------------------
extern "C" void kernel_launch(void* const* d_in, const int* in_sizes, int n_in,
                              void* d_out, int out_size)
{
    const float* x      = (const float*)d_in[0];
    const float* w_qkv  = (const float*)d_in[1];
    const float* b_qkv  = (const float*)d_in[2];
    const float* w_proj = (const float*)d_in[3];
    const float* b_proj = (const float*)d_in[4];
    float* out = (float*)d_out;

    gemm_qkv_mma<<<dim3(QKV_N / 128, MROWS / 128), 256>>>(x, w_qkv, b_qkv);
    attn_mma<<<dim3(BATCH * NHEAD, SEQ / 128), 256>>>();
    gemm_proj_mma<<<dim3(DIM / 128, MROWS / 128), 256>>>(w_proj, b_proj, out);
}

// round 7
// speedup vs baseline: 2.6682x; 1.1378x over previous
#include <cuda_runtime.h>
#include <cuda_bf16.h>
#include <cstdint>

// Problem constants
#define BATCH 8
#define SEQ 1024
#define DIM 768
#define NHEAD 12
#define HDIM 64
#define MROWS (BATCH * SEQ)          // 8192
#define QKV_N (3 * DIM)              // 2304
#define QKV_ELEMS (BATCH * NHEAD * SEQ * HDIM)

// Scratch (allocation-free rule: __device__ globals). All operands split bf16.
// NOTE: these are referenced ONLY from device code — passing them as kernel
// arguments from host silently yields host-shadow addresses (R5/R6 bug).
__device__ __nv_bfloat16 g_xh[MROWS * DIM],  g_xl[MROWS * DIM];
__device__ __nv_bfloat16 g_wqh[QKV_N * DIM], g_wql[QKV_N * DIM];
__device__ __nv_bfloat16 g_wph[DIM * DIM],   g_wpl[DIM * DIM];
__device__ __nv_bfloat16 g_qh[QKV_ELEMS], g_ql[QKV_ELEMS];   // [b,h,n,d], Q pre-scaled
__device__ __nv_bfloat16 g_kh[QKV_ELEMS], g_kl[QKV_ELEMS];
__device__ __nv_bfloat16 g_vh[QKV_ELEMS], g_vl[QKV_ELEMS];
__device__ __nv_bfloat16 g_ath[MROWS * DIM], g_atl[MROWS * DIM]; // attn out [b,n,h*d]

// ---------------------------------------------------------------------------
// PTX helpers (baseline PTX only — tcgen05 rejected by this toolchain's sm_103)
// ---------------------------------------------------------------------------
__device__ __forceinline__ uint32_t smem_to_u32(const void* p) {
    uint32_t a;
    asm("{ .reg .u64 t; cvta.to.shared.u64 t, %1; cvt.u32.u64 %0, t; }"
        : "=r"(a) : "l"(p));
    return a;
}

#define CVT_BF16X2_F32(result, a, b) \
    asm("cvt.rn.bf16x2.f32 %0, %1, %2;" : "=r"(result) : "f"(b), "f"(a))

#define LDSM_X4(r0, r1, r2, r3, addr) \
    asm volatile("ldmatrix.sync.aligned.m8n8.x4.shared.b16 {%0,%1,%2,%3}, [%4];" \
        : "=r"(r0), "=r"(r1), "=r"(r2), "=r"(r3) : "r"(addr))
#define LDSM_X2(r0, r1, addr) \
    asm volatile("ldmatrix.sync.aligned.m8n8.x2.shared.b16 {%0,%1}, [%2];" \
        : "=r"(r0), "=r"(r1) : "r"(addr))
#define LDSM_X2_T(r0, r1, addr) \
    asm volatile("ldmatrix.sync.aligned.m8n8.x2.trans.shared.b16 {%0,%1}, [%2];" \
        : "=r"(r0), "=r"(r1) : "r"(addr))

#define MMA16816(d, a0, a1, a2, a3, b0, b1) \
    asm volatile("mma.sync.aligned.m16n8k16.row.col.f32.bf16.bf16.f32 " \
        "{%0,%1,%2,%3}, {%4,%5,%6,%7}, {%8,%9}, {%0,%1,%2,%3};" \
        : "+f"((d)[0]), "+f"((d)[1]), "+f"((d)[2]), "+f"((d)[3]) \
        : "r"(a0), "r"(a1), "r"(a2), "r"(a3), "r"(b0), "r"(b1))

#define CP16(dst, src) \
    asm volatile("cp.async.cg.shared.global [%0], [%1], 16;" \
        :: "r"(dst), "l"(src))
#define CP_COMMIT asm volatile("cp.async.commit_group;")
#define CP_WAIT1  asm volatile("cp.async.wait_group 1;")
#define CP_WAIT0  asm volatile("cp.async.wait_group 0;")

__device__ __forceinline__ void pack_split(float a, float b,
                                           uint32_t& hi, uint32_t& lo) {
    CVT_BF16X2_F32(hi, a, b);
    float ra = a - __uint_as_float(hi << 16);
    float rb = b - __uint_as_float(hi & 0xffff0000u);
    CVT_BF16X2_F32(lo, ra, rb);
}

__device__ __forceinline__ float fexp(float x) {
    x = fmaxf(x, -87.0f);
    float t = x * 1.4426950408889634f;
    int   ei = __float2int_rn(t);
    float f  = t - (float)ei;
    float p = 1.3333558e-3f;
    p = fmaf(p, f, 9.6181291e-3f);
    p = fmaf(p, f, 5.5504109e-2f);
    p = fmaf(p, f, 2.4022651e-1f);
    p = fmaf(p, f, 6.9314718e-1f);
    p = fmaf(p, f, 1.0f);
    return __int_as_float(__float_as_int(p) + (ei << 23));
}

// ---------------------------------------------------------------------------
// Pre-split: fp32 -> bf16 hi/lo. Output globals selected IN DEVICE CODE
// (sel 0: x, 1: w_qkv, 2: w_proj) — fixes the R5/R6 host-shadow-pointer bug.
// ---------------------------------------------------------------------------
__global__ void conv_split(const float* __restrict__ src, int sel, int n4)
{
    int i = blockIdx.x * blockDim.x + threadIdx.x;
    if (i >= n4) return;
    __nv_bfloat16* hi = (sel == 0) ? g_xh : (sel == 1) ? g_wqh : g_wph;
    __nv_bfloat16* lo = (sel == 0) ? g_xl : (sel == 1) ? g_wql : g_wpl;
    float4 x = ((const float4*)src)[i];
    uint32_t h01, h23, q01, q23;
    CVT_BF16X2_F32(h01, x.x, x.y);
    CVT_BF16X2_F32(h23, x.z, x.w);
    float l0 = x.x - __uint_as_float(h01 << 16);
    float l1 = x.y - __uint_as_float(h01 & 0xffff0000u);
    float l2 = x.z - __uint_as_float(h23 << 16);
    float l3 = x.w - __uint_as_float(h23 & 0xffff0000u);
    CVT_BF16X2_F32(q01, l0, l1);
    CVT_BF16X2_F32(q23, l2, l3);
    ((uint2*)hi)[i] = make_uint2(h01, h23);
    ((uint2*)lo)[i] = make_uint2(q01, q23);
}

// ---------------------------------------------------------------------------
// bf16 GEMM over pre-split operands. C = Ah·Bh + Ah·Bl + Al·Bh, expressed as
// 36 uniform K=64 chunks (phase 0: h·h, 1: h·l, 2: l·h). CTA 128x128, 8 warps
// (64x32), cp.async 2-stage double buffer, 144B smem row stride.
// ---------------------------------------------------------------------------
#define STG_LDB 144
#define STG_TILE (128 * STG_LDB)       // 18432 B per operand tile
#define STAGE_B (2 * STG_TILE)         // 36864 B per stage
#define GEMM_SMEM2 (2 * STAGE_B)       // 73728 B
#define NCHUNKS 36

__device__ __forceinline__ void bf16_mainloop(
    const __nv_bfloat16* __restrict__ Ah, const __nv_bfloat16* __restrict__ Al,
    const __nv_bfloat16* __restrict__ Bh, const __nv_bfloat16* __restrict__ Bl,
    int bm, int bn, uint32_t sb, float acc[4][4][4])
{
    const int tid  = threadIdx.x;
    const int lane = tid & 31;
    const int wid  = tid >> 5;
    const int wm   = (wid >> 2) * 64;
    const int wn   = (wid & 3) * 32;

    #pragma unroll
    for (int mi = 0; mi < 4; mi++)
        #pragma unroll
        for (int nj = 0; nj < 4; nj++)
            #pragma unroll
            for (int r = 0; r < 4; r++) acc[mi][nj][r] = 0.f;

    const uint32_t a_row = (lane & 7) + ((lane >> 3) & 1) * 8;
    const uint32_t a_kb  = ((lane >> 4) & 1) * 16;
    const uint32_t b_row = lane & 7;
    const uint32_t b_kb  = ((lane >> 3) & 1) * 16;

    // issue chunk c's cp.asyncs into stage c&1
    auto issue = [&](int c) {
        int phase = c / 12;
        int ko = (c - phase * 12) * 64;
        const __nv_bfloat16* As = (phase == 2) ? Al : Ah;
        const __nv_bfloat16* Bs = (phase == 1) ? Bl : Bh;
        uint32_t st = sb + (uint32_t)(c & 1) * STAGE_B;
        #pragma unroll
        for (int i = 0; i < 4; i++) {
            int idx = tid + i * 256;          // 1024 16B-chunks per tile
            int row = idx >> 3, col = idx & 7;
            uint32_t doff = row * STG_LDB + col * 16;
            CP16(st + doff,            As + (size_t)(bm + row) * DIM + ko + col * 8);
            CP16(st + STG_TILE + doff, Bs + (size_t)(bn + row) * DIM + ko + col * 8);
        }
        CP_COMMIT;
    };

    issue(0);
    issue(1);

    for (int c = 0; c < NCHUNKS; c++) {
        if (c == NCHUNKS - 1) { CP_WAIT0; } else { CP_WAIT1; }
        __syncthreads();
        uint32_t st = sb + (uint32_t)(c & 1) * STAGE_B;
        #pragma unroll
        for (int k16 = 0; k16 < 4; k16++) {   // 4 steps cover all 64 k (bytes 0..127)
            const uint32_t kb = k16 * 32;
            uint32_t af[4][4], bf2[4][2];
            #pragma unroll
            for (int mi = 0; mi < 4; mi++) {
                uint32_t ad = st + (wm + mi * 16 + a_row) * STG_LDB + kb + a_kb;
                LDSM_X4(af[mi][0], af[mi][1], af[mi][2], af[mi][3], ad);
            }
            #pragma unroll
            for (int nj = 0; nj < 4; nj++) {
                uint32_t bd = st + STG_TILE + (wn + nj * 8 + b_row) * STG_LDB + kb + b_kb;
                LDSM_X2(bf2[nj][0], bf2[nj][1], bd);
            }
            #pragma unroll
            for (int mi = 0; mi < 4; mi++)
                #pragma unroll
                for (int nj = 0; nj < 4; nj++)
                    MMA16816(acc[mi][nj], af[mi][0], af[mi][1], af[mi][2], af[mi][3],
                             bf2[nj][0], bf2[nj][1]);
        }
        __syncthreads();
        if (c + 2 < NCHUNKS) issue(c + 2);
    }
}

// GEMM 1: qkv = x @ w_qkv^T + b_qkv -> split bf16 hi/lo [b,h,n,d]; Q *= 0.125
__global__ __launch_bounds__(256, 2)
void gemm_qkv_mma(const float* __restrict__ bias)
{
    extern __shared__ __align__(128) char smem[];
    const int bm = blockIdx.y * 128, bn = blockIdx.x * 128;
    float acc[4][4][4];
    bf16_mainloop(g_xh, g_xl, g_wqh, g_wql, bm, bn, smem_to_u32(smem), acc);

    const int lane = threadIdx.x & 31;
    const int wid  = threadIdx.x >> 5;
    const int wm   = (wid >> 2) * 64;
    const int wn   = (wid & 3) * 32;
    const int s = blockIdx.x / 6;                 // 0=q, 1=k, 2=v
    __nv_bfloat16* hb = (s == 0) ? g_qh : (s == 1) ? g_kh : g_vh;
    __nv_bfloat16* lb = (s == 0) ? g_ql : (s == 1) ? g_kl : g_vl;
    const float sc = (s == 0) ? 0.125f : 1.0f;

    #pragma unroll
    for (int mi = 0; mi < 4; mi++) {
        int m0 = bm + wm + mi * 16 + (lane >> 2);
        #pragma unroll
        for (int nj = 0; nj < 4; nj++) {
            int o  = bn + wn + nj * 8 + (lane & 3) * 2;
            int rl = o - s * DIM;
            int h = rl >> 6, d = rl & 63;
            float b0 = bias[o], b1 = bias[o + 1];
            #pragma unroll
            for (int rr = 0; rr < 2; rr++) {
                int m  = m0 + rr * 8;
                int bb = m >> 10, nn = m & 1023;
                float v0 = (acc[mi][nj][rr * 2 + 0] + b0) * sc;
                float v1 = (acc[mi][nj][rr * 2 + 1] + b1) * sc;
                uint32_t hi, lo;
                pack_split(v0, v1, hi, lo);
                size_t idx = ((size_t)(bb * NHEAD + h) * SEQ + nn) * HDIM + d;
                *(uint32_t*)&hb[idx] = hi;
                *(uint32_t*)&lb[idx] = lo;
            }
        }
    }
}

// GEMM 2: out = att @ w_proj^T + b_proj
__global__ __launch_bounds__(256, 2)
void gemm_proj_mma(const float* __restrict__ bias, float* __restrict__ out)
{
    extern __shared__ __align__(128) char smem[];
    const int bm = blockIdx.y * 128, bn = blockIdx.x * 128;
    float acc[4][4][4];
    bf16_mainloop(g_ath, g_atl, g_wph, g_wpl, bm, bn, smem_to_u32(smem), acc);

    const int lane = threadIdx.x & 31;
    const int wid  = threadIdx.x >> 5;
    const int wm   = (wid >> 2) * 64;
    const int wn   = (wid & 3) * 32;

    #pragma unroll
    for (int mi = 0; mi < 4; mi++) {
        int m0 = bm + wm + mi * 16 + (lane >> 2);
        #pragma unroll
        for (int nj = 0; nj < 4; nj++) {
            int o = bn + wn + nj * 8 + (lane & 3) * 2;
            float b0 = bias[o], b1 = bias[o + 1];
            #pragma unroll
            for (int rr = 0; rr < 2; rr++) {
                int m = m0 + rr * 8;
                float2 v = make_float2(acc[mi][nj][rr * 2 + 0] + b0,
                                       acc[mi][nj][rr * 2 + 1] + b1);
                *(float2*)&out[(size_t)m * DIM + o] = v;
            }
        }
    }
}

// ---------------------------------------------------------------------------
// Flash attention on mma.sync (R4 structure, passing); epilogue writes split bf16.
// ---------------------------------------------------------------------------
#define KB 64
#define ATLDB 144
#define AT_TILE (KB * ATLDB)

__global__ __launch_bounds__(256)
void attn_mma()
{
    __shared__ __align__(128) char smem[4 * AT_TILE];
    const uint32_t sb = smem_to_u32(smem);
    const int tid  = threadIdx.x;
    const int lane = tid & 31;
    const int wid  = tid >> 5;
    const int wm   = wid * 16;
    const int bh   = blockIdx.x;
    const int bb   = bh / NHEAD;
    const int h    = bh - bb * NHEAD;
    const int qb   = blockIdx.y;

    const size_t headoff = (size_t)bh * SEQ * HDIM;
    const size_t qoff    = headoff + (size_t)qb * 128 * HDIM;

    {
        const uint4* qh4 = (const uint4*)(g_qh + qoff);
        const uint4* ql4 = (const uint4*)(g_ql + qoff);
        #pragma unroll
        for (int i = 0; i < 4; i++) {
            int idx = tid + i * 256;
            int row = idx >> 3, c = idx & 7;
            *(uint4*)(smem + row * ATLDB + c * 16)               = qh4[idx];
            *(uint4*)(smem + 2 * AT_TILE + row * ATLDB + c * 16) = ql4[idx];
        }
    }
    __syncthreads();

    const uint32_t a_row = (lane & 7) + ((lane >> 3) & 1) * 8;
    const uint32_t a_kb  = ((lane >> 4) & 1) * 16;
    const uint32_t b_row = lane & 7;
    const uint32_t b_kb  = ((lane >> 3) & 1) * 16;

    uint32_t Qh[4][4], Ql[4][4];
    #pragma unroll
    for (int k = 0; k < 4; k++) {
        uint32_t ad = sb + (wm + a_row) * ATLDB + k * 32 + a_kb;
        LDSM_X4(Qh[k][0], Qh[k][1], Qh[k][2], Qh[k][3], ad);
        LDSM_X4(Ql[k][0], Ql[k][1], Ql[k][2], Ql[k][3], ad + 2 * AT_TILE);
    }
    __syncthreads();

    float O[8][4];
    #pragma unroll
    for (int nj = 0; nj < 8; nj++)
        #pragma unroll
        for (int r = 0; r < 4; r++) O[nj][r] = 0.f;
    float m0 = -1e30f, m1 = -1e30f, l0 = 0.f, l1 = 0.f;

    const uint4* kh4 = (const uint4*)(g_kh + headoff);
    const uint4* kl4 = (const uint4*)(g_kl + headoff);
    const uint4* vh4 = (const uint4*)(g_vh + headoff);
    const uint4* vl4 = (const uint4*)(g_vl + headoff);

    uint4 pk0[2], pk1[2], pv0[2], pv1[2];
    int srow[2], scol[2];
    #pragma unroll
    for (int i = 0; i < 2; i++) {
        int idx = tid + i * 256;
        srow[i] = idx >> 3; scol[i] = idx & 7;
        pk0[i] = kh4[idx]; pk1[i] = kl4[idx];
        pv0[i] = vh4[idx]; pv1[i] = vl4[idx];
    }

    for (int tb = 0; tb < SEQ / KB; tb++) {
        #pragma unroll
        for (int i = 0; i < 2; i++) {
            uint32_t boff = srow[i] * ATLDB + scol[i] * 16;
            *(uint4*)(smem + 0 * AT_TILE + boff) = pk0[i];
            *(uint4*)(smem + 1 * AT_TILE + boff) = pk1[i];
            *(uint4*)(smem + 2 * AT_TILE + boff) = pv0[i];
            *(uint4*)(smem + 3 * AT_TILE + boff) = pv1[i];
        }
        __syncthreads();
        if (tb + 1 < SEQ / KB) {
            size_t nb = (size_t)(tb + 1) * KB * HDIM / 8;
            #pragma unroll
            for (int i = 0; i < 2; i++) {
                int idx = tid + i * 256;
                pk0[i] = kh4[nb + idx]; pk1[i] = kl4[nb + idx];
                pv0[i] = vh4[nb + idx]; pv1[i] = vl4[nb + idx];
            }
        }

        float S[8][4];
        #pragma unroll
        for (int nj = 0; nj < 8; nj++)
            #pragma unroll
            for (int r = 0; r < 4; r++) S[nj][r] = 0.f;

        #pragma unroll
        for (int k = 0; k < 4; k++) {
            #pragma unroll
            for (int nj = 0; nj < 8; nj++) {
                uint32_t bd = sb + (nj * 8 + b_row) * ATLDB + k * 32 + b_kb;
                uint32_t kh0, kh1, kl0, kl1;
                LDSM_X2(kh0, kh1, bd);
                LDSM_X2(kl0, kl1, bd + AT_TILE);
                MMA16816(S[nj], Qh[k][0], Qh[k][1], Qh[k][2], Qh[k][3], kh0, kh1);
                MMA16816(S[nj], Qh[k][0], Qh[k][1], Qh[k][2], Qh[k][3], kl0, kl1);
                MMA16816(S[nj], Ql[k][0], Ql[k][1], Ql[k][2], Ql[k][3], kh0, kh1);
            }
        }

        float bm0 = S[0][0], bm1 = S[0][2];
        #pragma unroll
        for (int nj = 0; nj < 8; nj++) {
            bm0 = fmaxf(bm0, fmaxf(S[nj][0], S[nj][1]));
            bm1 = fmaxf(bm1, fmaxf(S[nj][2], S[nj][3]));
        }
        bm0 = fmaxf(bm0, __shfl_xor_sync(0xffffffffu, bm0, 1));
        bm0 = fmaxf(bm0, __shfl_xor_sync(0xffffffffu, bm0, 2));
        bm1 = fmaxf(bm1, __shfl_xor_sync(0xffffffffu, bm1, 1));
        bm1 = fmaxf(bm1, __shfl_xor_sync(0xffffffffu, bm1, 2));
        float nm0 = fmaxf(m0, bm0), nm1 = fmaxf(m1, bm1);
        float c0 = fexp(m0 - nm0),  c1 = fexp(m1 - nm1);
        m0 = nm0; m1 = nm1;

        float rs0 = 0.f, rs1 = 0.f;
        #pragma unroll
        for (int nj = 0; nj < 8; nj++) {
            S[nj][0] = fexp(S[nj][0] - m0);
            S[nj][1] = fexp(S[nj][1] - m0);
            S[nj][2] = fexp(S[nj][2] - m1);
            S[nj][3] = fexp(S[nj][3] - m1);
            rs0 += S[nj][0] + S[nj][1];
            rs1 += S[nj][2] + S[nj][3];
        }
        rs0 += __shfl_xor_sync(0xffffffffu, rs0, 1);
        rs0 += __shfl_xor_sync(0xffffffffu, rs0, 2);
        rs1 += __shfl_xor_sync(0xffffffffu, rs1, 1);
        rs1 += __shfl_xor_sync(0xffffffffu, rs1, 2);
        l0 = l0 * c0 + rs0;
        l1 = l1 * c1 + rs1;
        #pragma unroll
        for (int nj = 0; nj < 8; nj++) {
            O[nj][0] *= c0; O[nj][1] *= c0;
            O[nj][2] *= c1; O[nj][3] *= c1;
        }

        uint32_t Ph[4][4], Pl[4][4];
        #pragma unroll
        for (int t = 0; t < 4; t++) {
            pack_split(S[2 * t][0],     S[2 * t][1],     Ph[t][0], Pl[t][0]);
            pack_split(S[2 * t][2],     S[2 * t][3],     Ph[t][1], Pl[t][1]);
            pack_split(S[2 * t + 1][0], S[2 * t + 1][1], Ph[t][2], Pl[t][2]);
            pack_split(S[2 * t + 1][2], S[2 * t + 1][3], Ph[t][3], Pl[t][3]);
        }

        #pragma unroll
        for (int t = 0; t < 4; t++) {
            #pragma unroll
            for (int nj = 0; nj < 8; nj++) {
                uint32_t vaddr = sb + 2 * AT_TILE + (t * 16 + (lane & 15)) * ATLDB + nj * 16;
                uint32_t vh0, vh1, vl0, vl1;
                LDSM_X2_T(vh0, vh1, vaddr);
                LDSM_X2_T(vl0, vl1, vaddr + AT_TILE);
                MMA16816(O[nj], Ph[t][0], Ph[t][1], Ph[t][2], Ph[t][3], vh0, vh1);
                MMA16816(O[nj], Ph[t][0], Ph[t][1], Ph[t][2], Ph[t][3], vl0, vl1);
                MMA16816(O[nj], Pl[t][0], Pl[t][1], Pl[t][2], Pl[t][3], vh0, vh1);
            }
        }
        __syncthreads();
    }

    // epilogue: normalize and write SPLIT bf16 (feeds proj GEMM directly)
    float inv0 = 1.0f / l0, inv1 = 1.0f / l1;
    int row0 = qb * 128 + wm + (lane >> 2);
    int row1 = row0 + 8;
    size_t o0 = ((size_t)bb * SEQ + row0) * DIM + h * HDIM;
    size_t o1 = ((size_t)bb * SEQ + row1) * DIM + h * HDIM;
    #pragma unroll
    for (int nj = 0; nj < 8; nj++) {
        int col = nj * 8 + (lane & 3) * 2;
        uint32_t hi, lo;
        pack_split(O[nj][0] * inv0, O[nj][1] * inv0, hi, lo);
        *(uint32_t*)&g_ath[o0 + col] = hi;
        *(uint32_t*)&g_atl[o0 + col] = lo;
        pack_split(O[nj][2] * inv1, O[nj][3] * inv1, hi, lo);
        *(uint32_t*)&g_ath[o1 + col] = hi;
        *(uint32_t*)&g_atl[o1 + col] = lo;
    }
}

// ---------------------------------------------------------------------------
extern "C" void kernel_launch(void* const* d_in, const int* in_sizes, int n_in,
                              void* d_out, int out_size)
{
    const float* x      = (const float*)d_in[0];
    const float* w_qkv  = (const float*)d_in[1];
    const float* b_qkv  = (const float*)d_in[2];
    const float* w_proj = (const float*)d_in[3];
    const float* b_proj = (const float*)d_in[4];
    float* out = (float*)d_out;

    cudaFuncSetAttribute(gemm_qkv_mma,  cudaFuncAttributeMaxDynamicSharedMemorySize, GEMM_SMEM2);
    cudaFuncSetAttribute(gemm_proj_mma, cudaFuncAttributeMaxDynamicSharedMemorySize, GEMM_SMEM2);

    conv_split<<<(MROWS * DIM / 4 + 255) / 256, 256>>>(x,      0, MROWS * DIM / 4);
    conv_split<<<(QKV_N * DIM / 4 + 255) / 256, 256>>>(w_qkv,  1, QKV_N * DIM / 4);
    conv_split<<<(DIM * DIM / 4 + 255) / 256, 256>>>(w_proj,   2, DIM * DIM / 4);

    gemm_qkv_mma<<<dim3(QKV_N / 128, MROWS / 128), 256, GEMM_SMEM2>>>(b_qkv);
    attn_mma<<<dim3(BATCH * NHEAD, SEQ / 128), 256>>>();
    gemm_proj_mma<<<dim3(DIM / 128, MROWS / 128), 256, GEMM_SMEM2>>>(b_proj, out);
}

// round 8
// speedup vs baseline: 2.7509x; 1.0310x over previous
#include <cuda_runtime.h>
#include <cuda_bf16.h>
#include <cstdint>

// Problem constants
#define BATCH 8
#define SEQ 1024
#define DIM 768
#define NHEAD 12
#define HDIM 64
#define MROWS (BATCH * SEQ)          // 8192
#define QKV_N (3 * DIM)              // 2304
#define QKV_ELEMS (BATCH * NHEAD * SEQ * HDIM)

// Scratch (allocation-free rule: __device__ globals). All operands split bf16.
// Referenced ONLY from device code (host-shadow-pointer bug, R5/R6).
__device__ __nv_bfloat16 g_xh[MROWS * DIM],  g_xl[MROWS * DIM];
__device__ __nv_bfloat16 g_wqh[QKV_N * DIM], g_wql[QKV_N * DIM];
__device__ __nv_bfloat16 g_wph[DIM * DIM],   g_wpl[DIM * DIM];
__device__ __nv_bfloat16 g_qh[QKV_ELEMS], g_ql[QKV_ELEMS];   // [b,h,n,d], Q pre-scaled
__device__ __nv_bfloat16 g_kh[QKV_ELEMS], g_kl[QKV_ELEMS];
__device__ __nv_bfloat16 g_vh[QKV_ELEMS], g_vl[QKV_ELEMS];
__device__ __nv_bfloat16 g_ath[MROWS * DIM], g_atl[MROWS * DIM]; // attn out [b,n,h*d]

// ---------------------------------------------------------------------------
// PTX helpers (baseline PTX only — tcgen05 rejected by this toolchain's sm_103)
// ---------------------------------------------------------------------------
__device__ __forceinline__ uint32_t smem_to_u32(const void* p) {
    uint32_t a;
    asm("{ .reg .u64 t; cvta.to.shared.u64 t, %1; cvt.u32.u64 %0, t; }"
        : "=r"(a) : "l"(p));
    return a;
}

#define CVT_BF16X2_F32(result, a, b) \
    asm("cvt.rn.bf16x2.f32 %0, %1, %2;" : "=r"(result) : "f"(b), "f"(a))

#define LDSM_X4(r0, r1, r2, r3, addr) \
    asm volatile("ldmatrix.sync.aligned.m8n8.x4.shared.b16 {%0,%1,%2,%3}, [%4];" \
        : "=r"(r0), "=r"(r1), "=r"(r2), "=r"(r3) : "r"(addr))
#define LDSM_X2(r0, r1, addr) \
    asm volatile("ldmatrix.sync.aligned.m8n8.x2.shared.b16 {%0,%1}, [%2];" \
        : "=r"(r0), "=r"(r1) : "r"(addr))
#define LDSM_X2_T(r0, r1, addr) \
    asm volatile("ldmatrix.sync.aligned.m8n8.x2.trans.shared.b16 {%0,%1}, [%2];" \
        : "=r"(r0), "=r"(r1) : "r"(addr))

#define MMA16816(d, a0, a1, a2, a3, b0, b1) \
    asm volatile("mma.sync.aligned.m16n8k16.row.col.f32.bf16.bf16.f32 " \
        "{%0,%1,%2,%3}, {%4,%5,%6,%7}, {%8,%9}, {%0,%1,%2,%3};" \
        : "+f"((d)[0]), "+f"((d)[1]), "+f"((d)[2]), "+f"((d)[3]) \
        : "r"(a0), "r"(a1), "r"(a2), "r"(a3), "r"(b0), "r"(b1))

#define CP16(dst, src) \
    asm volatile("cp.async.cg.shared.global [%0], [%1], 16;" \
        :: "r"(dst), "l"(src))
#define CP_COMMIT asm volatile("cp.async.commit_group;")
#define CP_WAIT1  asm volatile("cp.async.wait_group 1;")
#define CP_WAIT0  asm volatile("cp.async.wait_group 0;")

__device__ __forceinline__ void pack_split(float a, float b,
                                           uint32_t& hi, uint32_t& lo) {
    CVT_BF16X2_F32(hi, a, b);
    float ra = a - __uint_as_float(hi << 16);
    float rb = b - __uint_as_float(hi & 0xffff0000u);
    CVT_BF16X2_F32(lo, ra, rb);
}

__device__ __forceinline__ float fexp(float x) {
    x = fmaxf(x, -87.0f);
    float t = x * 1.4426950408889634f;
    int   ei = __float2int_rn(t);
    float f  = t - (float)ei;
    float p = 1.3333558e-3f;
    p = fmaf(p, f, 9.6181291e-3f);
    p = fmaf(p, f, 5.5504109e-2f);
    p = fmaf(p, f, 2.4022651e-1f);
    p = fmaf(p, f, 6.9314718e-1f);
    p = fmaf(p, f, 1.0f);
    return __int_as_float(__float_as_int(p) + (ei << 23));
}

// ---------------------------------------------------------------------------
// Pre-split: fp32 -> bf16 hi/lo. Output globals selected IN DEVICE CODE.
// ---------------------------------------------------------------------------
__global__ void conv_split(const float* __restrict__ src, int sel, int n4)
{
    int i = blockIdx.x * blockDim.x + threadIdx.x;
    if (i >= n4) return;
    __nv_bfloat16* hi = (sel == 0) ? g_xh : (sel == 1) ? g_wqh : g_wph;
    __nv_bfloat16* lo = (sel == 0) ? g_xl : (sel == 1) ? g_wql : g_wpl;
    float4 x = ((const float4*)src)[i];
    uint32_t h01, h23, q01, q23;
    CVT_BF16X2_F32(h01, x.x, x.y);
    CVT_BF16X2_F32(h23, x.z, x.w);
    float l0 = x.x - __uint_as_float(h01 << 16);
    float l1 = x.y - __uint_as_float(h01 & 0xffff0000u);
    float l2 = x.z - __uint_as_float(h23 << 16);
    float l3 = x.w - __uint_as_float(h23 & 0xffff0000u);
    CVT_BF16X2_F32(q01, l0, l1);
    CVT_BF16X2_F32(q23, l2, l3);
    ((uint2*)hi)[i] = make_uint2(h01, h23);
    ((uint2*)lo)[i] = make_uint2(q01, q23);
}

// ---------------------------------------------------------------------------
// Split-bf16 GEMM, single-load scheme: each K=32 chunk loads Ah|Al|Bh|Bl ONCE
// and issues all 3 MMA passes (hh, hl, lh) — 2/3 the L2 traffic and 2/3 the
// ldmatrix count of the 3-phase scheme. CTA 128x128, 8 warps (64x32),
// cp.async 2-stage double buffer, 80B smem row stride (conflict-free).
// ---------------------------------------------------------------------------
#define KC2 32
#define NCH2 (DIM / KC2)               // 24 chunks
#define LDB2 80
#define T2 (128 * LDB2)                // 10240 B per tile
#define STAGE2 (4 * T2)                // 40960 B per stage (Ah|Al|Bh|Bl)
#define GEMM_SMEM2 (2 * STAGE2)        // 81920 B

__device__ __forceinline__ void bf16_mainloop(
    const __nv_bfloat16* __restrict__ Ah, const __nv_bfloat16* __restrict__ Al,
    const __nv_bfloat16* __restrict__ Bh, const __nv_bfloat16* __restrict__ Bl,
    int bm, int bn, uint32_t sb, float acc[4][4][4])
{
    const int tid  = threadIdx.x;
    const int lane = tid & 31;
    const int wid  = tid >> 5;
    const int wm   = (wid >> 2) * 64;
    const int wn   = (wid & 3) * 32;

    #pragma unroll
    for (int mi = 0; mi < 4; mi++)
        #pragma unroll
        for (int nj = 0; nj < 4; nj++)
            #pragma unroll
            for (int r = 0; r < 4; r++) acc[mi][nj][r] = 0.f;

    const uint32_t a_row = (lane & 7) + ((lane >> 3) & 1) * 8;
    const uint32_t a_kb  = ((lane >> 4) & 1) * 16;
    const uint32_t b_row = lane & 7;
    const uint32_t b_kb  = ((lane >> 3) & 1) * 16;

    // issue chunk c's cp.asyncs into stage c&1 (all 4 tiles, 64B rows)
    auto issue = [&](int c) {
        int ko = c * KC2;
        uint32_t st = sb + (uint32_t)(c & 1) * STAGE2;
        #pragma unroll
        for (int i = 0; i < 2; i++) {
            int idx = tid + i * 256;          // 512 16B-chunks per tile
            int row = idx >> 2, col = idx & 3;
            uint32_t doff = row * LDB2 + col * 16;
            const __nv_bfloat16* asrc = (const __nv_bfloat16*)0;
            size_t aoff = (size_t)(bm + row) * DIM + ko + col * 8;
            size_t boff = (size_t)(bn + row) * DIM + ko + col * 8;
            CP16(st + 0 * T2 + doff, Ah + aoff);
            CP16(st + 1 * T2 + doff, Al + aoff);
            CP16(st + 2 * T2 + doff, Bh + boff);
            CP16(st + 3 * T2 + doff, Bl + boff);
            (void)asrc;
        }
        CP_COMMIT;
    };

    issue(0);
    issue(1);

    for (int c = 0; c < NCH2; c++) {
        if (c == NCH2 - 1) { CP_WAIT0; } else { CP_WAIT1; }
        __syncthreads();
        uint32_t st = sb + (uint32_t)(c & 1) * STAGE2;
        #pragma unroll
        for (int k16 = 0; k16 < 2; k16++) {
            const uint32_t kb = k16 * 32;     // bytes 0, 32 within 64B row
            uint32_t bh2[4][2], bl2[4][2];
            #pragma unroll
            for (int nj = 0; nj < 4; nj++) {
                uint32_t bd = st + 2 * T2 + (wn + nj * 8 + b_row) * LDB2 + kb + b_kb;
                LDSM_X2(bh2[nj][0], bh2[nj][1], bd);
                LDSM_X2(bl2[nj][0], bl2[nj][1], bd + T2);
            }
            #pragma unroll
            for (int mi = 0; mi < 4; mi++) {
                uint32_t ad = st + (wm + mi * 16 + a_row) * LDB2 + kb + a_kb;
                uint32_t ah0, ah1, ah2, ah3, al0, al1, al2, al3;
                LDSM_X4(ah0, ah1, ah2, ah3, ad);
                #pragma unroll
                for (int nj = 0; nj < 4; nj++)
                    MMA16816(acc[mi][nj], ah0, ah1, ah2, ah3, bh2[nj][0], bh2[nj][1]);
                #pragma unroll
                for (int nj = 0; nj < 4; nj++)
                    MMA16816(acc[mi][nj], ah0, ah1, ah2, ah3, bl2[nj][0], bl2[nj][1]);
                LDSM_X4(al0, al1, al2, al3, ad + T2);
                #pragma unroll
                for (int nj = 0; nj < 4; nj++)
                    MMA16816(acc[mi][nj], al0, al1, al2, al3, bh2[nj][0], bh2[nj][1]);
            }
        }
        __syncthreads();
        if (c + 2 < NCH2) issue(c + 2);
    }
}

// GEMM 1: qkv = x @ w_qkv^T + b_qkv -> split bf16 hi/lo [b,h,n,d]; Q *= 0.125
__global__ __launch_bounds__(256, 2)
void gemm_qkv_mma(const float* __restrict__ bias)
{
    extern __shared__ __align__(128) char smem[];
    const int bm = blockIdx.y * 128, bn = blockIdx.x * 128;
    float acc[4][4][4];
    bf16_mainloop(g_xh, g_xl, g_wqh, g_wql, bm, bn, smem_to_u32(smem), acc);

    const int lane = threadIdx.x & 31;
    const int wid  = threadIdx.x >> 5;
    const int wm   = (wid >> 2) * 64;
    const int wn   = (wid & 3) * 32;
    const int s = blockIdx.x / 6;                 // 0=q, 1=k, 2=v
    __nv_bfloat16* hb = (s == 0) ? g_qh : (s == 1) ? g_kh : g_vh;
    __nv_bfloat16* lb = (s == 0) ? g_ql : (s == 1) ? g_kl : g_vl;
    const float sc = (s == 0) ? 0.125f : 1.0f;

    #pragma unroll
    for (int mi = 0; mi < 4; mi++) {
        int m0 = bm + wm + mi * 16 + (lane >> 2);
        #pragma unroll
        for (int nj = 0; nj < 4; nj++) {
            int o  = bn + wn + nj * 8 + (lane & 3) * 2;
            int rl = o - s * DIM;
            int h = rl >> 6, d = rl & 63;
            float b0 = bias[o], b1 = bias[o + 1];
            #pragma unroll
            for (int rr = 0; rr < 2; rr++) {
                int m  = m0 + rr * 8;
                int bb = m >> 10, nn = m & 1023;
                float v0 = (acc[mi][nj][rr * 2 + 0] + b0) * sc;
                float v1 = (acc[mi][nj][rr * 2 + 1] + b1) * sc;
                uint32_t hi, lo;
                pack_split(v0, v1, hi, lo);
                size_t idx = ((size_t)(bb * NHEAD + h) * SEQ + nn) * HDIM + d;
                *(uint32_t*)&hb[idx] = hi;
                *(uint32_t*)&lb[idx] = lo;
            }
        }
    }
}

// GEMM 2: out = att @ w_proj^T + b_proj
__global__ __launch_bounds__(256, 2)
void gemm_proj_mma(const float* __restrict__ bias, float* __restrict__ out)
{
    extern __shared__ __align__(128) char smem[];
    const int bm = blockIdx.y * 128, bn = blockIdx.x * 128;
    float acc[4][4][4];
    bf16_mainloop(g_ath, g_atl, g_wph, g_wpl, bm, bn, smem_to_u32(smem), acc);

    const int lane = threadIdx.x & 31;
    const int wid  = threadIdx.x >> 5;
    const int wm   = (wid >> 2) * 64;
    const int wn   = (wid & 3) * 32;

    #pragma unroll
    for (int mi = 0; mi < 4; mi++) {
        int m0 = bm + wm + mi * 16 + (lane >> 2);
        #pragma unroll
        for (int nj = 0; nj < 4; nj++) {
            int o = bn + wn + nj * 8 + (lane & 3) * 2;
            float b0 = bias[o], b1 = bias[o + 1];
            #pragma unroll
            for (int rr = 0; rr < 2; rr++) {
                int m = m0 + rr * 8;
                float2 v = make_float2(acc[mi][nj][rr * 2 + 0] + b0,
                                       acc[mi][nj][rr * 2 + 1] + b1);
                *(float2*)&out[(size_t)m * DIM + o] = v;
            }
        }
    }
}

// ---------------------------------------------------------------------------
// Flash attention on mma.sync (unchanged from R7 passing version).
// ---------------------------------------------------------------------------
#define KB 64
#define ATLDB 144
#define AT_TILE (KB * ATLDB)

__global__ __launch_bounds__(256)
void attn_mma()
{
    __shared__ __align__(128) char smem[4 * AT_TILE];
    const uint32_t sb = smem_to_u32(smem);
    const int tid  = threadIdx.x;
    const int lane = tid & 31;
    const int wid  = tid >> 5;
    const int wm   = wid * 16;
    const int bh   = blockIdx.x;
    const int bb   = bh / NHEAD;
    const int h    = bh - bb * NHEAD;
    const int qb   = blockIdx.y;

    const size_t headoff = (size_t)bh * SEQ * HDIM;
    const size_t qoff    = headoff + (size_t)qb * 128 * HDIM;

    {
        const uint4* qh4 = (const uint4*)(g_qh + qoff);
        const uint4* ql4 = (const uint4*)(g_ql + qoff);
        #pragma unroll
        for (int i = 0; i < 4; i++) {
            int idx = tid + i * 256;
            int row = idx >> 3, c = idx & 7;
            *(uint4*)(smem + row * ATLDB + c * 16)               = qh4[idx];
            *(uint4*)(smem + 2 * AT_TILE + row * ATLDB + c * 16) = ql4[idx];
        }
    }
    __syncthreads();

    const uint32_t a_row = (lane & 7) + ((lane >> 3) & 1) * 8;
    const uint32_t a_kb  = ((lane >> 4) & 1) * 16;
    const uint32_t b_row = lane & 7;
    const uint32_t b_kb  = ((lane >> 3) & 1) * 16;

    uint32_t Qh[4][4], Ql[4][4];
    #pragma unroll
    for (int k = 0; k < 4; k++) {
        uint32_t ad = sb + (wm + a_row) * ATLDB + k * 32 + a_kb;
        LDSM_X4(Qh[k][0], Qh[k][1], Qh[k][2], Qh[k][3], ad);
        LDSM_X4(Ql[k][0], Ql[k][1], Ql[k][2], Ql[k][3], ad + 2 * AT_TILE);
    }
    __syncthreads();

    float O[8][4];
    #pragma unroll
    for (int nj = 0; nj < 8; nj++)
        #pragma unroll
        for (int r = 0; r < 4; r++) O[nj][r] = 0.f;
    float m0 = -1e30f, m1 = -1e30f, l0 = 0.f, l1 = 0.f;

    const uint4* kh4 = (const uint4*)(g_kh + headoff);
    const uint4* kl4 = (const uint4*)(g_kl + headoff);
    const uint4* vh4 = (const uint4*)(g_vh + headoff);
    const uint4* vl4 = (const uint4*)(g_vl + headoff);

    uint4 pk0[2], pk1[2], pv0[2], pv1[2];
    int srow[2], scol[2];
    #pragma unroll
    for (int i = 0; i < 2; i++) {
        int idx = tid + i * 256;
        srow[i] = idx >> 3; scol[i] = idx & 7;
        pk0[i] = kh4[idx]; pk1[i] = kl4[idx];
        pv0[i] = vh4[idx]; pv1[i] = vl4[idx];
    }

    for (int tb = 0; tb < SEQ / KB; tb++) {
        #pragma unroll
        for (int i = 0; i < 2; i++) {
            uint32_t boff = srow[i] * ATLDB + scol[i] * 16;
            *(uint4*)(smem + 0 * AT_TILE + boff) = pk0[i];
            *(uint4*)(smem + 1 * AT_TILE + boff) = pk1[i];
            *(uint4*)(smem + 2 * AT_TILE + boff) = pv0[i];
            *(uint4*)(smem + 3 * AT_TILE + boff) = pv1[i];
        }
        __syncthreads();
        if (tb + 1 < SEQ / KB) {
            size_t nb = (size_t)(tb + 1) * KB * HDIM / 8;
            #pragma unroll
            for (int i = 0; i < 2; i++) {
                int idx = tid + i * 256;
                pk0[i] = kh4[nb + idx]; pk1[i] = kl4[nb + idx];
                pv0[i] = vh4[nb + idx]; pv1[i] = vl4[nb + idx];
            }
        }

        float S[8][4];
        #pragma unroll
        for (int nj = 0; nj < 8; nj++)
            #pragma unroll
            for (int r = 0; r < 4; r++) S[nj][r] = 0.f;

        #pragma unroll
        for (int k = 0; k < 4; k++) {
            #pragma unroll
            for (int nj = 0; nj < 8; nj++) {
                uint32_t bd = sb + (nj * 8 + b_row) * ATLDB + k * 32 + b_kb;
                uint32_t kh0, kh1, kl0, kl1;
                LDSM_X2(kh0, kh1, bd);
                LDSM_X2(kl0, kl1, bd + AT_TILE);
                MMA16816(S[nj], Qh[k][0], Qh[k][1], Qh[k][2], Qh[k][3], kh0, kh1);
                MMA16816(S[nj], Qh[k][0], Qh[k][1], Qh[k][2], Qh[k][3], kl0, kl1);
                MMA16816(S[nj], Ql[k][0], Ql[k][1], Ql[k][2], Ql[k][3], kh0, kh1);
            }
        }

        float bm0 = S[0][0], bm1 = S[0][2];
        #pragma unroll
        for (int nj = 0; nj < 8; nj++) {
            bm0 = fmaxf(bm0, fmaxf(S[nj][0], S[nj][1]));
            bm1 = fmaxf(bm1, fmaxf(S[nj][2], S[nj][3]));
        }
        bm0 = fmaxf(bm0, __shfl_xor_sync(0xffffffffu, bm0, 1));
        bm0 = fmaxf(bm0, __shfl_xor_sync(0xffffffffu, bm0, 2));
        bm1 = fmaxf(bm1, __shfl_xor_sync(0xffffffffu, bm1, 1));
        bm1 = fmaxf(bm1, __shfl_xor_sync(0xffffffffu, bm1, 2));
        float nm0 = fmaxf(m0, bm0), nm1 = fmaxf(m1, bm1);
        float c0 = fexp(m0 - nm0),  c1 = fexp(m1 - nm1);
        m0 = nm0; m1 = nm1;

        float rs0 = 0.f, rs1 = 0.f;
        #pragma unroll
        for (int nj = 0; nj < 8; nj++) {
            S[nj][0] = fexp(S[nj][0] - m0);
            S[nj][1] = fexp(S[nj][1] - m0);
            S[nj][2] = fexp(S[nj][2] - m1);
            S[nj][3] = fexp(S[nj][3] - m1);
            rs0 += S[nj][0] + S[nj][1];
            rs1 += S[nj][2] + S[nj][3];
        }
        rs0 += __shfl_xor_sync(0xffffffffu, rs0, 1);
        rs0 += __shfl_xor_sync(0xffffffffu, rs0, 2);
        rs1 += __shfl_xor_sync(0xffffffffu, rs1, 1);
        rs1 += __shfl_xor_sync(0xffffffffu, rs1, 2);
        l0 = l0 * c0 + rs0;
        l1 = l1 * c1 + rs1;
        #pragma unroll
        for (int nj = 0; nj < 8; nj++) {
            O[nj][0] *= c0; O[nj][1] *= c0;
            O[nj][2] *= c1; O[nj][3] *= c1;
        }

        uint32_t Ph[4][4], Pl[4][4];
        #pragma unroll
        for (int t = 0; t < 4; t++) {
            pack_split(S[2 * t][0],     S[2 * t][1],     Ph[t][0], Pl[t][0]);
            pack_split(S[2 * t][2],     S[2 * t][3],     Ph[t][1], Pl[t][1]);
            pack_split(S[2 * t + 1][0], S[2 * t + 1][1], Ph[t][2], Pl[t][2]);
            pack_split(S[2 * t + 1][2], S[2 * t + 1][3], Ph[t][3], Pl[t][3]);
        }

        #pragma unroll
        for (int t = 0; t < 4; t++) {
            #pragma unroll
            for (int nj = 0; nj < 8; nj++) {
                uint32_t vaddr = sb + 2 * AT_TILE + (t * 16 + (lane & 15)) * ATLDB + nj * 16;
                uint32_t vh0, vh1, vl0, vl1;
                LDSM_X2_T(vh0, vh1, vaddr);
                LDSM_X2_T(vl0, vl1, vaddr + AT_TILE);
                MMA16816(O[nj], Ph[t][0], Ph[t][1], Ph[t][2], Ph[t][3], vh0, vh1);
                MMA16816(O[nj], Ph[t][0], Ph[t][1], Ph[t][2], Ph[t][3], vl0, vl1);
                MMA16816(O[nj], Pl[t][0], Pl[t][1], Pl[t][2], Pl[t][3], vh0, vh1);
            }
        }
        __syncthreads();
    }

    // epilogue: normalize and write SPLIT bf16 (feeds proj GEMM directly)
    float inv0 = 1.0f / l0, inv1 = 1.0f / l1;
    int row0 = qb * 128 + wm + (lane >> 2);
    int row1 = row0 + 8;
    size_t o0 = ((size_t)bb * SEQ + row0) * DIM + h * HDIM;
    size_t o1 = ((size_t)bb * SEQ + row1) * DIM + h * HDIM;
    #pragma unroll
    for (int nj = 0; nj < 8; nj++) {
        int col = nj * 8 + (lane & 3) * 2;
        uint32_t hi, lo;
        pack_split(O[nj][0] * inv0, O[nj][1] * inv0, hi, lo);
        *(uint32_t*)&g_ath[o0 + col] = hi;
        *(uint32_t*)&g_atl[o0 + col] = lo;
        pack_split(O[nj][2] * inv1, O[nj][3] * inv1, hi, lo);
        *(uint32_t*)&g_ath[o1 + col] = hi;
        *(uint32_t*)&g_atl[o1 + col] = lo;
    }
}

// ---------------------------------------------------------------------------
extern "C" void kernel_launch(void* const* d_in, const int* in_sizes, int n_in,
                              void* d_out, int out_size)
{
    const float* x      = (const float*)d_in[0];
    const float* w_qkv  = (const float*)d_in[1];
    const float* b_qkv  = (const float*)d_in[2];
    const float* w_proj = (const float*)d_in[3];
    const float* b_proj = (const float*)d_in[4];
    float* out = (float*)d_out;

    cudaFuncSetAttribute(gemm_qkv_mma,  cudaFuncAttributeMaxDynamicSharedMemorySize, GEMM_SMEM2);
    cudaFuncSetAttribute(gemm_proj_mma, cudaFuncAttributeMaxDynamicSharedMemorySize, GEMM_SMEM2);

    conv_split<<<(MROWS * DIM / 4 + 255) / 256, 256>>>(x,      0, MROWS * DIM / 4);
    conv_split<<<(QKV_N * DIM / 4 + 255) / 256, 256>>>(w_qkv,  1, QKV_N * DIM / 4);
    conv_split<<<(DIM * DIM / 4 + 255) / 256, 256>>>(w_proj,   2, DIM * DIM / 4);

    gemm_qkv_mma<<<dim3(QKV_N / 128, MROWS / 128), 256, GEMM_SMEM2>>>(b_qkv);
    attn_mma<<<dim3(BATCH * NHEAD, SEQ / 128), 256>>>();
    gemm_proj_mma<<<dim3(DIM / 128, MROWS / 128), 256, GEMM_SMEM2>>>(b_proj, out);
}

// round 9
// speedup vs baseline: 2.9166x; 1.0602x over previous
#include <cuda_runtime.h>
#include <cuda_bf16.h>
#include <cstdint>

// Problem constants
#define BATCH 8
#define SEQ 1024
#define DIM 768
#define NHEAD 12
#define HDIM 64
#define MROWS (BATCH * SEQ)          // 8192
#define QKV_N (3 * DIM)              // 2304
#define QKV_ELEMS (BATCH * NHEAD * SEQ * HDIM)

// Scratch (allocation-free rule: __device__ globals). All operands split bf16.
// Referenced ONLY from device code (host-shadow-pointer bug, R5/R6).
__device__ __nv_bfloat16 g_xh[MROWS * DIM],  g_xl[MROWS * DIM];
__device__ __nv_bfloat16 g_wqh[QKV_N * DIM], g_wql[QKV_N * DIM];
__device__ __nv_bfloat16 g_wph[DIM * DIM],   g_wpl[DIM * DIM];
__device__ __nv_bfloat16 g_qh[QKV_ELEMS], g_ql[QKV_ELEMS];   // [b,h,n,d], Q pre-scaled
__device__ __nv_bfloat16 g_kh[QKV_ELEMS], g_kl[QKV_ELEMS];
__device__ __nv_bfloat16 g_vh[QKV_ELEMS], g_vl[QKV_ELEMS];
__device__ __nv_bfloat16 g_ath[MROWS * DIM], g_atl[MROWS * DIM]; // attn out [b,n,h*d]

// ---------------------------------------------------------------------------
// PTX helpers (baseline PTX only — tcgen05 rejected by this toolchain's sm_103)
// ---------------------------------------------------------------------------
__device__ __forceinline__ uint32_t smem_to_u32(const void* p) {
    uint32_t a;
    asm("{ .reg .u64 t; cvta.to.shared.u64 t, %1; cvt.u32.u64 %0, t; }"
        : "=r"(a) : "l"(p));
    return a;
}

#define CVT_BF16X2_F32(result, a, b) \
    asm("cvt.rn.bf16x2.f32 %0, %1, %2;" : "=r"(result) : "f"(b), "f"(a))

#define LDSM_X4(r0, r1, r2, r3, addr) \
    asm volatile("ldmatrix.sync.aligned.m8n8.x4.shared.b16 {%0,%1,%2,%3}, [%4];" \
        : "=r"(r0), "=r"(r1), "=r"(r2), "=r"(r3) : "r"(addr))
#define LDSM_X4_T(r0, r1, r2, r3, addr) \
    asm volatile("ldmatrix.sync.aligned.m8n8.x4.trans.shared.b16 {%0,%1,%2,%3}, [%4];" \
        : "=r"(r0), "=r"(r1), "=r"(r2), "=r"(r3) : "r"(addr))
#define LDSM_X2(r0, r1, addr) \
    asm volatile("ldmatrix.sync.aligned.m8n8.x2.shared.b16 {%0,%1}, [%2];" \
        : "=r"(r0), "=r"(r1) : "r"(addr))

#define MMA16816(d, a0, a1, a2, a3, b0, b1) \
    asm volatile("mma.sync.aligned.m16n8k16.row.col.f32.bf16.bf16.f32 " \
        "{%0,%1,%2,%3}, {%4,%5,%6,%7}, {%8,%9}, {%0,%1,%2,%3};" \
        : "+f"((d)[0]), "+f"((d)[1]), "+f"((d)[2]), "+f"((d)[3]) \
        : "r"(a0), "r"(a1), "r"(a2), "r"(a3), "r"(b0), "r"(b1))

#define CP16(dst, src) \
    asm volatile("cp.async.cg.shared.global [%0], [%1], 16;" \
        :: "r"(dst), "l"(src))
#define CP_COMMIT asm volatile("cp.async.commit_group;")
#define CP_WAIT1  asm volatile("cp.async.wait_group 1;")
#define CP_WAIT0  asm volatile("cp.async.wait_group 0;")

__device__ __forceinline__ void pack_split(float a, float b,
                                           uint32_t& hi, uint32_t& lo) {
    CVT_BF16X2_F32(hi, a, b);
    float ra = a - __uint_as_float(hi << 16);
    float rb = b - __uint_as_float(hi & 0xffff0000u);
    CVT_BF16X2_F32(lo, ra, rb);
}

__device__ __forceinline__ float fexp(float x) {
    x = fmaxf(x, -87.0f);
    float t = x * 1.4426950408889634f;
    int   ei = __float2int_rn(t);
    float f  = t - (float)ei;
    float p = 1.3333558e-3f;
    p = fmaf(p, f, 9.6181291e-3f);
    p = fmaf(p, f, 5.5504109e-2f);
    p = fmaf(p, f, 2.4022651e-1f);
    p = fmaf(p, f, 6.9314718e-1f);
    p = fmaf(p, f, 1.0f);
    return __int_as_float(__float_as_int(p) + (ei << 23));
}

// ---------------------------------------------------------------------------
// Pre-split: fp32 -> bf16 hi/lo. Output globals selected IN DEVICE CODE.
// ---------------------------------------------------------------------------
__global__ void conv_split(const float* __restrict__ src, int sel, int n4)
{
    int i = blockIdx.x * blockDim.x + threadIdx.x;
    if (i >= n4) return;
    __nv_bfloat16* hi = (sel == 0) ? g_xh : (sel == 1) ? g_wqh : g_wph;
    __nv_bfloat16* lo = (sel == 0) ? g_xl : (sel == 1) ? g_wql : g_wpl;
    float4 x = ((const float4*)src)[i];
    uint32_t h01, h23, q01, q23;
    CVT_BF16X2_F32(h01, x.x, x.y);
    CVT_BF16X2_F32(h23, x.z, x.w);
    float l0 = x.x - __uint_as_float(h01 << 16);
    float l1 = x.y - __uint_as_float(h01 & 0xffff0000u);
    float l2 = x.z - __uint_as_float(h23 << 16);
    float l3 = x.w - __uint_as_float(h23 & 0xffff0000u);
    CVT_BF16X2_F32(q01, l0, l1);
    CVT_BF16X2_F32(q23, l2, l3);
    ((uint2*)hi)[i] = make_uint2(h01, h23);
    ((uint2*)lo)[i] = make_uint2(q01, q23);
}

// ---------------------------------------------------------------------------
// Split-bf16 GEMM (unchanged from R8 passing version).
// ---------------------------------------------------------------------------
#define KC2 32
#define NCH2 (DIM / KC2)               // 24 chunks
#define LDB2 80
#define T2 (128 * LDB2)                // 10240 B per tile
#define STAGE2 (4 * T2)                // 40960 B per stage (Ah|Al|Bh|Bl)
#define GEMM_SMEM2 (2 * STAGE2)        // 81920 B

__device__ __forceinline__ void bf16_mainloop(
    const __nv_bfloat16* __restrict__ Ah, const __nv_bfloat16* __restrict__ Al,
    const __nv_bfloat16* __restrict__ Bh, const __nv_bfloat16* __restrict__ Bl,
    int bm, int bn, uint32_t sb, float acc[4][4][4])
{
    const int tid  = threadIdx.x;
    const int lane = tid & 31;
    const int wid  = tid >> 5;
    const int wm   = (wid >> 2) * 64;
    const int wn   = (wid & 3) * 32;

    #pragma unroll
    for (int mi = 0; mi < 4; mi++)
        #pragma unroll
        for (int nj = 0; nj < 4; nj++)
            #pragma unroll
            for (int r = 0; r < 4; r++) acc[mi][nj][r] = 0.f;

    const uint32_t a_row = (lane & 7) + ((lane >> 3) & 1) * 8;
    const uint32_t a_kb  = ((lane >> 4) & 1) * 16;
    const uint32_t b_row = lane & 7;
    const uint32_t b_kb  = ((lane >> 3) & 1) * 16;

    auto issue = [&](int c) {
        int ko = c * KC2;
        uint32_t st = sb + (uint32_t)(c & 1) * STAGE2;
        #pragma unroll
        for (int i = 0; i < 2; i++) {
            int idx = tid + i * 256;
            int row = idx >> 2, col = idx & 3;
            uint32_t doff = row * LDB2 + col * 16;
            size_t aoff = (size_t)(bm + row) * DIM + ko + col * 8;
            size_t boff = (size_t)(bn + row) * DIM + ko + col * 8;
            CP16(st + 0 * T2 + doff, Ah + aoff);
            CP16(st + 1 * T2 + doff, Al + aoff);
            CP16(st + 2 * T2 + doff, Bh + boff);
            CP16(st + 3 * T2 + doff, Bl + boff);
        }
        CP_COMMIT;
    };

    issue(0);
    issue(1);

    for (int c = 0; c < NCH2; c++) {
        if (c == NCH2 - 1) { CP_WAIT0; } else { CP_WAIT1; }
        __syncthreads();
        uint32_t st = sb + (uint32_t)(c & 1) * STAGE2;
        #pragma unroll
        for (int k16 = 0; k16 < 2; k16++) {
            const uint32_t kb = k16 * 32;
            uint32_t bh2[4][2], bl2[4][2];
            #pragma unroll
            for (int nj = 0; nj < 4; nj++) {
                uint32_t bd = st + 2 * T2 + (wn + nj * 8 + b_row) * LDB2 + kb + b_kb;
                LDSM_X2(bh2[nj][0], bh2[nj][1], bd);
                LDSM_X2(bl2[nj][0], bl2[nj][1], bd + T2);
            }
            #pragma unroll
            for (int mi = 0; mi < 4; mi++) {
                uint32_t ad = st + (wm + mi * 16 + a_row) * LDB2 + kb + a_kb;
                uint32_t ah0, ah1, ah2, ah3, al0, al1, al2, al3;
                LDSM_X4(ah0, ah1, ah2, ah3, ad);
                #pragma unroll
                for (int nj = 0; nj < 4; nj++)
                    MMA16816(acc[mi][nj], ah0, ah1, ah2, ah3, bh2[nj][0], bh2[nj][1]);
                #pragma unroll
                for (int nj = 0; nj < 4; nj++)
                    MMA16816(acc[mi][nj], ah0, ah1, ah2, ah3, bl2[nj][0], bl2[nj][1]);
                LDSM_X4(al0, al1, al2, al3, ad + T2);
                #pragma unroll
                for (int nj = 0; nj < 4; nj++)
                    MMA16816(acc[mi][nj], al0, al1, al2, al3, bh2[nj][0], bh2[nj][1]);
            }
        }
        __syncthreads();
        if (c + 2 < NCH2) issue(c + 2);
    }
}

// GEMM 1: qkv = x @ w_qkv^T + b_qkv -> split bf16 hi/lo [b,h,n,d]; Q *= 0.125
__global__ __launch_bounds__(256, 2)
void gemm_qkv_mma(const float* __restrict__ bias)
{
    extern __shared__ __align__(128) char smem[];
    const int bm = blockIdx.y * 128, bn = blockIdx.x * 128;
    float acc[4][4][4];
    bf16_mainloop(g_xh, g_xl, g_wqh, g_wql, bm, bn, smem_to_u32(smem), acc);

    const int lane = threadIdx.x & 31;
    const int wid  = threadIdx.x >> 5;
    const int wm   = (wid >> 2) * 64;
    const int wn   = (wid & 3) * 32;
    const int s = blockIdx.x / 6;                 // 0=q, 1=k, 2=v
    __nv_bfloat16* hb = (s == 0) ? g_qh : (s == 1) ? g_kh : g_vh;
    __nv_bfloat16* lb = (s == 0) ? g_ql : (s == 1) ? g_kl : g_vl;
    const float sc = (s == 0) ? 0.125f : 1.0f;

    #pragma unroll
    for (int mi = 0; mi < 4; mi++) {
        int m0 = bm + wm + mi * 16 + (lane >> 2);
        #pragma unroll
        for (int nj = 0; nj < 4; nj++) {
            int o  = bn + wn + nj * 8 + (lane & 3) * 2;
            int rl = o - s * DIM;
            int h = rl >> 6, d = rl & 63;
            float b0 = bias[o], b1 = bias[o + 1];
            #pragma unroll
            for (int rr = 0; rr < 2; rr++) {
                int m  = m0 + rr * 8;
                int bb = m >> 10, nn = m & 1023;
                float v0 = (acc[mi][nj][rr * 2 + 0] + b0) * sc;
                float v1 = (acc[mi][nj][rr * 2 + 1] + b1) * sc;
                uint32_t hi, lo;
                pack_split(v0, v1, hi, lo);
                size_t idx = ((size_t)(bb * NHEAD + h) * SEQ + nn) * HDIM + d;
                *(uint32_t*)&hb[idx] = hi;
                *(uint32_t*)&lb[idx] = lo;
            }
        }
    }
}

// GEMM 2: out = att @ w_proj^T + b_proj
__global__ __launch_bounds__(256, 2)
void gemm_proj_mma(const float* __restrict__ bias, float* __restrict__ out)
{
    extern __shared__ __align__(128) char smem[];
    const int bm = blockIdx.y * 128, bn = blockIdx.x * 128;
    float acc[4][4][4];
    bf16_mainloop(g_ath, g_atl, g_wph, g_wpl, bm, bn, smem_to_u32(smem), acc);

    const int lane = threadIdx.x & 31;
    const int wid  = threadIdx.x >> 5;
    const int wm   = (wid >> 2) * 64;
    const int wn   = (wid & 3) * 32;

    #pragma unroll
    for (int mi = 0; mi < 4; mi++) {
        int m0 = bm + wm + mi * 16 + (lane >> 2);
        #pragma unroll
        for (int nj = 0; nj < 4; nj++) {
            int o = bn + wn + nj * 8 + (lane & 3) * 2;
            float b0 = bias[o], b1 = bias[o + 1];
            #pragma unroll
            for (int rr = 0; rr < 2; rr++) {
                int m = m0 + rr * 8;
                float2 v = make_float2(acc[mi][nj][rr * 2 + 0] + b0,
                                       acc[mi][nj][rr * 2 + 1] + b1);
                *(float2*)&out[(size_t)m * DIM + o] = v;
            }
        }
    }
}

// ---------------------------------------------------------------------------
// Flash attention, R9: cp.async double-buffered K/V stages (1 sync/block),
// x4 ldmatrix (nj-pairs) for K and V, 128-reg cap -> 2 CTAs/SM.
// ---------------------------------------------------------------------------
#define KB 64
#define ATLDB 144
#define ATILE (KB * ATLDB)             // 9216 per tile
#define ASTAGE (4 * ATILE)             // 36864 per stage (Kh|Kl|Vh|Vl)
#define ATT_SMEM (2 * ASTAGE)          // 73728 dynamic

__global__ __launch_bounds__(256, 2)
void attn_mma()
{
    extern __shared__ __align__(128) char smem[];
    const uint32_t sb = smem_to_u32(smem);
    const int tid  = threadIdx.x;
    const int lane = tid & 31;
    const int wid  = tid >> 5;
    const int wm   = wid * 16;
    const int bh   = blockIdx.x;
    const int bb   = bh / NHEAD;
    const int h    = bh - bb * NHEAD;
    const int qb   = blockIdx.y;

    const size_t headoff = (size_t)bh * SEQ * HDIM;
    const size_t qoff    = headoff + (size_t)qb * 128 * HDIM;

    // ---- Stage Q (128x64): hi at stage0 base, lo at stage1 base ----
    {
        const uint4* qh4 = (const uint4*)(g_qh + qoff);
        const uint4* ql4 = (const uint4*)(g_ql + qoff);
        #pragma unroll
        for (int i = 0; i < 4; i++) {
            int idx = tid + i * 256;
            int row = idx >> 3, c = idx & 7;
            *(uint4*)(smem + row * ATLDB + c * 16)          = qh4[idx];
            *(uint4*)(smem + ASTAGE + row * ATLDB + c * 16) = ql4[idx];
        }
    }
    __syncthreads();

    const uint32_t a_row = (lane & 7) + ((lane >> 3) & 1) * 8;
    const uint32_t a_kb  = ((lane >> 4) & 1) * 16;
    // x4 K-load lane mapping: nj-pair rows + k16-half select
    const uint32_t kp_row = ((lane >> 4) << 3) + (lane & 7);
    const uint32_t kp_kb  = ((lane >> 3) & 1) << 4;

    uint32_t Qh[4][4], Ql[4][4];
    #pragma unroll
    for (int k = 0; k < 4; k++) {
        uint32_t ad = sb + (wm + a_row) * ATLDB + k * 32 + a_kb;
        LDSM_X4(Qh[k][0], Qh[k][1], Qh[k][2], Qh[k][3], ad);
        LDSM_X4(Ql[k][0], Ql[k][1], Ql[k][2], Ql[k][3], ad + ASTAGE);
    }
    __syncthreads();          // Q regions about to be reused as K/V stages

    float O[8][4];
    #pragma unroll
    for (int nj = 0; nj < 8; nj++)
        #pragma unroll
        for (int r = 0; r < 4; r++) O[nj][r] = 0.f;
    float m0 = -1e30f, m1 = -1e30f, l0 = 0.f, l1 = 0.f;

    // cp.async staging: 4 tiles x 64 rows x 128B per stage
    auto issue_kv = [&](int t) {
        uint32_t st = sb + (uint32_t)(t & 1) * ASTAGE;
        size_t base = headoff + (size_t)t * KB * HDIM;
        #pragma unroll
        for (int i = 0; i < 2; i++) {
            int idx = tid + i * 256;          // 512 16B-chunks per tile
            int row = idx >> 3, col = idx & 7;
            uint32_t doff = row * ATLDB + col * 16;
            size_t goff = base + row * HDIM + col * 8;
            CP16(st + 0 * ATILE + doff, g_kh + goff);
            CP16(st + 1 * ATILE + doff, g_kl + goff);
            CP16(st + 2 * ATILE + doff, g_vh + goff);
            CP16(st + 3 * ATILE + doff, g_vl + goff);
        }
        CP_COMMIT;
    };

    issue_kv(0);

    for (int tb = 0; tb < SEQ / KB; tb++) {
        CP_WAIT0;
        __syncthreads();              // stage tb data visible to all warps
        if (tb + 1 < SEQ / KB) issue_kv(tb + 1);   // writes other stage
        uint32_t st = sb + (uint32_t)(tb & 1) * ASTAGE;

        // ---- S = Q K^T (scale folded into Q) ----
        float S[8][4];
        #pragma unroll
        for (int nj = 0; nj < 8; nj++)
            #pragma unroll
            for (int r = 0; r < 4; r++) S[nj][r] = 0.f;

        #pragma unroll
        for (int k = 0; k < 4; k++) {
            #pragma unroll
            for (int njp = 0; njp < 4; njp++) {
                uint32_t bd = st + (njp * 16 + kp_row) * ATLDB + k * 32 + kp_kb;
                uint32_t kh0, kh1, kh2, kh3, kl0, kl1, kl2, kl3;
                LDSM_X4(kh0, kh1, kh2, kh3, bd);
                LDSM_X4(kl0, kl1, kl2, kl3, bd + ATILE);
                MMA16816(S[njp * 2],     Qh[k][0], Qh[k][1], Qh[k][2], Qh[k][3], kh0, kh1);
                MMA16816(S[njp * 2 + 1], Qh[k][0], Qh[k][1], Qh[k][2], Qh[k][3], kh2, kh3);
                MMA16816(S[njp * 2],     Qh[k][0], Qh[k][1], Qh[k][2], Qh[k][3], kl0, kl1);
                MMA16816(S[njp * 2 + 1], Qh[k][0], Qh[k][1], Qh[k][2], Qh[k][3], kl2, kl3);
                MMA16816(S[njp * 2],     Ql[k][0], Ql[k][1], Ql[k][2], Ql[k][3], kh0, kh1);
                MMA16816(S[njp * 2 + 1], Ql[k][0], Ql[k][1], Ql[k][2], Ql[k][3], kh2, kh3);
            }
        }

        // ---- online softmax (rows r=lane>>2 and r+8) ----
        float bm0 = S[0][0], bm1 = S[0][2];
        #pragma unroll
        for (int nj = 0; nj < 8; nj++) {
            bm0 = fmaxf(bm0, fmaxf(S[nj][0], S[nj][1]));
            bm1 = fmaxf(bm1, fmaxf(S[nj][2], S[nj][3]));
        }
        bm0 = fmaxf(bm0, __shfl_xor_sync(0xffffffffu, bm0, 1));
        bm0 = fmaxf(bm0, __shfl_xor_sync(0xffffffffu, bm0, 2));
        bm1 = fmaxf(bm1, __shfl_xor_sync(0xffffffffu, bm1, 1));
        bm1 = fmaxf(bm1, __shfl_xor_sync(0xffffffffu, bm1, 2));
        float nm0 = fmaxf(m0, bm0), nm1 = fmaxf(m1, bm1);
        float c0 = fexp(m0 - nm0),  c1 = fexp(m1 - nm1);
        m0 = nm0; m1 = nm1;

        float rs0 = 0.f, rs1 = 0.f;
        #pragma unroll
        for (int nj = 0; nj < 8; nj++) {
            S[nj][0] = fexp(S[nj][0] - m0);
            S[nj][1] = fexp(S[nj][1] - m0);
            S[nj][2] = fexp(S[nj][2] - m1);
            S[nj][3] = fexp(S[nj][3] - m1);
            rs0 += S[nj][0] + S[nj][1];
            rs1 += S[nj][2] + S[nj][3];
        }
        rs0 += __shfl_xor_sync(0xffffffffu, rs0, 1);
        rs0 += __shfl_xor_sync(0xffffffffu, rs0, 2);
        rs1 += __shfl_xor_sync(0xffffffffu, rs1, 1);
        rs1 += __shfl_xor_sync(0xffffffffu, rs1, 2);
        l0 = l0 * c0 + rs0;
        l1 = l1 * c1 + rs1;
        #pragma unroll
        for (int nj = 0; nj < 8; nj++) {
            O[nj][0] *= c0; O[nj][1] *= c0;
            O[nj][2] *= c1; O[nj][3] *= c1;
        }

        // ---- P (C-layout) -> A-frags hi/lo, purely in registers ----
        uint32_t Ph[4][4], Pl[4][4];
        #pragma unroll
        for (int t = 0; t < 4; t++) {
            pack_split(S[2 * t][0],     S[2 * t][1],     Ph[t][0], Pl[t][0]);
            pack_split(S[2 * t][2],     S[2 * t][3],     Ph[t][1], Pl[t][1]);
            pack_split(S[2 * t + 1][0], S[2 * t + 1][1], Ph[t][2], Pl[t][2]);
            pack_split(S[2 * t + 1][2], S[2 * t + 1][3], Ph[t][3], Pl[t][3]);
        }

        // ---- O += P V (V via x4 trans ldmatrix, nj-pairs) ----
        #pragma unroll
        for (int t = 0; t < 4; t++) {
            #pragma unroll
            for (int njp = 0; njp < 4; njp++) {
                uint32_t vaddr = st + 2 * ATILE + (t * 16 + (lane & 15)) * ATLDB
                                 + njp * 32 + ((lane >> 4) << 4);
                uint32_t vh0, vh1, vh2, vh3, vl0, vl1, vl2, vl3;
                LDSM_X4_T(vh0, vh1, vh2, vh3, vaddr);
                LDSM_X4_T(vl0, vl1, vl2, vl3, vaddr + ATILE);
                MMA16816(O[njp * 2],     Ph[t][0], Ph[t][1], Ph[t][2], Ph[t][3], vh0, vh1);
                MMA16816(O[njp * 2 + 1], Ph[t][0], Ph[t][1], Ph[t][2], Ph[t][3], vh2, vh3);
                MMA16816(O[njp * 2],     Ph[t][0], Ph[t][1], Ph[t][2], Ph[t][3], vl0, vl1);
                MMA16816(O[njp * 2 + 1], Ph[t][0], Ph[t][1], Ph[t][2], Ph[t][3], vl2, vl3);
                MMA16816(O[njp * 2],     Pl[t][0], Pl[t][1], Pl[t][2], Pl[t][3], vh0, vh1);
                MMA16816(O[njp * 2 + 1], Pl[t][0], Pl[t][1], Pl[t][2], Pl[t][3], vh2, vh3);
            }
        }
        // no trailing sync: next iteration's sync orders stage reuse
    }

    // ---- epilogue: normalize and write SPLIT bf16 (feeds proj GEMM) ----
    float inv0 = 1.0f / l0, inv1 = 1.0f / l1;
    int row0 = qb * 128 + wm + (lane >> 2);
    int row1 = row0 + 8;
    size_t o0 = ((size_t)bb * SEQ + row0) * DIM + h * HDIM;
    size_t o1 = ((size_t)bb * SEQ + row1) * DIM + h * HDIM;
    #pragma unroll
    for (int nj = 0; nj < 8; nj++) {
        int col = nj * 8 + (lane & 3) * 2;
        uint32_t hi, lo;
        pack_split(O[nj][0] * inv0, O[nj][1] * inv0, hi, lo);
        *(uint32_t*)&g_ath[o0 + col] = hi;
        *(uint32_t*)&g_atl[o0 + col] = lo;
        pack_split(O[nj][2] * inv1, O[nj][3] * inv1, hi, lo);
        *(uint32_t*)&g_ath[o1 + col] = hi;
        *(uint32_t*)&g_atl[o1 + col] = lo;
    }
}

// ---------------------------------------------------------------------------
extern "C" void kernel_launch(void* const* d_in, const int* in_sizes, int n_in,
                              void* d_out, int out_size)
{
    const float* x      = (const float*)d_in[0];
    const float* w_qkv  = (const float*)d_in[1];
    const float* b_qkv  = (const float*)d_in[2];
    const float* w_proj = (const float*)d_in[3];
    const float* b_proj = (const float*)d_in[4];
    float* out = (float*)d_out;

    cudaFuncSetAttribute(gemm_qkv_mma,  cudaFuncAttributeMaxDynamicSharedMemorySize, GEMM_SMEM2);
    cudaFuncSetAttribute(gemm_proj_mma, cudaFuncAttributeMaxDynamicSharedMemorySize, GEMM_SMEM2);
    cudaFuncSetAttribute(attn_mma,      cudaFuncAttributeMaxDynamicSharedMemorySize, ATT_SMEM);

    conv_split<<<(MROWS * DIM / 4 + 255) / 256, 256>>>(x,      0, MROWS * DIM / 4);
    conv_split<<<(QKV_N * DIM / 4 + 255) / 256, 256>>>(w_qkv,  1, QKV_N * DIM / 4);
    conv_split<<<(DIM * DIM / 4 + 255) / 256, 256>>>(w_proj,   2, DIM * DIM / 4);

    gemm_qkv_mma<<<dim3(QKV_N / 128, MROWS / 128), 256, GEMM_SMEM2>>>(b_qkv);
    attn_mma<<<dim3(BATCH * NHEAD, SEQ / 128), 256, ATT_SMEM>>>();
    gemm_proj_mma<<<dim3(DIM / 128, MROWS / 128), 256, GEMM_SMEM2>>>(b_proj, out);
}

// round 10
// speedup vs baseline: 4.2137x; 1.4447x over previous
#include <cuda_runtime.h>
#include <cuda_fp16.h>
#include <cstdint>

// Problem constants
#define BATCH 8
#define SEQ 1024
#define DIM 768
#define NHEAD 12
#define HDIM 64
#define MROWS (BATCH * SEQ)          // 8192
#define QKV_N (3 * DIM)              // 2304
#define QKV_ELEMS (BATCH * NHEAD * SEQ * HDIM)

// log2(e)/8 folded into Q so softmax runs in exp2 domain
#define QSCALE (0.125f * 1.44269504088896f)

// Scratch (allocation-free rule: __device__ globals). fp16 2-term scheme:
// A-side operands keep HI only; B-side operands keep HI+LO.
__device__ __half g_xh[MROWS * DIM];
__device__ __half g_wqh[QKV_N * DIM], g_wql[QKV_N * DIM];
__device__ __half g_wph[DIM * DIM],   g_wpl[DIM * DIM];
__device__ __half g_qh[QKV_ELEMS];                        // [b,h,n,d], pre-scaled
__device__ __half g_kh[QKV_ELEMS], g_kl[QKV_ELEMS];
__device__ __half g_vh[QKV_ELEMS], g_vl[QKV_ELEMS];
__device__ __half g_ath[MROWS * DIM];                     // attn out [b,n,h*d]

// ---------------------------------------------------------------------------
// PTX helpers (baseline PTX only — tcgen05 rejected by this toolchain's sm_103)
// ---------------------------------------------------------------------------
__device__ __forceinline__ uint32_t smem_to_u32(const void* p) {
    uint32_t a;
    asm("{ .reg .u64 t; cvta.to.shared.u64 t, %1; cvt.u32.u64 %0, t; }"
        : "=r"(a) : "l"(p));
    return a;
}

#define LDSM_X4(r0, r1, r2, r3, addr) \
    asm volatile("ldmatrix.sync.aligned.m8n8.x4.shared.b16 {%0,%1,%2,%3}, [%4];" \
        : "=r"(r0), "=r"(r1), "=r"(r2), "=r"(r3) : "r"(addr))
#define LDSM_X4_T(r0, r1, r2, r3, addr) \
    asm volatile("ldmatrix.sync.aligned.m8n8.x4.trans.shared.b16 {%0,%1,%2,%3}, [%4];" \
        : "=r"(r0), "=r"(r1), "=r"(r2), "=r"(r3) : "r"(addr))

// fp16 MMA, fp32 accumulate
#define MMA16816(d, a0, a1, a2, a3, b0, b1) \
    asm volatile("mma.sync.aligned.m16n8k16.row.col.f32.f16.f16.f32 " \
        "{%0,%1,%2,%3}, {%4,%5,%6,%7}, {%8,%9}, {%0,%1,%2,%3};" \
        : "+f"((d)[0]), "+f"((d)[1]), "+f"((d)[2]), "+f"((d)[3]) \
        : "r"(a0), "r"(a1), "r"(a2), "r"(a3), "r"(b0), "r"(b1))

#define CP16(dst, src) \
    asm volatile("cp.async.cg.shared.global [%0], [%1], 16;" \
        :: "r"(dst), "l"(src))
#define CP_COMMIT asm volatile("cp.async.commit_group;")
#define CP_WAIT1  asm volatile("cp.async.wait_group 1;")
#define CP_WAIT0  asm volatile("cp.async.wait_group 0;")

// fp16 pack helpers
__device__ __forceinline__ uint32_t pack2_f16(float a, float b) {
    __half2 h = __floats2half2_rn(a, b);      // a -> lo, b -> hi
    return *reinterpret_cast<uint32_t*>(&h);
}
__device__ __forceinline__ void split2_f16(float a, float b,
                                           uint32_t& hi, uint32_t& lo) {
    __half2 h = __floats2half2_rn(a, b);
    float2 f = __half22float2(h);
    __half2 l = __floats2half2_rn(a - f.x, b - f.y);
    hi = *reinterpret_cast<uint32_t*>(&h);
    lo = *reinterpret_cast<uint32_t*>(&l);
}
__device__ __forceinline__ uint2 pack4_hi(float4 v) {
    return make_uint2(pack2_f16(v.x, v.y), pack2_f16(v.z, v.w));
}
__device__ __forceinline__ void split4_f16(float4 v, uint2& hi, uint2& lo) {
    uint32_t h0, l0, h1, l1;
    split2_f16(v.x, v.y, h0, l0);
    split2_f16(v.z, v.w, h1, l1);
    hi = make_uint2(h0, h1);
    lo = make_uint2(l0, l1);
}

// exp2 on the FMA pipe (scores already in log2 domain via QSCALE).
// deg-4 poly on [-0.5,0.5], max rel err ~4e-5.
__device__ __forceinline__ float fexp2(float x) {
    x = fmaxf(x, -100.0f);
    int   e = __float2int_rn(x);
    float f = x - (float)e;
    float p = 9.6179669e-3f;
    p = fmaf(p, f, 5.5504109e-2f);
    p = fmaf(p, f, 2.4022651e-1f);
    p = fmaf(p, f, 6.9314718e-1f);
    p = fmaf(p, f, 1.0f);
    return __int_as_float(__float_as_int(p) + (e << 23));
}

// ---------------------------------------------------------------------------
// Merged pre-split kernel: x (hi only), w_qkv (hi+lo), w_proj (hi+lo).
// Output globals referenced in device code only (host-shadow bug, R5/R6).
// ---------------------------------------------------------------------------
#define NX4  (MROWS * DIM / 4)       // 1572864
#define NWQ4 (QKV_N * DIM / 4)       // 442368
#define NWP4 (DIM * DIM / 4)         // 147456
#define NCONV_TOTAL (NX4 + NWQ4 + NWP4)

__global__ void conv_split_all(const float* __restrict__ x,
                               const float* __restrict__ wq,
                               const float* __restrict__ wp)
{
    int i = blockIdx.x * blockDim.x + threadIdx.x;
    if (i < NX4) {
        ((uint2*)g_xh)[i] = pack4_hi(((const float4*)x)[i]);
    } else if (i < NX4 + NWQ4) {
        int j = i - NX4;
        uint2 hi, lo;
        split4_f16(((const float4*)wq)[j], hi, lo);
        ((uint2*)g_wqh)[j] = hi;
        ((uint2*)g_wql)[j] = lo;
    } else if (i < NCONV_TOTAL) {
        int j = i - NX4 - NWQ4;
        uint2 hi, lo;
        split4_f16(((const float4*)wp)[j], hi, lo);
        ((uint2*)g_wph)[j] = hi;
        ((uint2*)g_wpl)[j] = lo;
    }
}

// ---------------------------------------------------------------------------
// fp16 2-term GEMM: C = Ah·Bh + Ah·Bl. K=32 chunks, 3 smem stages (Ah|Bh|Bl),
// cp.async prefetch distance 2, ONE __syncthreads per chunk. CTA 128x128,
// 8 warps (64x32), 80B row stride (conflict-free ldmatrix).
// ---------------------------------------------------------------------------
#define KC2 32
#define NCH2 (DIM / KC2)               // 24 chunks
#define LDB2 80
#define T2 (128 * LDB2)                // 10240 B per tile
#define STAGE3 (3 * T2)                // 30720 B per stage (Ah|Bh|Bl)
#define GEMM_SMEM3 (3 * STAGE3)        // 92160 B (2 CTAs/SM: 184320 <= 228K)

__device__ __forceinline__ void f16_mainloop(
    const __half* __restrict__ Ah,
    const __half* __restrict__ Bh, const __half* __restrict__ Bl,
    int bm, int bn, uint32_t sb, float acc[4][4][4])
{
    const int tid  = threadIdx.x;
    const int lane = tid & 31;
    const int wid  = tid >> 5;
    const int wm   = (wid >> 2) * 64;
    const int wn   = (wid & 3) * 32;

    #pragma unroll
    for (int mi = 0; mi < 4; mi++)
        #pragma unroll
        for (int nj = 0; nj < 4; nj++)
            #pragma unroll
            for (int r = 0; r < 4; r++) acc[mi][nj][r] = 0.f;

    const uint32_t a_row  = (lane & 7) + ((lane >> 3) & 1) * 8;
    const uint32_t a_kb   = ((lane >> 4) & 1) * 16;
    // x4 B-frag mapping (attention-verified): nj-pair rows + k-half select
    const uint32_t kp_row = ((lane >> 4) << 3) + (lane & 7);
    const uint32_t kp_kb  = ((lane >> 3) & 1) << 4;

    auto issue = [&](int c) {
        int ko = c * KC2;
        uint32_t st = sb + (uint32_t)(c % 3) * STAGE3;
        #pragma unroll
        for (int i = 0; i < 2; i++) {
            int idx = tid + i * 256;          // 512 16B-chunks per tile
            int row = idx >> 2, col = idx & 3;
            uint32_t doff = row * LDB2 + col * 16;
            size_t aoff = (size_t)(bm + row) * DIM + ko + col * 8;
            size_t boff = (size_t)(bn + row) * DIM + ko + col * 8;
            CP16(st + 0 * T2 + doff, Ah + aoff);
            CP16(st + 1 * T2 + doff, Bh + boff);
            CP16(st + 2 * T2 + doff, Bl + boff);
        }
        CP_COMMIT;
    };

    issue(0);
    issue(1);

    for (int c = 0; c < NCH2; c++) {
        if (c == NCH2 - 1) { CP_WAIT0; } else { CP_WAIT1; }
        __syncthreads();                       // chunk c visible; c-1 reads done
        if (c + 2 < NCH2) issue(c + 2);        // stage consumed at c-1: safe
        uint32_t st = sb + (uint32_t)(c % 3) * STAGE3;
        #pragma unroll
        for (int k16 = 0; k16 < 2; k16++) {
            const uint32_t kb = k16 * 32;
            uint32_t bh[2][4], bl[2][4];
            #pragma unroll
            for (int njp = 0; njp < 2; njp++) {
                uint32_t bd = st + T2 + (wn + njp * 16 + kp_row) * LDB2 + kb + kp_kb;
                LDSM_X4(bh[njp][0], bh[njp][1], bh[njp][2], bh[njp][3], bd);
                LDSM_X4(bl[njp][0], bl[njp][1], bl[njp][2], bl[njp][3], bd + T2);
            }
            #pragma unroll
            for (int mi = 0; mi < 4; mi++) {
                uint32_t ad = st + (wm + mi * 16 + a_row) * LDB2 + kb + a_kb;
                uint32_t a0, a1, a2, a3;
                LDSM_X4(a0, a1, a2, a3, ad);
                #pragma unroll
                for (int njp = 0; njp < 2; njp++) {
                    MMA16816(acc[mi][njp * 2],     a0, a1, a2, a3, bh[njp][0], bh[njp][1]);
                    MMA16816(acc[mi][njp * 2 + 1], a0, a1, a2, a3, bh[njp][2], bh[njp][3]);
                    MMA16816(acc[mi][njp * 2],     a0, a1, a2, a3, bl[njp][0], bl[njp][1]);
                    MMA16816(acc[mi][njp * 2 + 1], a0, a1, a2, a3, bl[njp][2], bl[njp][3]);
                }
            }
        }
    }
}

// GEMM 1: qkv = x @ w_qkv^T + b_qkv -> fp16 [b,h,n,d]; Q scaled by QSCALE, hi only
__global__ __launch_bounds__(256, 2)
void gemm_qkv_mma(const float* __restrict__ bias)
{
    extern __shared__ __align__(128) char smem[];
    const int bm = blockIdx.y * 128, bn = blockIdx.x * 128;
    float acc[4][4][4];
    f16_mainloop(g_xh, g_wqh, g_wql, bm, bn, smem_to_u32(smem), acc);

    const int lane = threadIdx.x & 31;
    const int wid  = threadIdx.x >> 5;
    const int wm   = (wid >> 2) * 64;
    const int wn   = (wid & 3) * 32;
    const int s = blockIdx.x / 6;                 // 0=q, 1=k, 2=v
    __half* hb = (s == 0) ? g_qh : (s == 1) ? g_kh : g_vh;
    __half* lb = (s == 1) ? g_kl : g_vl;          // unused for s==0

    #pragma unroll
    for (int mi = 0; mi < 4; mi++) {
        int m0 = bm + wm + mi * 16 + (lane >> 2);
        #pragma unroll
        for (int nj = 0; nj < 4; nj++) {
            int o  = bn + wn + nj * 8 + (lane & 3) * 2;
            int rl = o - s * DIM;
            int h = rl >> 6, d = rl & 63;
            float b0 = bias[o], b1 = bias[o + 1];
            #pragma unroll
            for (int rr = 0; rr < 2; rr++) {
                int m  = m0 + rr * 8;
                int bb = m >> 10, nn = m & 1023;
                float v0 = acc[mi][nj][rr * 2 + 0] + b0;
                float v1 = acc[mi][nj][rr * 2 + 1] + b1;
                size_t idx = ((size_t)(bb * NHEAD + h) * SEQ + nn) * HDIM + d;
                if (s == 0) {
                    *(uint32_t*)&hb[idx] = pack2_f16(v0 * QSCALE, v1 * QSCALE);
                } else {
                    uint32_t hi, lo;
                    split2_f16(v0, v1, hi, lo);
                    *(uint32_t*)&hb[idx] = hi;
                    *(uint32_t*)&lb[idx] = lo;
                }
            }
        }
    }
}

// GEMM 2: out = att @ w_proj^T + b_proj
__global__ __launch_bounds__(256, 2)
void gemm_proj_mma(const float* __restrict__ bias, float* __restrict__ out)
{
    extern __shared__ __align__(128) char smem[];
    const int bm = blockIdx.y * 128, bn = blockIdx.x * 128;
    float acc[4][4][4];
    f16_mainloop(g_ath, g_wph, g_wpl, bm, bn, smem_to_u32(smem), acc);

    const int lane = threadIdx.x & 31;
    const int wid  = threadIdx.x >> 5;
    const int wm   = (wid >> 2) * 64;
    const int wn   = (wid & 3) * 32;

    #pragma unroll
    for (int mi = 0; mi < 4; mi++) {
        int m0 = bm + wm + mi * 16 + (lane >> 2);
        #pragma unroll
        for (int nj = 0; nj < 4; nj++) {
            int o = bn + wn + nj * 8 + (lane & 3) * 2;
            float b0 = bias[o], b1 = bias[o + 1];
            #pragma unroll
            for (int rr = 0; rr < 2; rr++) {
                int m = m0 + rr * 8;
                float2 v = make_float2(acc[mi][nj][rr * 2 + 0] + b0,
                                       acc[mi][nj][rr * 2 + 1] + b1);
                *(float2*)&out[(size_t)m * DIM + o] = v;
            }
        }
    }
}

// ---------------------------------------------------------------------------
// Flash attention, fp16 2-term: S = Qh·(Kh+Kl), O += Ph·(Vh+Vl).
// exp2-domain softmax (scale folded into Q). cp.async double-buffered K/V,
// 1 sync per block, x4 ldmatrix, 2 CTAs/SM.
// ---------------------------------------------------------------------------
#define KB 64
#define ATLDB 144
#define ATILE (KB * ATLDB)             // 9216 per tile
#define ASTAGE (4 * ATILE)             // 36864 per stage (Kh|Kl|Vh|Vl)
#define ATT_SMEM (2 * ASTAGE)          // 73728 dynamic

__global__ __launch_bounds__(256, 2)
void attn_mma()
{
    extern __shared__ __align__(128) char smem[];
    const uint32_t sb = smem_to_u32(smem);
    const int tid  = threadIdx.x;
    const int lane = tid & 31;
    const int wid  = tid >> 5;
    const int wm   = wid * 16;
    const int bh   = blockIdx.x;
    const int bb   = bh / NHEAD;
    const int h    = bh - bb * NHEAD;
    const int qb   = blockIdx.y;

    const size_t headoff = (size_t)bh * SEQ * HDIM;
    const size_t qoff    = headoff + (size_t)qb * 128 * HDIM;

    // ---- Stage Q hi (128x64 fp16) ----
    {
        const uint4* qh4 = (const uint4*)(g_qh + qoff);
        #pragma unroll
        for (int i = 0; i < 4; i++) {
            int idx = tid + i * 256;
            int row = idx >> 3, c = idx & 7;
            *(uint4*)(smem + row * ATLDB + c * 16) = qh4[idx];
        }
    }
    __syncthreads();

    const uint32_t a_row  = (lane & 7) + ((lane >> 3) & 1) * 8;
    const uint32_t a_kb   = ((lane >> 4) & 1) * 16;
    const uint32_t kp_row = ((lane >> 4) << 3) + (lane & 7);
    const uint32_t kp_kb  = ((lane >> 3) & 1) << 4;

    uint32_t Qh[4][4];
    #pragma unroll
    for (int k = 0; k < 4; k++) {
        uint32_t ad = sb + (wm + a_row) * ATLDB + k * 32 + a_kb;
        LDSM_X4(Qh[k][0], Qh[k][1], Qh[k][2], Qh[k][3], ad);
    }
    __syncthreads();          // Q region about to be reused as K/V stage

    float O[8][4];
    #pragma unroll
    for (int nj = 0; nj < 8; nj++)
        #pragma unroll
        for (int r = 0; r < 4; r++) O[nj][r] = 0.f;
    float m0 = -1e30f, m1 = -1e30f, l0 = 0.f, l1 = 0.f;

    auto issue_kv = [&](int t) {
        uint32_t st = sb + (uint32_t)(t & 1) * ASTAGE;
        size_t base = headoff + (size_t)t * KB * HDIM;
        #pragma unroll
        for (int i = 0; i < 2; i++) {
            int idx = tid + i * 256;
            int row = idx >> 3, col = idx & 7;
            uint32_t doff = row * ATLDB + col * 16;
            size_t goff = base + row * HDIM + col * 8;
            CP16(st + 0 * ATILE + doff, g_kh + goff);
            CP16(st + 1 * ATILE + doff, g_kl + goff);
            CP16(st + 2 * ATILE + doff, g_vh + goff);
            CP16(st + 3 * ATILE + doff, g_vl + goff);
        }
        CP_COMMIT;
    };

    issue_kv(0);

    for (int tb = 0; tb < SEQ / KB; tb++) {
        CP_WAIT0;
        __syncthreads();
        if (tb + 1 < SEQ / KB) issue_kv(tb + 1);
        uint32_t st = sb + (uint32_t)(tb & 1) * ASTAGE;

        // ---- S = Qh K^T (log2-scaled; scale folded into Q) ----
        float S[8][4];
        #pragma unroll
        for (int nj = 0; nj < 8; nj++)
            #pragma unroll
            for (int r = 0; r < 4; r++) S[nj][r] = 0.f;

        #pragma unroll
        for (int k = 0; k < 4; k++) {
            #pragma unroll
            for (int njp = 0; njp < 4; njp++) {
                uint32_t bd = st + (njp * 16 + kp_row) * ATLDB + k * 32 + kp_kb;
                uint32_t kh0, kh1, kh2, kh3, kl0, kl1, kl2, kl3;
                LDSM_X4(kh0, kh1, kh2, kh3, bd);
                LDSM_X4(kl0, kl1, kl2, kl3, bd + ATILE);
                MMA16816(S[njp * 2],     Qh[k][0], Qh[k][1], Qh[k][2], Qh[k][3], kh0, kh1);
                MMA16816(S[njp * 2 + 1], Qh[k][0], Qh[k][1], Qh[k][2], Qh[k][3], kh2, kh3);
                MMA16816(S[njp * 2],     Qh[k][0], Qh[k][1], Qh[k][2], Qh[k][3], kl0, kl1);
                MMA16816(S[njp * 2 + 1], Qh[k][0], Qh[k][1], Qh[k][2], Qh[k][3], kl2, kl3);
            }
        }

        // ---- online softmax in exp2 domain ----
        float bm0 = S[0][0], bm1 = S[0][2];
        #pragma unroll
        for (int nj = 0; nj < 8; nj++) {
            bm0 = fmaxf(bm0, fmaxf(S[nj][0], S[nj][1]));
            bm1 = fmaxf(bm1, fmaxf(S[nj][2], S[nj][3]));
        }
        bm0 = fmaxf(bm0, __shfl_xor_sync(0xffffffffu, bm0, 1));
        bm0 = fmaxf(bm0, __shfl_xor_sync(0xffffffffu, bm0, 2));
        bm1 = fmaxf(bm1, __shfl_xor_sync(0xffffffffu, bm1, 1));
        bm1 = fmaxf(bm1, __shfl_xor_sync(0xffffffffu, bm1, 2));
        float nm0 = fmaxf(m0, bm0), nm1 = fmaxf(m1, bm1);
        float c0 = fexp2(m0 - nm0),  c1 = fexp2(m1 - nm1);
        m0 = nm0; m1 = nm1;

        float rs0 = 0.f, rs1 = 0.f;
        #pragma unroll
        for (int nj = 0; nj < 8; nj++) {
            S[nj][0] = fexp2(S[nj][0] - m0);
            S[nj][1] = fexp2(S[nj][1] - m0);
            S[nj][2] = fexp2(S[nj][2] - m1);
            S[nj][3] = fexp2(S[nj][3] - m1);
            rs0 += S[nj][0] + S[nj][1];
            rs1 += S[nj][2] + S[nj][3];
        }
        rs0 += __shfl_xor_sync(0xffffffffu, rs0, 1);
        rs0 += __shfl_xor_sync(0xffffffffu, rs0, 2);
        rs1 += __shfl_xor_sync(0xffffffffu, rs1, 1);
        rs1 += __shfl_xor_sync(0xffffffffu, rs1, 2);
        l0 = l0 * c0 + rs0;
        l1 = l1 * c1 + rs1;
        #pragma unroll
        for (int nj = 0; nj < 8; nj++) {
            O[nj][0] *= c0; O[nj][1] *= c0;
            O[nj][2] *= c1; O[nj][3] *= c1;
        }

        // ---- P (C-layout) -> fp16 A-frags, hi only ----
        uint32_t Ph[4][4];
        #pragma unroll
        for (int t = 0; t < 4; t++) {
            Ph[t][0] = pack2_f16(S[2 * t][0],     S[2 * t][1]);
            Ph[t][1] = pack2_f16(S[2 * t][2],     S[2 * t][3]);
            Ph[t][2] = pack2_f16(S[2 * t + 1][0], S[2 * t + 1][1]);
            Ph[t][3] = pack2_f16(S[2 * t + 1][2], S[2 * t + 1][3]);
        }

        // ---- O += Ph (Vh + Vl) via x4 trans ldmatrix ----
        #pragma unroll
        for (int t = 0; t < 4; t++) {
            #pragma unroll
            for (int njp = 0; njp < 4; njp++) {
                uint32_t vaddr = st + 2 * ATILE + (t * 16 + (lane & 15)) * ATLDB
                                 + njp * 32 + ((lane >> 4) << 4);
                uint32_t vh0, vh1, vh2, vh3, vl0, vl1, vl2, vl3;
                LDSM_X4_T(vh0, vh1, vh2, vh3, vaddr);
                LDSM_X4_T(vl0, vl1, vl2, vl3, vaddr + ATILE);
                MMA16816(O[njp * 2],     Ph[t][0], Ph[t][1], Ph[t][2], Ph[t][3], vh0, vh1);
                MMA16816(O[njp * 2 + 1], Ph[t][0], Ph[t][1], Ph[t][2], Ph[t][3], vh2, vh3);
                MMA16816(O[njp * 2],     Ph[t][0], Ph[t][1], Ph[t][2], Ph[t][3], vl0, vl1);
                MMA16816(O[njp * 2 + 1], Ph[t][0], Ph[t][1], Ph[t][2], Ph[t][3], vl2, vl3);
            }
        }
        // next iteration's sync orders stage reuse
    }

    // ---- epilogue: normalize, write fp16 hi (feeds proj GEMM A-side) ----
    float inv0 = 1.0f / l0, inv1 = 1.0f / l1;
    int row0 = qb * 128 + wm + (lane >> 2);
    int row1 = row0 + 8;
    size_t o0 = ((size_t)bb * SEQ + row0) * DIM + h * HDIM;
    size_t o1 = ((size_t)bb * SEQ + row1) * DIM + h * HDIM;
    #pragma unroll
    for (int nj = 0; nj < 8; nj++) {
        int col = nj * 8 + (lane & 3) * 2;
        *(uint32_t*)&g_ath[o0 + col] = pack2_f16(O[nj][0] * inv0, O[nj][1] * inv0);
        *(uint32_t*)&g_ath[o1 + col] = pack2_f16(O[nj][2] * inv1, O[nj][3] * inv1);
    }
}

// ---------------------------------------------------------------------------
extern "C" void kernel_launch(void* const* d_in, const int* in_sizes, int n_in,
                              void* d_out, int out_size)
{
    const float* x      = (const float*)d_in[0];
    const float* w_qkv  = (const float*)d_in[1];
    const float* b_qkv  = (const float*)d_in[2];
    const float* w_proj = (const float*)d_in[3];
    const float* b_proj = (const float*)d_in[4];
    float* out = (float*)d_out;

    cudaFuncSetAttribute(gemm_qkv_mma,  cudaFuncAttributeMaxDynamicSharedMemorySize, GEMM_SMEM3);
    cudaFuncSetAttribute(gemm_proj_mma, cudaFuncAttributeMaxDynamicSharedMemorySize, GEMM_SMEM3);
    cudaFuncSetAttribute(attn_mma,      cudaFuncAttributeMaxDynamicSharedMemorySize, ATT_SMEM);

    conv_split_all<<<(NCONV_TOTAL + 255) / 256, 256>>>(x, w_qkv, w_proj);
    gemm_qkv_mma<<<dim3(QKV_N / 128, MROWS / 128), 256, GEMM_SMEM3>>>(b_qkv);
    attn_mma<<<dim3(BATCH * NHEAD, SEQ / 128), 256, ATT_SMEM>>>();
    gemm_proj_mma<<<dim3(DIM / 128, MROWS / 128), 256, GEMM_SMEM3>>>(b_proj, out);
}

// round 11
// speedup vs baseline: 4.6104x; 1.0942x over previous
#include <cuda_runtime.h>
#include <cuda_fp16.h>
#include <cstdint>

// Problem constants
#define BATCH 8
#define SEQ 1024
#define DIM 768
#define NHEAD 12
#define HDIM 64
#define MROWS (BATCH * SEQ)          // 8192
#define QKV_N (3 * DIM)              // 2304
#define QKV_ELEMS (BATCH * NHEAD * SEQ * HDIM)

// log2(e)/8 folded into Q so softmax runs in exp2 domain
#define QSCALE (0.125f * 1.44269504088896f)

// Scratch (allocation-free rule: __device__ globals). fp16 mixed-precision:
// A-side + K keep HI only; GEMM B-side weights and V keep HI+LO.
__device__ __half g_xh[MROWS * DIM];
__device__ __half g_wqh[QKV_N * DIM], g_wql[QKV_N * DIM];
__device__ __half g_wph[DIM * DIM],   g_wpl[DIM * DIM];
__device__ __half g_qh[QKV_ELEMS];                        // [b,h,n,d], pre-scaled
__device__ __half g_kh[QKV_ELEMS];                        // hi only (R11)
__device__ __half g_vh[QKV_ELEMS], g_vl[QKV_ELEMS];
__device__ __half g_ath[MROWS * DIM];                     // attn out [b,n,h*d]

// ---------------------------------------------------------------------------
// PTX helpers (baseline PTX only — tcgen05 rejected by this toolchain's sm_103)
// ---------------------------------------------------------------------------
__device__ __forceinline__ uint32_t smem_to_u32(const void* p) {
    uint32_t a;
    asm("{ .reg .u64 t; cvta.to.shared.u64 t, %1; cvt.u32.u64 %0, t; }"
        : "=r"(a) : "l"(p));
    return a;
}

#define LDSM_X4(r0, r1, r2, r3, addr) \
    asm volatile("ldmatrix.sync.aligned.m8n8.x4.shared.b16 {%0,%1,%2,%3}, [%4];" \
        : "=r"(r0), "=r"(r1), "=r"(r2), "=r"(r3) : "r"(addr))
#define LDSM_X4_T(r0, r1, r2, r3, addr) \
    asm volatile("ldmatrix.sync.aligned.m8n8.x4.trans.shared.b16 {%0,%1,%2,%3}, [%4];" \
        : "=r"(r0), "=r"(r1), "=r"(r2), "=r"(r3) : "r"(addr))

// fp16 MMA, fp32 accumulate
#define MMA16816(d, a0, a1, a2, a3, b0, b1) \
    asm volatile("mma.sync.aligned.m16n8k16.row.col.f32.f16.f16.f32 " \
        "{%0,%1,%2,%3}, {%4,%5,%6,%7}, {%8,%9}, {%0,%1,%2,%3};" \
        : "+f"((d)[0]), "+f"((d)[1]), "+f"((d)[2]), "+f"((d)[3]) \
        : "r"(a0), "r"(a1), "r"(a2), "r"(a3), "r"(b0), "r"(b1))

#define CP16(dst, src) \
    asm volatile("cp.async.cg.shared.global [%0], [%1], 16;" \
        :: "r"(dst), "l"(src))
#define CP_COMMIT asm volatile("cp.async.commit_group;")
#define CP_WAIT1  asm volatile("cp.async.wait_group 1;")
#define CP_WAIT0  asm volatile("cp.async.wait_group 0;")

// fp16 pack helpers
__device__ __forceinline__ uint32_t pack2_f16(float a, float b) {
    __half2 h = __floats2half2_rn(a, b);
    return *reinterpret_cast<uint32_t*>(&h);
}
__device__ __forceinline__ void split2_f16(float a, float b,
                                           uint32_t& hi, uint32_t& lo) {
    __half2 h = __floats2half2_rn(a, b);
    float2 f = __half22float2(h);
    __half2 l = __floats2half2_rn(a - f.x, b - f.y);
    hi = *reinterpret_cast<uint32_t*>(&h);
    lo = *reinterpret_cast<uint32_t*>(&l);
}
__device__ __forceinline__ uint2 pack4_hi(float4 v) {
    return make_uint2(pack2_f16(v.x, v.y), pack2_f16(v.z, v.w));
}
__device__ __forceinline__ void split4_f16(float4 v, uint2& hi, uint2& lo) {
    uint32_t h0, l0, h1, l1;
    split2_f16(v.x, v.y, h0, l0);
    split2_f16(v.z, v.w, h1, l1);
    hi = make_uint2(h0, h1);
    lo = make_uint2(l0, l1);
}

// exp2 on the FMA pipe (scores already in log2 domain via QSCALE).
__device__ __forceinline__ float fexp2(float x) {
    x = fmaxf(x, -100.0f);
    int   e = __float2int_rn(x);
    float f = x - (float)e;
    float p = 9.6179669e-3f;
    p = fmaf(p, f, 5.5504109e-2f);
    p = fmaf(p, f, 2.4022651e-1f);
    p = fmaf(p, f, 6.9314718e-1f);
    p = fmaf(p, f, 1.0f);
    return __int_as_float(__float_as_int(p) + (e << 23));
}

// ---------------------------------------------------------------------------
// Merged pre-split kernel: x (hi only), w_qkv (hi+lo), w_proj (hi+lo).
// Output globals referenced in device code only (host-shadow bug, R5/R6).
// ---------------------------------------------------------------------------
#define NX4  (MROWS * DIM / 4)
#define NWQ4 (QKV_N * DIM / 4)
#define NWP4 (DIM * DIM / 4)
#define NCONV_TOTAL (NX4 + NWQ4 + NWP4)

__global__ void conv_split_all(const float* __restrict__ x,
                               const float* __restrict__ wq,
                               const float* __restrict__ wp)
{
    int i = blockIdx.x * blockDim.x + threadIdx.x;
    if (i < NX4) {
        ((uint2*)g_xh)[i] = pack4_hi(((const float4*)x)[i]);
    } else if (i < NX4 + NWQ4) {
        int j = i - NX4;
        uint2 hi, lo;
        split4_f16(((const float4*)wq)[j], hi, lo);
        ((uint2*)g_wqh)[j] = hi;
        ((uint2*)g_wql)[j] = lo;
    } else if (i < NCONV_TOTAL) {
        int j = i - NX4 - NWQ4;
        uint2 hi, lo;
        split4_f16(((const float4*)wp)[j], hi, lo);
        ((uint2*)g_wph)[j] = hi;
        ((uint2*)g_wpl)[j] = lo;
    }
}

// ---------------------------------------------------------------------------
// fp16 2-term GEMM: C = Ah·Bh + Ah·Bl. K=32 chunks, 3 smem stages (Ah|Bh|Bl),
// cp.async prefetch distance 2, ONE __syncthreads per chunk. (R10 passing.)
// ---------------------------------------------------------------------------
#define KC2 32
#define NCH2 (DIM / KC2)
#define LDB2 80
#define T2 (128 * LDB2)
#define STAGE3 (3 * T2)
#define GEMM_SMEM3 (3 * STAGE3)

__device__ __forceinline__ void f16_mainloop(
    const __half* __restrict__ Ah,
    const __half* __restrict__ Bh, const __half* __restrict__ Bl,
    int bm, int bn, uint32_t sb, float acc[4][4][4])
{
    const int tid  = threadIdx.x;
    const int lane = tid & 31;
    const int wid  = tid >> 5;
    const int wm   = (wid >> 2) * 64;
    const int wn   = (wid & 3) * 32;

    #pragma unroll
    for (int mi = 0; mi < 4; mi++)
        #pragma unroll
        for (int nj = 0; nj < 4; nj++)
            #pragma unroll
            for (int r = 0; r < 4; r++) acc[mi][nj][r] = 0.f;

    const uint32_t a_row  = (lane & 7) + ((lane >> 3) & 1) * 8;
    const uint32_t a_kb   = ((lane >> 4) & 1) * 16;
    const uint32_t kp_row = ((lane >> 4) << 3) + (lane & 7);
    const uint32_t kp_kb  = ((lane >> 3) & 1) << 4;

    auto issue = [&](int c) {
        int ko = c * KC2;
        uint32_t st = sb + (uint32_t)(c % 3) * STAGE3;
        #pragma unroll
        for (int i = 0; i < 2; i++) {
            int idx = tid + i * 256;
            int row = idx >> 2, col = idx & 3;
            uint32_t doff = row * LDB2 + col * 16;
            size_t aoff = (size_t)(bm + row) * DIM + ko + col * 8;
            size_t boff = (size_t)(bn + row) * DIM + ko + col * 8;
            CP16(st + 0 * T2 + doff, Ah + aoff);
            CP16(st + 1 * T2 + doff, Bh + boff);
            CP16(st + 2 * T2 + doff, Bl + boff);
        }
        CP_COMMIT;
    };

    issue(0);
    issue(1);

    for (int c = 0; c < NCH2; c++) {
        if (c == NCH2 - 1) { CP_WAIT0; } else { CP_WAIT1; }
        __syncthreads();
        if (c + 2 < NCH2) issue(c + 2);
        uint32_t st = sb + (uint32_t)(c % 3) * STAGE3;
        #pragma unroll
        for (int k16 = 0; k16 < 2; k16++) {
            const uint32_t kb = k16 * 32;
            uint32_t bh[2][4], bl[2][4];
            #pragma unroll
            for (int njp = 0; njp < 2; njp++) {
                uint32_t bd = st + T2 + (wn + njp * 16 + kp_row) * LDB2 + kb + kp_kb;
                LDSM_X4(bh[njp][0], bh[njp][1], bh[njp][2], bh[njp][3], bd);
                LDSM_X4(bl[njp][0], bl[njp][1], bl[njp][2], bl[njp][3], bd + T2);
            }
            #pragma unroll
            for (int mi = 0; mi < 4; mi++) {
                uint32_t ad = st + (wm + mi * 16 + a_row) * LDB2 + kb + a_kb;
                uint32_t a0, a1, a2, a3;
                LDSM_X4(a0, a1, a2, a3, ad);
                #pragma unroll
                for (int njp = 0; njp < 2; njp++) {
                    MMA16816(acc[mi][njp * 2],     a0, a1, a2, a3, bh[njp][0], bh[njp][1]);
                    MMA16816(acc[mi][njp * 2 + 1], a0, a1, a2, a3, bh[njp][2], bh[njp][3]);
                    MMA16816(acc[mi][njp * 2],     a0, a1, a2, a3, bl[njp][0], bl[njp][1]);
                    MMA16816(acc[mi][njp * 2 + 1], a0, a1, a2, a3, bl[njp][2], bl[njp][3]);
                }
            }
        }
    }
}

// GEMM 1: qkv = x @ w_qkv^T + b_qkv. Q: scaled hi. K: hi. V: hi+lo.
__global__ __launch_bounds__(256, 2)
void gemm_qkv_mma(const float* __restrict__ bias)
{
    extern __shared__ __align__(128) char smem[];
    const int bm = blockIdx.y * 128, bn = blockIdx.x * 128;
    float acc[4][4][4];
    f16_mainloop(g_xh, g_wqh, g_wql, bm, bn, smem_to_u32(smem), acc);

    const int lane = threadIdx.x & 31;
    const int wid  = threadIdx.x >> 5;
    const int wm   = (wid >> 2) * 64;
    const int wn   = (wid & 3) * 32;
    const int s = blockIdx.x / 6;                 // 0=q, 1=k, 2=v
    __half* hb = (s == 0) ? g_qh : (s == 1) ? g_kh : g_vh;

    #pragma unroll
    for (int mi = 0; mi < 4; mi++) {
        int m0 = bm + wm + mi * 16 + (lane >> 2);
        #pragma unroll
        for (int nj = 0; nj < 4; nj++) {
            int o  = bn + wn + nj * 8 + (lane & 3) * 2;
            int rl = o - s * DIM;
            int h = rl >> 6, d = rl & 63;
            float b0 = bias[o], b1 = bias[o + 1];
            #pragma unroll
            for (int rr = 0; rr < 2; rr++) {
                int m  = m0 + rr * 8;
                int bb = m >> 10, nn = m & 1023;
                float v0 = acc[mi][nj][rr * 2 + 0] + b0;
                float v1 = acc[mi][nj][rr * 2 + 1] + b1;
                size_t idx = ((size_t)(bb * NHEAD + h) * SEQ + nn) * HDIM + d;
                if (s == 0) {
                    *(uint32_t*)&hb[idx] = pack2_f16(v0 * QSCALE, v1 * QSCALE);
                } else if (s == 1) {
                    *(uint32_t*)&hb[idx] = pack2_f16(v0, v1);
                } else {
                    uint32_t hi, lo;
                    split2_f16(v0, v1, hi, lo);
                    *(uint32_t*)&hb[idx] = hi;
                    *(uint32_t*)&g_vl[idx] = lo;
                }
            }
        }
    }
}

// GEMM 2: out = att @ w_proj^T + b_proj
__global__ __launch_bounds__(256, 2)
void gemm_proj_mma(const float* __restrict__ bias, float* __restrict__ out)
{
    extern __shared__ __align__(128) char smem[];
    const int bm = blockIdx.y * 128, bn = blockIdx.x * 128;
    float acc[4][4][4];
    f16_mainloop(g_ath, g_wph, g_wpl, bm, bn, smem_to_u32(smem), acc);

    const int lane = threadIdx.x & 31;
    const int wid  = threadIdx.x >> 5;
    const int wm   = (wid >> 2) * 64;
    const int wn   = (wid & 3) * 32;

    #pragma unroll
    for (int mi = 0; mi < 4; mi++) {
        int m0 = bm + wm + mi * 16 + (lane >> 2);
        #pragma unroll
        for (int nj = 0; nj < 4; nj++) {
            int o = bn + wn + nj * 8 + (lane & 3) * 2;
            float b0 = bias[o], b1 = bias[o + 1];
            #pragma unroll
            for (int rr = 0; rr < 2; rr++) {
                int m = m0 + rr * 8;
                float2 v = make_float2(acc[mi][nj][rr * 2 + 0] + b0,
                                       acc[mi][nj][rr * 2 + 1] + b1);
                *(float2*)&out[(size_t)m * DIM + o] = v;
            }
        }
    }
}

// ---------------------------------------------------------------------------
// Flash attention, R11: S = Qh·Kh (K hi only), O += Ph·(Vh+Vl).
// Stage = Kh|Vh|Vl (3 tiles). Warp-voted rescale skip. 2 CTAs/SM.
// ---------------------------------------------------------------------------
#define KB 64
#define ATLDB 144
#define ATILE (KB * ATLDB)             // 9216 per tile
#define ASTAGE (3 * ATILE)             // 27648 per stage (Kh|Vh|Vl)
#define ATT_SMEM (2 * ASTAGE)          // 55296 dynamic

__global__ __launch_bounds__(256, 2)
void attn_mma()
{
    extern __shared__ __align__(128) char smem[];
    const uint32_t sb = smem_to_u32(smem);
    const int tid  = threadIdx.x;
    const int lane = tid & 31;
    const int wid  = tid >> 5;
    const int wm   = wid * 16;
    const int bh   = blockIdx.x;
    const int bb   = bh / NHEAD;
    const int h    = bh - bb * NHEAD;
    const int qb   = blockIdx.y;

    const size_t headoff = (size_t)bh * SEQ * HDIM;
    const size_t qoff    = headoff + (size_t)qb * 128 * HDIM;

    // ---- Stage Q hi (128x64 fp16, 18432B -> fits in stage0's 27648B) ----
    {
        const uint4* qh4 = (const uint4*)(g_qh + qoff);
        #pragma unroll
        for (int i = 0; i < 4; i++) {
            int idx = tid + i * 256;
            int row = idx >> 3, c = idx & 7;
            *(uint4*)(smem + row * ATLDB + c * 16) = qh4[idx];
        }
    }
    __syncthreads();

    const uint32_t a_row  = (lane & 7) + ((lane >> 3) & 1) * 8;
    const uint32_t a_kb   = ((lane >> 4) & 1) * 16;
    const uint32_t kp_row = ((lane >> 4) << 3) + (lane & 7);
    const uint32_t kp_kb  = ((lane >> 3) & 1) << 4;

    uint32_t Qh[4][4];
    #pragma unroll
    for (int k = 0; k < 4; k++) {
        uint32_t ad = sb + (wm + a_row) * ATLDB + k * 32 + a_kb;
        LDSM_X4(Qh[k][0], Qh[k][1], Qh[k][2], Qh[k][3], ad);
    }
    __syncthreads();          // Q region about to be reused as K/V stage

    float O[8][4];
    #pragma unroll
    for (int nj = 0; nj < 8; nj++)
        #pragma unroll
        for (int r = 0; r < 4; r++) O[nj][r] = 0.f;
    float m0 = -1e30f, m1 = -1e30f, l0 = 0.f, l1 = 0.f;

    auto issue_kv = [&](int t) {
        uint32_t st = sb + (uint32_t)(t & 1) * ASTAGE;
        size_t base = headoff + (size_t)t * KB * HDIM;
        #pragma unroll
        for (int i = 0; i < 2; i++) {
            int idx = tid + i * 256;
            int row = idx >> 3, col = idx & 7;
            uint32_t doff = row * ATLDB + col * 16;
            size_t goff = base + row * HDIM + col * 8;
            CP16(st + 0 * ATILE + doff, g_kh + goff);
            CP16(st + 1 * ATILE + doff, g_vh + goff);
            CP16(st + 2 * ATILE + doff, g_vl + goff);
        }
        CP_COMMIT;
    };

    issue_kv(0);

    for (int tb = 0; tb < SEQ / KB; tb++) {
        CP_WAIT0;
        __syncthreads();
        if (tb + 1 < SEQ / KB) issue_kv(tb + 1);
        uint32_t st = sb + (uint32_t)(tb & 1) * ASTAGE;

        // ---- S = Qh Kh^T (log2-scaled; scale folded into Q) ----
        float S[8][4];
        #pragma unroll
        for (int nj = 0; nj < 8; nj++)
            #pragma unroll
            for (int r = 0; r < 4; r++) S[nj][r] = 0.f;

        #pragma unroll
        for (int k = 0; k < 4; k++) {
            #pragma unroll
            for (int njp = 0; njp < 4; njp++) {
                uint32_t bd = st + (njp * 16 + kp_row) * ATLDB + k * 32 + kp_kb;
                uint32_t kh0, kh1, kh2, kh3;
                LDSM_X4(kh0, kh1, kh2, kh3, bd);
                MMA16816(S[njp * 2],     Qh[k][0], Qh[k][1], Qh[k][2], Qh[k][3], kh0, kh1);
                MMA16816(S[njp * 2 + 1], Qh[k][0], Qh[k][1], Qh[k][2], Qh[k][3], kh2, kh3);
            }
        }

        // ---- online softmax in exp2 domain, warp-voted rescale skip ----
        float bm0 = S[0][0], bm1 = S[0][2];
        #pragma unroll
        for (int nj = 0; nj < 8; nj++) {
            bm0 = fmaxf(bm0, fmaxf(S[nj][0], S[nj][1]));
            bm1 = fmaxf(bm1, fmaxf(S[nj][2], S[nj][3]));
        }
        bm0 = fmaxf(bm0, __shfl_xor_sync(0xffffffffu, bm0, 1));
        bm0 = fmaxf(bm0, __shfl_xor_sync(0xffffffffu, bm0, 2));
        bm1 = fmaxf(bm1, __shfl_xor_sync(0xffffffffu, bm1, 1));
        bm1 = fmaxf(bm1, __shfl_xor_sync(0xffffffffu, bm1, 2));
        bool grew = (bm0 > m0) | (bm1 > m1);
        if (__any_sync(0xffffffffu, grew)) {
            float nm0 = fmaxf(m0, bm0), nm1 = fmaxf(m1, bm1);
            float c0 = fexp2(m0 - nm0),  c1 = fexp2(m1 - nm1);
            m0 = nm0; m1 = nm1;
            l0 *= c0; l1 *= c1;
            #pragma unroll
            for (int nj = 0; nj < 8; nj++) {
                O[nj][0] *= c0; O[nj][1] *= c0;
                O[nj][2] *= c1; O[nj][3] *= c1;
            }
        }

        float rs0 = 0.f, rs1 = 0.f;
        #pragma unroll
        for (int nj = 0; nj < 8; nj++) {
            S[nj][0] = fexp2(S[nj][0] - m0);
            S[nj][1] = fexp2(S[nj][1] - m0);
            S[nj][2] = fexp2(S[nj][2] - m1);
            S[nj][3] = fexp2(S[nj][3] - m1);
            rs0 += S[nj][0] + S[nj][1];
            rs1 += S[nj][2] + S[nj][3];
        }
        rs0 += __shfl_xor_sync(0xffffffffu, rs0, 1);
        rs0 += __shfl_xor_sync(0xffffffffu, rs0, 2);
        rs1 += __shfl_xor_sync(0xffffffffu, rs1, 1);
        rs1 += __shfl_xor_sync(0xffffffffu, rs1, 2);
        l0 += rs0;
        l1 += rs1;

        // ---- P (C-layout) -> fp16 A-frags, hi only ----
        uint32_t Ph[4][4];
        #pragma unroll
        for (int t = 0; t < 4; t++) {
            Ph[t][0] = pack2_f16(S[2 * t][0],     S[2 * t][1]);
            Ph[t][1] = pack2_f16(S[2 * t][2],     S[2 * t][3]);
            Ph[t][2] = pack2_f16(S[2 * t + 1][0], S[2 * t + 1][1]);
            Ph[t][3] = pack2_f16(S[2 * t + 1][2], S[2 * t + 1][3]);
        }

        // ---- O += Ph (Vh + Vl) via x4 trans ldmatrix ----
        #pragma unroll
        for (int t = 0; t < 4; t++) {
            #pragma unroll
            for (int njp = 0; njp < 4; njp++) {
                uint32_t vaddr = st + 1 * ATILE + (t * 16 + (lane & 15)) * ATLDB
                                 + njp * 32 + ((lane >> 4) << 4);
                uint32_t vh0, vh1, vh2, vh3, vl0, vl1, vl2, vl3;
                LDSM_X4_T(vh0, vh1, vh2, vh3, vaddr);
                LDSM_X4_T(vl0, vl1, vl2, vl3, vaddr + ATILE);
                MMA16816(O[njp * 2],     Ph[t][0], Ph[t][1], Ph[t][2], Ph[t][3], vh0, vh1);
                MMA16816(O[njp * 2 + 1], Ph[t][0], Ph[t][1], Ph[t][2], Ph[t][3], vh2, vh3);
                MMA16816(O[njp * 2],     Ph[t][0], Ph[t][1], Ph[t][2], Ph[t][3], vl0, vl1);
                MMA16816(O[njp * 2 + 1], Ph[t][0], Ph[t][1], Ph[t][2], Ph[t][3], vl2, vl3);
            }
        }
        // next iteration's sync orders stage reuse
    }

    // ---- epilogue: normalize, write fp16 hi (feeds proj GEMM A-side) ----
    float inv0 = 1.0f / l0, inv1 = 1.0f / l1;
    int row0 = qb * 128 + wm + (lane >> 2);
    int row1 = row0 + 8;
    size_t o0 = ((size_t)bb * SEQ + row0) * DIM + h * HDIM;
    size_t o1 = ((size_t)bb * SEQ + row1) * DIM + h * HDIM;
    #pragma unroll
    for (int nj = 0; nj < 8; nj++) {
        int col = nj * 8 + (lane & 3) * 2;
        *(uint32_t*)&g_ath[o0 + col] = pack2_f16(O[nj][0] * inv0, O[nj][1] * inv0);
        *(uint32_t*)&g_ath[o1 + col] = pack2_f16(O[nj][2] * inv1, O[nj][3] * inv1);
    }
}

// ---------------------------------------------------------------------------
extern "C" void kernel_launch(void* const* d_in, const int* in_sizes, int n_in,
                              void* d_out, int out_size)
{
    const float* x      = (const float*)d_in[0];
    const float* w_qkv  = (const float*)d_in[1];
    const float* b_qkv  = (const float*)d_in[2];
    const float* w_proj = (const float*)d_in[3];
    const float* b_proj = (const float*)d_in[4];
    float* out = (float*)d_out;

    cudaFuncSetAttribute(gemm_qkv_mma,  cudaFuncAttributeMaxDynamicSharedMemorySize, GEMM_SMEM3);
    cudaFuncSetAttribute(gemm_proj_mma, cudaFuncAttributeMaxDynamicSharedMemorySize, GEMM_SMEM3);
    cudaFuncSetAttribute(attn_mma,      cudaFuncAttributeMaxDynamicSharedMemorySize, ATT_SMEM);

    conv_split_all<<<(NCONV_TOTAL + 255) / 256, 256>>>(x, w_qkv, w_proj);
    gemm_qkv_mma<<<dim3(QKV_N / 128, MROWS / 128), 256, GEMM_SMEM3>>>(b_qkv);
    attn_mma<<<dim3(BATCH * NHEAD, SEQ / 128), 256, ATT_SMEM>>>();
    gemm_proj_mma<<<dim3(DIM / 128, MROWS / 128), 256, GEMM_SMEM3>>>(b_proj, out);
}

// round 14
// speedup vs baseline: 4.7364x; 1.0273x over previous
#include <cuda_runtime.h>
#include <cuda_fp16.h>
#include <cstdint>

// Problem constants
#define BATCH 8
#define SEQ 1024
#define DIM 768
#define NHEAD 12
#define HDIM 64
#define MROWS (BATCH * SEQ)          // 8192
#define QKV_N (3 * DIM)              // 2304
#define QKV_ELEMS (BATCH * NHEAD * SEQ * HDIM)

// log2(e)/8 folded into Q so softmax runs in exp2 domain
#define QSCALE (0.125f * 1.44269504088896f)

// Scratch (allocation-free rule: __device__ globals). fp16 mixed-precision:
// A-side + K keep HI only; GEMM B-side weights and V keep HI+LO.
__device__ __half g_xh[MROWS * DIM];
__device__ __half g_wqh[QKV_N * DIM], g_wql[QKV_N * DIM];
__device__ __half g_wph[DIM * DIM],   g_wpl[DIM * DIM];
__device__ __half g_qh[QKV_ELEMS];                        // [b,h,n,d], pre-scaled
__device__ __half g_kh[QKV_ELEMS];                        // hi only
__device__ __half g_vh[QKV_ELEMS], g_vl[QKV_ELEMS];
__device__ __half g_ath[MROWS * DIM];                     // attn out [b,n,h*d]

// ---------------------------------------------------------------------------
// PTX helpers (baseline PTX only — tcgen05 rejected by this toolchain's sm_103)
// ---------------------------------------------------------------------------
__device__ __forceinline__ uint32_t smem_to_u32(const void* p) {
    uint32_t a;
    asm("{ .reg .u64 t; cvta.to.shared.u64 t, %1; cvt.u32.u64 %0, t; }"
        : "=r"(a) : "l"(p));
    return a;
}

#define LDSM_X4(r0, r1, r2, r3, addr) \
    asm volatile("ldmatrix.sync.aligned.m8n8.x4.shared.b16 {%0,%1,%2,%3}, [%4];" \
        : "=r"(r0), "=r"(r1), "=r"(r2), "=r"(r3) : "r"(addr))
#define LDSM_X4_T(r0, r1, r2, r3, addr) \
    asm volatile("ldmatrix.sync.aligned.m8n8.x4.trans.shared.b16 {%0,%1,%2,%3}, [%4];" \
        : "=r"(r0), "=r"(r1), "=r"(r2), "=r"(r3) : "r"(addr))

// fp16 MMA, fp32 accumulate
#define MMA16816(d, a0, a1, a2, a3, b0, b1) \
    asm volatile("mma.sync.aligned.m16n8k16.row.col.f32.f16.f16.f32 " \
        "{%0,%1,%2,%3}, {%4,%5,%6,%7}, {%8,%9}, {%0,%1,%2,%3};" \
        : "+f"((d)[0]), "+f"((d)[1]), "+f"((d)[2]), "+f"((d)[3]) \
        : "r"(a0), "r"(a1), "r"(a2), "r"(a3), "r"(b0), "r"(b1))

#define CP16(dst, src) \
    asm volatile("cp.async.cg.shared.global [%0], [%1], 16;" \
        :: "r"(dst), "l"(src))
#define CP_COMMIT asm volatile("cp.async.commit_group;")
#define CP_WAIT1  asm volatile("cp.async.wait_group 1;")
#define CP_WAIT0  asm volatile("cp.async.wait_group 0;")

// MUFU exp2 (single EX2 instruction; scores already in log2 domain)
__device__ __forceinline__ float ex2(float x) {
    float r;
    asm("ex2.approx.ftz.f32 %0, %1;" : "=f"(r) : "f"(x));
    return r;
}

// fp16 pack helpers
__device__ __forceinline__ uint32_t pack2_f16(float a, float b) {
    __half2 h = __floats2half2_rn(a, b);
    return *reinterpret_cast<uint32_t*>(&h);
}
__device__ __forceinline__ void split2_f16(float a, float b,
                                           uint32_t& hi, uint32_t& lo) {
    __half2 h = __floats2half2_rn(a, b);
    float2 f = __half22float2(h);
    __half2 l = __floats2half2_rn(a - f.x, b - f.y);
    hi = *reinterpret_cast<uint32_t*>(&h);
    lo = *reinterpret_cast<uint32_t*>(&l);
}
__device__ __forceinline__ uint2 pack4_hi(float4 v) {
    return make_uint2(pack2_f16(v.x, v.y), pack2_f16(v.z, v.w));
}
__device__ __forceinline__ void split4_f16(float4 v, uint2& hi, uint2& lo) {
    uint32_t h0, l0, h1, l1;
    split2_f16(v.x, v.y, h0, l0);
    split2_f16(v.z, v.w, h1, l1);
    hi = make_uint2(h0, h1);
    lo = make_uint2(l0, l1);
}

// ---------------------------------------------------------------------------
// Merged pre-split kernel: x (hi only), w_qkv (hi+lo), w_proj (hi+lo).
// Output globals referenced in device code only (host-shadow bug, R5/R6).
// ---------------------------------------------------------------------------
#define NX4  (MROWS * DIM / 4)
#define NWQ4 (QKV_N * DIM / 4)
#define NWP4 (DIM * DIM / 4)
#define NCONV_TOTAL (NX4 + NWQ4 + NWP4)

__global__ void conv_split_all(const float* __restrict__ x,
                               const float* __restrict__ wq,
                               const float* __restrict__ wp)
{
    int i = blockIdx.x * blockDim.x + threadIdx.x;
    if (i < NX4) {
        ((uint2*)g_xh)[i] = pack4_hi(((const float4*)x)[i]);
    } else if (i < NX4 + NWQ4) {
        int j = i - NX4;
        uint2 hi, lo;
        split4_f16(((const float4*)wq)[j], hi, lo);
        ((uint2*)g_wqh)[j] = hi;
        ((uint2*)g_wql)[j] = lo;
    } else if (i < NCONV_TOTAL) {
        int j = i - NX4 - NWQ4;
        uint2 hi, lo;
        split4_f16(((const float4*)wp)[j], hi, lo);
        ((uint2*)g_wph)[j] = hi;
        ((uint2*)g_wpl)[j] = lo;
    }
}

// ---------------------------------------------------------------------------
// fp16 2-term GEMM: C = Ah·Bh + Ah·Bl. K=32 chunks, 3 smem stages (A|Bh|Bl),
// cp.async prefetch distance 2, ONE __syncthreads per chunk. Templated on MI
// (warp-tile M rows = MI*16; CTA M = MI*32): MI=4 -> 128x128, MI=2 -> 64x128.
// ---------------------------------------------------------------------------
#define KC2 32
#define NCH2 (DIM / KC2)
#define LDB2 80
#define TB2 (128 * LDB2)               // B tile: 10240 B

template<int MI>
__device__ __forceinline__ void f16_mainloop(
    const __half* __restrict__ Ah,
    const __half* __restrict__ Bh, const __half* __restrict__ Bl,
    int bm, int bn, uint32_t sb, float acc[MI][4][4])
{
    constexpr int TA   = MI * 32 * LDB2;     // A tile bytes (incl. row padding)
    constexpr int STG  = TA + 2 * TB2;       // stage bytes
    constexpr int NCHA = MI * 32 * 4;        // A DATA chunks: rows x 4x16B
                                             // (R13 bug: TA/16 counted padding
                                             //  -> OOB rows; fixed)

    const int tid  = threadIdx.x;
    const int lane = tid & 31;
    const int wid  = tid >> 5;
    const int wm   = (wid >> 2) * (MI * 16);
    const int wn   = (wid & 3) * 32;

    #pragma unroll
    for (int mi = 0; mi < MI; mi++)
        #pragma unroll
        for (int nj = 0; nj < 4; nj++)
            #pragma unroll
            for (int r = 0; r < 4; r++) acc[mi][nj][r] = 0.f;

    const uint32_t a_row  = (lane & 7) + ((lane >> 3) & 1) * 8;
    const uint32_t a_kb   = ((lane >> 4) & 1) * 16;
    const uint32_t kp_row = ((lane >> 4) << 3) + (lane & 7);
    const uint32_t kp_kb  = ((lane >> 3) & 1) << 4;

    auto issue = [&](int c) {
        int ko = c * KC2;
        uint32_t st = sb + (uint32_t)(c % 3) * STG;
        #pragma unroll
        for (int i = 0; i < NCHA / 256; i++) {   // NCHA is 256 (MI=2) or 512 (MI=4)
            int idx = tid + i * 256;
            int row = idx >> 2, col = idx & 3;
            CP16(st + row * LDB2 + col * 16,
                 Ah + (size_t)(bm + row) * DIM + ko + col * 8);
        }
        #pragma unroll
        for (int i = 0; i < 2; i++) {
            int idx = tid + i * 256;
            int row = idx >> 2, col = idx & 3;
            uint32_t doff = row * LDB2 + col * 16;
            size_t boff = (size_t)(bn + row) * DIM + ko + col * 8;
            CP16(st + TA + doff,       Bh + boff);
            CP16(st + TA + TB2 + doff, Bl + boff);
        }
        CP_COMMIT;
    };

    issue(0);
    issue(1);

    for (int c = 0; c < NCH2; c++) {
        if (c == NCH2 - 1) { CP_WAIT0; } else { CP_WAIT1; }
        __syncthreads();
        if (c + 2 < NCH2) issue(c + 2);
        uint32_t st = sb + (uint32_t)(c % 3) * STG;
        #pragma unroll
        for (int k16 = 0; k16 < 2; k16++) {
            const uint32_t kb = k16 * 32;
            uint32_t bh[2][4], bl[2][4];
            #pragma unroll
            for (int njp = 0; njp < 2; njp++) {
                uint32_t bd = st + TA + (wn + njp * 16 + kp_row) * LDB2 + kb + kp_kb;
                LDSM_X4(bh[njp][0], bh[njp][1], bh[njp][2], bh[njp][3], bd);
                LDSM_X4(bl[njp][0], bl[njp][1], bl[njp][2], bl[njp][3], bd + TB2);
            }
            #pragma unroll
            for (int mi = 0; mi < MI; mi++) {
                uint32_t ad = st + (wm + mi * 16 + a_row) * LDB2 + kb + a_kb;
                uint32_t a0, a1, a2, a3;
                LDSM_X4(a0, a1, a2, a3, ad);
                #pragma unroll
                for (int njp = 0; njp < 2; njp++) {
                    MMA16816(acc[mi][njp * 2],     a0, a1, a2, a3, bh[njp][0], bh[njp][1]);
                    MMA16816(acc[mi][njp * 2 + 1], a0, a1, a2, a3, bh[njp][2], bh[njp][3]);
                    MMA16816(acc[mi][njp * 2],     a0, a1, a2, a3, bl[njp][0], bl[njp][1]);
                    MMA16816(acc[mi][njp * 2 + 1], a0, a1, a2, a3, bl[njp][2], bl[njp][3]);
                }
            }
        }
    }
}

#define GEMM_SMEM_QKV  (3 * (128 * LDB2 + 2 * TB2))   // 92160 B (MI=4)
#define GEMM_SMEM_PROJ (3 * (64 * LDB2 + 2 * TB2))    // 76800 B (MI=2)

// GEMM 1: qkv = x @ w_qkv^T + b_qkv. Q: scaled hi. K: hi. V: hi+lo.
__global__ __launch_bounds__(256, 2)
void gemm_qkv_mma(const float* __restrict__ bias)
{
    extern __shared__ __align__(128) char smem[];
    const int bm = blockIdx.y * 128, bn = blockIdx.x * 128;
    float acc[4][4][4];
    f16_mainloop<4>(g_xh, g_wqh, g_wql, bm, bn, smem_to_u32(smem), acc);

    const int lane = threadIdx.x & 31;
    const int wid  = threadIdx.x >> 5;
    const int wm   = (wid >> 2) * 64;
    const int wn   = (wid & 3) * 32;
    const int s = blockIdx.x / 6;                 // 0=q, 1=k, 2=v
    __half* hb = (s == 0) ? g_qh : (s == 1) ? g_kh : g_vh;

    #pragma unroll
    for (int mi = 0; mi < 4; mi++) {
        int m0 = bm + wm + mi * 16 + (lane >> 2);
        #pragma unroll
        for (int nj = 0; nj < 4; nj++) {
            int o  = bn + wn + nj * 8 + (lane & 3) * 2;
            int rl = o - s * DIM;
            int h = rl >> 6, d = rl & 63;
            float b0 = bias[o], b1 = bias[o + 1];
            #pragma unroll
            for (int rr = 0; rr < 2; rr++) {
                int m  = m0 + rr * 8;
                int bb = m >> 10, nn = m & 1023;
                float v0 = acc[mi][nj][rr * 2 + 0] + b0;
                float v1 = acc[mi][nj][rr * 2 + 1] + b1;
                size_t idx = ((size_t)(bb * NHEAD + h) * SEQ + nn) * HDIM + d;
                if (s == 0) {
                    *(uint32_t*)&hb[idx] = pack2_f16(v0 * QSCALE, v1 * QSCALE);
                } else if (s == 1) {
                    *(uint32_t*)&hb[idx] = pack2_f16(v0, v1);
                } else {
                    uint32_t hi, lo;
                    split2_f16(v0, v1, hi, lo);
                    *(uint32_t*)&hb[idx] = hi;
                    *(uint32_t*)&g_vl[idx] = lo;
                }
            }
        }
    }
}

// GEMM 2: out = att @ w_proj^T + b_proj. MI=2 (64-row CTAs) to fix wave tail.
__global__ __launch_bounds__(256, 2)
void gemm_proj_mma(const float* __restrict__ bias, float* __restrict__ out)
{
    extern __shared__ __align__(128) char smem[];
    const int bm = blockIdx.y * 64, bn = blockIdx.x * 128;
    float acc[2][4][4];
    f16_mainloop<2>(g_ath, g_wph, g_wpl, bm, bn, smem_to_u32(smem), acc);

    const int lane = threadIdx.x & 31;
    const int wid  = threadIdx.x >> 5;
    const int wm   = (wid >> 2) * 32;
    const int wn   = (wid & 3) * 32;

    #pragma unroll
    for (int mi = 0; mi < 2; mi++) {
        int m0 = bm + wm + mi * 16 + (lane >> 2);
        #pragma unroll
        for (int nj = 0; nj < 4; nj++) {
            int o = bn + wn + nj * 8 + (lane & 3) * 2;
            float b0 = bias[o], b1 = bias[o + 1];
            #pragma unroll
            for (int rr = 0; rr < 2; rr++) {
                int m = m0 + rr * 8;
                float2 v = make_float2(acc[mi][nj][rr * 2 + 0] + b0,
                                       acc[mi][nj][rr * 2 + 1] + b1);
                *(float2*)&out[(size_t)m * DIM + o] = v;
            }
        }
    }
}

// ---------------------------------------------------------------------------
// Flash attention: S = Qh·Kh, O += Ph·(Vh+Vl). exp2 via MUFU (ex2.approx).
// Stage = Kh|Vh|Vl, double-buffered cp.async, warp-voted rescale skip.
// ---------------------------------------------------------------------------
#define KB 64
#define ATLDB 144
#define ATILE (KB * ATLDB)             // 9216 per tile
#define ASTAGE (3 * ATILE)             // 27648 per stage (Kh|Vh|Vl)
#define ATT_SMEM (2 * ASTAGE)          // 55296 dynamic

__global__ __launch_bounds__(256, 2)
void attn_mma()
{
    extern __shared__ __align__(128) char smem[];
    const uint32_t sb = smem_to_u32(smem);
    const int tid  = threadIdx.x;
    const int lane = tid & 31;
    const int wid  = tid >> 5;
    const int wm   = wid * 16;
    const int bh   = blockIdx.x;
    const int bb   = bh / NHEAD;
    const int h    = bh - bb * NHEAD;
    const int qb   = blockIdx.y;

    const size_t headoff = (size_t)bh * SEQ * HDIM;
    const size_t qoff    = headoff + (size_t)qb * 128 * HDIM;

    // ---- Stage Q hi (128x64 fp16) ----
    {
        const uint4* qh4 = (const uint4*)(g_qh + qoff);
        #pragma unroll
        for (int i = 0; i < 4; i++) {
            int idx = tid + i * 256;
            int row = idx >> 3, c = idx & 7;
            *(uint4*)(smem + row * ATLDB + c * 16) = qh4[idx];
        }
    }
    __syncthreads();

    const uint32_t a_row  = (lane & 7) + ((lane >> 3) & 1) * 8;
    const uint32_t a_kb   = ((lane >> 4) & 1) * 16;
    const uint32_t kp_row = ((lane >> 4) << 3) + (lane & 7);
    const uint32_t kp_kb  = ((lane >> 3) & 1) << 4;

    uint32_t Qh[4][4];
    #pragma unroll
    for (int k = 0; k < 4; k++) {
        uint32_t ad = sb + (wm + a_row) * ATLDB + k * 32 + a_kb;
        LDSM_X4(Qh[k][0], Qh[k][1], Qh[k][2], Qh[k][3], ad);
    }
    __syncthreads();          // Q region about to be reused as K/V stage

    float O[8][4];
    #pragma unroll
    for (int nj = 0; nj < 8; nj++)
        #pragma unroll
        for (int r = 0; r < 4; r++) O[nj][r] = 0.f;
    float m0 = -1e30f, m1 = -1e30f, l0 = 0.f, l1 = 0.f;

    auto issue_kv = [&](int t) {
        uint32_t st = sb + (uint32_t)(t & 1) * ASTAGE;
        size_t base = headoff + (size_t)t * KB * HDIM;
        #pragma unroll
        for (int i = 0; i < 2; i++) {
            int idx = tid + i * 256;
            int row = idx >> 3, col = idx & 7;
            uint32_t doff = row * ATLDB + col * 16;
            size_t goff = base + row * HDIM + col * 8;
            CP16(st + 0 * ATILE + doff, g_kh + goff);
            CP16(st + 1 * ATILE + doff, g_vh + goff);
            CP16(st + 2 * ATILE + doff, g_vl + goff);
        }
        CP_COMMIT;
    };

    issue_kv(0);

    for (int tb = 0; tb < SEQ / KB; tb++) {
        CP_WAIT0;
        __syncthreads();
        if (tb + 1 < SEQ / KB) issue_kv(tb + 1);
        uint32_t st = sb + (uint32_t)(tb & 1) * ASTAGE;

        // ---- S = Qh Kh^T (log2-scaled; scale folded into Q) ----
        float S[8][4];
        #pragma unroll
        for (int nj = 0; nj < 8; nj++)
            #pragma unroll
            for (int r = 0; r < 4; r++) S[nj][r] = 0.f;

        #pragma unroll
        for (int k = 0; k < 4; k++) {
            #pragma unroll
            for (int njp = 0; njp < 4; njp++) {
                uint32_t bd = st + (njp * 16 + kp_row) * ATLDB + k * 32 + kp_kb;
                uint32_t kh0, kh1, kh2, kh3;
                LDSM_X4(kh0, kh1, kh2, kh3, bd);
                MMA16816(S[njp * 2],     Qh[k][0], Qh[k][1], Qh[k][2], Qh[k][3], kh0, kh1);
                MMA16816(S[njp * 2 + 1], Qh[k][0], Qh[k][1], Qh[k][2], Qh[k][3], kh2, kh3);
            }
        }

        // ---- online softmax in exp2 domain (MUFU exp), voted rescale skip ----
        float bm0 = S[0][0], bm1 = S[0][2];
        #pragma unroll
        for (int nj = 0; nj < 8; nj++) {
            bm0 = fmaxf(bm0, fmaxf(S[nj][0], S[nj][1]));
            bm1 = fmaxf(bm1, fmaxf(S[nj][2], S[nj][3]));
        }
        bm0 = fmaxf(bm0, __shfl_xor_sync(0xffffffffu, bm0, 1));
        bm0 = fmaxf(bm0, __shfl_xor_sync(0xffffffffu, bm0, 2));
        bm1 = fmaxf(bm1, __shfl_xor_sync(0xffffffffu, bm1, 1));
        bm1 = fmaxf(bm1, __shfl_xor_sync(0xffffffffu, bm1, 2));
        bool grew = (bm0 > m0) | (bm1 > m1);
        if (__any_sync(0xffffffffu, grew)) {
            float nm0 = fmaxf(m0, bm0), nm1 = fmaxf(m1, bm1);
            float c0 = ex2(m0 - nm0), c1 = ex2(m1 - nm1);
            m0 = nm0; m1 = nm1;
            l0 *= c0; l1 *= c1;
            #pragma unroll
            for (int nj = 0; nj < 8; nj++) {
                O[nj][0] *= c0; O[nj][1] *= c0;
                O[nj][2] *= c1; O[nj][3] *= c1;
            }
        }

        float rs0 = 0.f, rs1 = 0.f;
        #pragma unroll
        for (int nj = 0; nj < 8; nj++) {
            S[nj][0] = ex2(S[nj][0] - m0);
            S[nj][1] = ex2(S[nj][1] - m0);
            S[nj][2] = ex2(S[nj][2] - m1);
            S[nj][3] = ex2(S[nj][3] - m1);
            rs0 += S[nj][0] + S[nj][1];
            rs1 += S[nj][2] + S[nj][3];
        }
        rs0 += __shfl_xor_sync(0xffffffffu, rs0, 1);
        rs0 += __shfl_xor_sync(0xffffffffu, rs0, 2);
        rs1 += __shfl_xor_sync(0xffffffffu, rs1, 1);
        rs1 += __shfl_xor_sync(0xffffffffu, rs1, 2);
        l0 += rs0;
        l1 += rs1;

        // ---- P (C-layout) -> fp16 A-frags, hi only ----
        uint32_t Ph[4][4];
        #pragma unroll
        for (int t = 0; t < 4; t++) {
            Ph[t][0] = pack2_f16(S[2 * t][0],     S[2 * t][1]);
            Ph[t][1] = pack2_f16(S[2 * t][2],     S[2 * t][3]);
            Ph[t][2] = pack2_f16(S[2 * t + 1][0], S[2 * t + 1][1]);
            Ph[t][3] = pack2_f16(S[2 * t + 1][2], S[2 * t + 1][3]);
        }

        // ---- O += Ph (Vh + Vl) via x4 trans ldmatrix ----
        #pragma unroll
        for (int t = 0; t < 4; t++) {
            #pragma unroll
            for (int njp = 0; njp < 4; njp++) {
                uint32_t vaddr = st + 1 * ATILE + (t * 16 + (lane & 15)) * ATLDB
                                 + njp * 32 + ((lane >> 4) << 4);
                uint32_t vh0, vh1, vh2, vh3, vl0, vl1, vl2, vl3;
                LDSM_X4_T(vh0, vh1, vh2, vh3, vaddr);
                LDSM_X4_T(vl0, vl1, vl2, vl3, vaddr + ATILE);
                MMA16816(O[njp * 2],     Ph[t][0], Ph[t][1], Ph[t][2], Ph[t][3], vh0, vh1);
                MMA16816(O[njp * 2 + 1], Ph[t][0], Ph[t][1], Ph[t][2], Ph[t][3], vh2, vh3);
                MMA16816(O[njp * 2],     Ph[t][0], Ph[t][1], Ph[t][2], Ph[t][3], vl0, vl1);
                MMA16816(O[njp * 2 + 1], Ph[t][0], Ph[t][1], Ph[t][2], Ph[t][3], vl2, vl3);
            }
        }
        // next iteration's sync orders stage reuse
    }

    // ---- epilogue: normalize, write fp16 hi (feeds proj GEMM A-side) ----
    float inv0 = 1.0f / l0, inv1 = 1.0f / l1;
    int row0 = qb * 128 + wm + (lane >> 2);
    int row1 = row0 + 8;
    size_t o0 = ((size_t)bb * SEQ + row0) * DIM + h * HDIM;
    size_t o1 = ((size_t)bb * SEQ + row1) * DIM + h * HDIM;
    #pragma unroll
    for (int nj = 0; nj < 8; nj++) {
        int col = nj * 8 + (lane & 3) * 2;
        *(uint32_t*)&g_ath[o0 + col] = pack2_f16(O[nj][0] * inv0, O[nj][1] * inv0);
        *(uint32_t*)&g_ath[o1 + col] = pack2_f16(O[nj][2] * inv1, O[nj][3] * inv1);
    }
}

// ---------------------------------------------------------------------------
extern "C" void kernel_launch(void* const* d_in, const int* in_sizes, int n_in,
                              void* d_out, int out_size)
{
    const float* x      = (const float*)d_in[0];
    const float* w_qkv  = (const float*)d_in[1];
    const float* b_qkv  = (const float*)d_in[2];
    const float* w_proj = (const float*)d_in[3];
    const float* b_proj = (const float*)d_in[4];
    float* out = (float*)d_out;

    cudaFuncSetAttribute(gemm_qkv_mma,  cudaFuncAttributeMaxDynamicSharedMemorySize, GEMM_SMEM_QKV);
    cudaFuncSetAttribute(gemm_proj_mma, cudaFuncAttributeMaxDynamicSharedMemorySize, GEMM_SMEM_PROJ);
    cudaFuncSetAttribute(attn_mma,      cudaFuncAttributeMaxDynamicSharedMemorySize, ATT_SMEM);

    conv_split_all<<<(NCONV_TOTAL + 255) / 256, 256>>>(x, w_qkv, w_proj);
    gemm_qkv_mma<<<dim3(QKV_N / 128, MROWS / 128), 256, GEMM_SMEM_QKV>>>(b_qkv);
    attn_mma<<<dim3(BATCH * NHEAD, SEQ / 128), 256, ATT_SMEM>>>();
    gemm_proj_mma<<<dim3(DIM / 128, MROWS / 64), 256, GEMM_SMEM_PROJ>>>(b_proj, out);
}

// round 15
// speedup vs baseline: 4.9031x; 1.0352x over previous
#include <cuda_runtime.h>
#include <cuda_fp16.h>
#include <cstdint>

// Problem constants
#define BATCH 8
#define SEQ 1024
#define DIM 768
#define NHEAD 12
#define HDIM 64
#define MROWS (BATCH * SEQ)          // 8192
#define QKV_N (3 * DIM)              // 2304
#define QKV_ELEMS (BATCH * NHEAD * SEQ * HDIM)

// log2(e)/8 folded into Q so softmax runs in exp2 domain
#define QSCALE (0.125f * 1.44269504088896f)

// Scratch (allocation-free rule: __device__ globals). fp16 mixed-precision:
// A-side + K keep HI only; GEMM B-side weights and V keep HI+LO.
__device__ __half g_xh[MROWS * DIM];
__device__ __half g_wqh[QKV_N * DIM], g_wql[QKV_N * DIM];
__device__ __half g_wph[DIM * DIM],   g_wpl[DIM * DIM];
__device__ __half g_qh[QKV_ELEMS];                        // [b,h,n,d], pre-scaled
__device__ __half g_kh[QKV_ELEMS];                        // hi only
__device__ __half g_vh[QKV_ELEMS], g_vl[QKV_ELEMS];
__device__ __half g_ath[MROWS * DIM];                     // attn out [b,n,h*d]

// ---------------------------------------------------------------------------
// PTX helpers (baseline PTX only — tcgen05 rejected by this toolchain's sm_103)
// ---------------------------------------------------------------------------
__device__ __forceinline__ uint32_t smem_to_u32(const void* p) {
    uint32_t a;
    asm("{ .reg .u64 t; cvta.to.shared.u64 t, %1; cvt.u32.u64 %0, t; }"
        : "=r"(a) : "l"(p));
    return a;
}

#define LDSM_X4(r0, r1, r2, r3, addr) \
    asm volatile("ldmatrix.sync.aligned.m8n8.x4.shared.b16 {%0,%1,%2,%3}, [%4];" \
        : "=r"(r0), "=r"(r1), "=r"(r2), "=r"(r3) : "r"(addr))
#define LDSM_X4_T(r0, r1, r2, r3, addr) \
    asm volatile("ldmatrix.sync.aligned.m8n8.x4.trans.shared.b16 {%0,%1,%2,%3}, [%4];" \
        : "=r"(r0), "=r"(r1), "=r"(r2), "=r"(r3) : "r"(addr))

// fp16 MMA, fp32 accumulate
#define MMA16816(d, a0, a1, a2, a3, b0, b1) \
    asm volatile("mma.sync.aligned.m16n8k16.row.col.f32.f16.f16.f32 " \
        "{%0,%1,%2,%3}, {%4,%5,%6,%7}, {%8,%9}, {%0,%1,%2,%3};" \
        : "+f"((d)[0]), "+f"((d)[1]), "+f"((d)[2]), "+f"((d)[3]) \
        : "r"(a0), "r"(a1), "r"(a2), "r"(a3), "r"(b0), "r"(b1))

#define CP16(dst, src) \
    asm volatile("cp.async.cg.shared.global [%0], [%1], 16;" \
        :: "r"(dst), "l"(src))
#define CP_COMMIT asm volatile("cp.async.commit_group;")
#define CP_WAIT1  asm volatile("cp.async.wait_group 1;")
#define CP_WAIT0  asm volatile("cp.async.wait_group 0;")

// MUFU exp2 (single EX2 instruction; scores already in log2 domain)
__device__ __forceinline__ float ex2(float x) {
    float r;
    asm("ex2.approx.ftz.f32 %0, %1;" : "=f"(r) : "f"(x));
    return r;
}

// fp16 pack helpers
__device__ __forceinline__ uint32_t pack2_f16(float a, float b) {
    __half2 h = __floats2half2_rn(a, b);
    return *reinterpret_cast<uint32_t*>(&h);
}
__device__ __forceinline__ void split2_f16(float a, float b,
                                           uint32_t& hi, uint32_t& lo) {
    __half2 h = __floats2half2_rn(a, b);
    float2 f = __half22float2(h);
    __half2 l = __floats2half2_rn(a - f.x, b - f.y);
    hi = *reinterpret_cast<uint32_t*>(&h);
    lo = *reinterpret_cast<uint32_t*>(&l);
}
__device__ __forceinline__ uint2 pack4_hi(float4 v) {
    return make_uint2(pack2_f16(v.x, v.y), pack2_f16(v.z, v.w));
}
__device__ __forceinline__ void split4_f16(float4 v, uint2& hi, uint2& lo) {
    uint32_t h0, l0, h1, l1;
    split2_f16(v.x, v.y, h0, l0);
    split2_f16(v.z, v.w, h1, l1);
    hi = make_uint2(h0, h1);
    lo = make_uint2(l0, l1);
}

// ---------------------------------------------------------------------------
// Merged pre-split kernel: x (hi only), w_qkv (hi+lo), w_proj (hi+lo).
// Output globals referenced in device code only (host-shadow bug, R5/R6).
// ---------------------------------------------------------------------------
#define NX4  (MROWS * DIM / 4)
#define NWQ4 (QKV_N * DIM / 4)
#define NWP4 (DIM * DIM / 4)
#define NCONV_TOTAL (NX4 + NWQ4 + NWP4)

__global__ void conv_split_all(const float* __restrict__ x,
                               const float* __restrict__ wq,
                               const float* __restrict__ wp)
{
    int i = blockIdx.x * blockDim.x + threadIdx.x;
    if (i < NX4) {
        ((uint2*)g_xh)[i] = pack4_hi(((const float4*)x)[i]);
    } else if (i < NX4 + NWQ4) {
        int j = i - NX4;
        uint2 hi, lo;
        split4_f16(((const float4*)wq)[j], hi, lo);
        ((uint2*)g_wqh)[j] = hi;
        ((uint2*)g_wql)[j] = lo;
    } else if (i < NCONV_TOTAL) {
        int j = i - NX4 - NWQ4;
        uint2 hi, lo;
        split4_f16(((const float4*)wp)[j], hi, lo);
        ((uint2*)g_wph)[j] = hi;
        ((uint2*)g_wpl)[j] = lo;
    }
}

// ---------------------------------------------------------------------------
// fp16 2-term GEMM: C = Ah·Bh + Ah·Bl. K=32 chunks, 3 smem stages (A|Bh|Bl),
// cp.async prefetch distance 2, ONE __syncthreads per chunk.
// MI=4 (128x128 CTA tile) for BOTH GEMMs — MI=2 regressed proj (R14: B-panel
// traffic doubles, +67% total tile traffic; wave-tail gain was smaller).
// ---------------------------------------------------------------------------
#define KC2 32
#define NCH2 (DIM / KC2)
#define LDB2 80
#define TB2 (128 * LDB2)               // B tile: 10240 B

template<int MI>
__device__ __forceinline__ void f16_mainloop(
    const __half* __restrict__ Ah,
    const __half* __restrict__ Bh, const __half* __restrict__ Bl,
    int bm, int bn, uint32_t sb, float acc[MI][4][4])
{
    constexpr int TA   = MI * 32 * LDB2;     // A tile bytes (incl. row padding)
    constexpr int STG  = TA + 2 * TB2;       // stage bytes
    constexpr int NCHA = MI * 32 * 4;        // A DATA chunks (rows x 4x16B)

    const int tid  = threadIdx.x;
    const int lane = tid & 31;
    const int wid  = tid >> 5;
    const int wm   = (wid >> 2) * (MI * 16);
    const int wn   = (wid & 3) * 32;

    #pragma unroll
    for (int mi = 0; mi < MI; mi++)
        #pragma unroll
        for (int nj = 0; nj < 4; nj++)
            #pragma unroll
            for (int r = 0; r < 4; r++) acc[mi][nj][r] = 0.f;

    const uint32_t a_row  = (lane & 7) + ((lane >> 3) & 1) * 8;
    const uint32_t a_kb   = ((lane >> 4) & 1) * 16;
    const uint32_t kp_row = ((lane >> 4) << 3) + (lane & 7);
    const uint32_t kp_kb  = ((lane >> 3) & 1) << 4;

    auto issue = [&](int c) {
        int ko = c * KC2;
        uint32_t st = sb + (uint32_t)(c % 3) * STG;
        #pragma unroll
        for (int i = 0; i < NCHA / 256; i++) {
            int idx = tid + i * 256;
            int row = idx >> 2, col = idx & 3;
            CP16(st + row * LDB2 + col * 16,
                 Ah + (size_t)(bm + row) * DIM + ko + col * 8);
        }
        #pragma unroll
        for (int i = 0; i < 2; i++) {
            int idx = tid + i * 256;
            int row = idx >> 2, col = idx & 3;
            uint32_t doff = row * LDB2 + col * 16;
            size_t boff = (size_t)(bn + row) * DIM + ko + col * 8;
            CP16(st + TA + doff,       Bh + boff);
            CP16(st + TA + TB2 + doff, Bl + boff);
        }
        CP_COMMIT;
    };

    issue(0);
    issue(1);

    for (int c = 0; c < NCH2; c++) {
        if (c == NCH2 - 1) { CP_WAIT0; } else { CP_WAIT1; }
        __syncthreads();
        if (c + 2 < NCH2) issue(c + 2);
        uint32_t st = sb + (uint32_t)(c % 3) * STG;
        #pragma unroll
        for (int k16 = 0; k16 < 2; k16++) {
            const uint32_t kb = k16 * 32;
            uint32_t bh[2][4], bl[2][4];
            #pragma unroll
            for (int njp = 0; njp < 2; njp++) {
                uint32_t bd = st + TA + (wn + njp * 16 + kp_row) * LDB2 + kb + kp_kb;
                LDSM_X4(bh[njp][0], bh[njp][1], bh[njp][2], bh[njp][3], bd);
                LDSM_X4(bl[njp][0], bl[njp][1], bl[njp][2], bl[njp][3], bd + TB2);
            }
            #pragma unroll
            for (int mi = 0; mi < MI; mi++) {
                uint32_t ad = st + (wm + mi * 16 + a_row) * LDB2 + kb + a_kb;
                uint32_t a0, a1, a2, a3;
                LDSM_X4(a0, a1, a2, a3, ad);
                #pragma unroll
                for (int njp = 0; njp < 2; njp++) {
                    MMA16816(acc[mi][njp * 2],     a0, a1, a2, a3, bh[njp][0], bh[njp][1]);
                    MMA16816(acc[mi][njp * 2 + 1], a0, a1, a2, a3, bh[njp][2], bh[njp][3]);
                    MMA16816(acc[mi][njp * 2],     a0, a1, a2, a3, bl[njp][0], bl[njp][1]);
                    MMA16816(acc[mi][njp * 2 + 1], a0, a1, a2, a3, bl[njp][2], bl[njp][3]);
                }
            }
        }
    }
}

#define GEMM_SMEM_QKV (3 * (128 * LDB2 + 2 * TB2))   // 92160 B (MI=4)

// GEMM 1: qkv = x @ w_qkv^T + b_qkv. Q: scaled hi. K: hi. V: hi+lo.
__global__ __launch_bounds__(256, 2)
void gemm_qkv_mma(const float* __restrict__ bias)
{
    extern __shared__ __align__(128) char smem[];
    const int bm = blockIdx.y * 128, bn = blockIdx.x * 128;
    float acc[4][4][4];
    f16_mainloop<4>(g_xh, g_wqh, g_wql, bm, bn, smem_to_u32(smem), acc);

    const int lane = threadIdx.x & 31;
    const int wid  = threadIdx.x >> 5;
    const int wm   = (wid >> 2) * 64;
    const int wn   = (wid & 3) * 32;
    const int s = blockIdx.x / 6;                 // 0=q, 1=k, 2=v
    __half* hb = (s == 0) ? g_qh : (s == 1) ? g_kh : g_vh;

    #pragma unroll
    for (int mi = 0; mi < 4; mi++) {
        int m0 = bm + wm + mi * 16 + (lane >> 2);
        #pragma unroll
        for (int nj = 0; nj < 4; nj++) {
            int o  = bn + wn + nj * 8 + (lane & 3) * 2;
            int rl = o - s * DIM;
            int h = rl >> 6, d = rl & 63;
            float b0 = bias[o], b1 = bias[o + 1];
            #pragma unroll
            for (int rr = 0; rr < 2; rr++) {
                int m  = m0 + rr * 8;
                int bb = m >> 10, nn = m & 1023;
                float v0 = acc[mi][nj][rr * 2 + 0] + b0;
                float v1 = acc[mi][nj][rr * 2 + 1] + b1;
                size_t idx = ((size_t)(bb * NHEAD + h) * SEQ + nn) * HDIM + d;
                if (s == 0) {
                    *(uint32_t*)&hb[idx] = pack2_f16(v0 * QSCALE, v1 * QSCALE);
                } else if (s == 1) {
                    *(uint32_t*)&hb[idx] = pack2_f16(v0, v1);
                } else {
                    uint32_t hi, lo;
                    split2_f16(v0, v1, hi, lo);
                    *(uint32_t*)&hb[idx] = hi;
                    *(uint32_t*)&g_vl[idx] = lo;
                }
            }
        }
    }
}

// GEMM 2: out = att @ w_proj^T + b_proj. MI=4 (reverted from MI=2, R14).
__global__ __launch_bounds__(256, 2)
void gemm_proj_mma(const float* __restrict__ bias, float* __restrict__ out)
{
    extern __shared__ __align__(128) char smem[];
    const int bm = blockIdx.y * 128, bn = blockIdx.x * 128;
    float acc[4][4][4];
    f16_mainloop<4>(g_ath, g_wph, g_wpl, bm, bn, smem_to_u32(smem), acc);

    const int lane = threadIdx.x & 31;
    const int wid  = threadIdx.x >> 5;
    const int wm   = (wid >> 2) * 64;
    const int wn   = (wid & 3) * 32;

    #pragma unroll
    for (int mi = 0; mi < 4; mi++) {
        int m0 = bm + wm + mi * 16 + (lane >> 2);
        #pragma unroll
        for (int nj = 0; nj < 4; nj++) {
            int o = bn + wn + nj * 8 + (lane & 3) * 2;
            float b0 = bias[o], b1 = bias[o + 1];
            #pragma unroll
            for (int rr = 0; rr < 2; rr++) {
                int m = m0 + rr * 8;
                float2 v = make_float2(acc[mi][nj][rr * 2 + 0] + b0,
                                       acc[mi][nj][rr * 2 + 1] + b1);
                *(float2*)&out[(size_t)m * DIM + o] = v;
            }
        }
    }
}

// ---------------------------------------------------------------------------
// Flash attention: S = Qh·Kh, O += Ph·(Vh+Vl). exp2 via MUFU (ex2.approx).
// Stage = Kh|Vh|Vl, double-buffered cp.async, warp-voted rescale skip.
// (R14-validated: ~123 us.)
// ---------------------------------------------------------------------------
#define KB 64
#define ATLDB 144
#define ATILE (KB * ATLDB)             // 9216 per tile
#define ASTAGE (3 * ATILE)             // 27648 per stage (Kh|Vh|Vl)
#define ATT_SMEM (2 * ASTAGE)          // 55296 dynamic

__global__ __launch_bounds__(256, 2)
void attn_mma()
{
    extern __shared__ __align__(128) char smem[];
    const uint32_t sb = smem_to_u32(smem);
    const int tid  = threadIdx.x;
    const int lane = tid & 31;
    const int wid  = tid >> 5;
    const int wm   = wid * 16;
    const int bh   = blockIdx.x;
    const int bb   = bh / NHEAD;
    const int h    = bh - bb * NHEAD;
    const int qb   = blockIdx.y;

    const size_t headoff = (size_t)bh * SEQ * HDIM;
    const size_t qoff    = headoff + (size_t)qb * 128 * HDIM;

    // ---- Stage Q hi (128x64 fp16) ----
    {
        const uint4* qh4 = (const uint4*)(g_qh + qoff);
        #pragma unroll
        for (int i = 0; i < 4; i++) {
            int idx = tid + i * 256;
            int row = idx >> 3, c = idx & 7;
            *(uint4*)(smem + row * ATLDB + c * 16) = qh4[idx];
        }
    }
    __syncthreads();

    const uint32_t a_row  = (lane & 7) + ((lane >> 3) & 1) * 8;
    const uint32_t a_kb   = ((lane >> 4) & 1) * 16;
    const uint32_t kp_row = ((lane >> 4) << 3) + (lane & 7);
    const uint32_t kp_kb  = ((lane >> 3) & 1) << 4;

    uint32_t Qh[4][4];
    #pragma unroll
    for (int k = 0; k < 4; k++) {
        uint32_t ad = sb + (wm + a_row) * ATLDB + k * 32 + a_kb;
        LDSM_X4(Qh[k][0], Qh[k][1], Qh[k][2], Qh[k][3], ad);
    }
    __syncthreads();          // Q region about to be reused as K/V stage

    float O[8][4];
    #pragma unroll
    for (int nj = 0; nj < 8; nj++)
        #pragma unroll
        for (int r = 0; r < 4; r++) O[nj][r] = 0.f;
    float m0 = -1e30f, m1 = -1e30f, l0 = 0.f, l1 = 0.f;

    auto issue_kv = [&](int t) {
        uint32_t st = sb + (uint32_t)(t & 1) * ASTAGE;
        size_t base = headoff + (size_t)t * KB * HDIM;
        #pragma unroll
        for (int i = 0; i < 2; i++) {
            int idx = tid + i * 256;
            int row = idx >> 3, col = idx & 7;
            uint32_t doff = row * ATLDB + col * 16;
            size_t goff = base + row * HDIM + col * 8;
            CP16(st + 0 * ATILE + doff, g_kh + goff);
            CP16(st + 1 * ATILE + doff, g_vh + goff);
            CP16(st + 2 * ATILE + doff, g_vl + goff);
        }
        CP_COMMIT;
    };

    issue_kv(0);

    for (int tb = 0; tb < SEQ / KB; tb++) {
        CP_WAIT0;
        __syncthreads();
        if (tb + 1 < SEQ / KB) issue_kv(tb + 1);
        uint32_t st = sb + (uint32_t)(tb & 1) * ASTAGE;

        // ---- S = Qh Kh^T (log2-scaled; scale folded into Q) ----
        float S[8][4];
        #pragma unroll
        for (int nj = 0; nj < 8; nj++)
            #pragma unroll
            for (int r = 0; r < 4; r++) S[nj][r] = 0.f;

        #pragma unroll
        for (int k = 0; k < 4; k++) {
            #pragma unroll
            for (int njp = 0; njp < 4; njp++) {
                uint32_t bd = st + (njp * 16 + kp_row) * ATLDB + k * 32 + kp_kb;
                uint32_t kh0, kh1, kh2, kh3;
                LDSM_X4(kh0, kh1, kh2, kh3, bd);
                MMA16816(S[njp * 2],     Qh[k][0], Qh[k][1], Qh[k][2], Qh[k][3], kh0, kh1);
                MMA16816(S[njp * 2 + 1], Qh[k][0], Qh[k][1], Qh[k][2], Qh[k][3], kh2, kh3);
            }
        }

        // ---- online softmax in exp2 domain (MUFU exp), voted rescale skip ----
        float bm0 = S[0][0], bm1 = S[0][2];
        #pragma unroll
        for (int nj = 0; nj < 8; nj++) {
            bm0 = fmaxf(bm0, fmaxf(S[nj][0], S[nj][1]));
            bm1 = fmaxf(bm1, fmaxf(S[nj][2], S[nj][3]));
        }
        bm0 = fmaxf(bm0, __shfl_xor_sync(0xffffffffu, bm0, 1));
        bm0 = fmaxf(bm0, __shfl_xor_sync(0xffffffffu, bm0, 2));
        bm1 = fmaxf(bm1, __shfl_xor_sync(0xffffffffu, bm1, 1));
        bm1 = fmaxf(bm1, __shfl_xor_sync(0xffffffffu, bm1, 2));
        bool grew = (bm0 > m0) | (bm1 > m1);
        if (__any_sync(0xffffffffu, grew)) {
            float nm0 = fmaxf(m0, bm0), nm1 = fmaxf(m1, bm1);
            float c0 = ex2(m0 - nm0), c1 = ex2(m1 - nm1);
            m0 = nm0; m1 = nm1;
            l0 *= c0; l1 *= c1;
            #pragma unroll
            for (int nj = 0; nj < 8; nj++) {
                O[nj][0] *= c0; O[nj][1] *= c0;
                O[nj][2] *= c1; O[nj][3] *= c1;
            }
        }

        float rs0 = 0.f, rs1 = 0.f;
        #pragma unroll
        for (int nj = 0; nj < 8; nj++) {
            S[nj][0] = ex2(S[nj][0] - m0);
            S[nj][1] = ex2(S[nj][1] - m0);
            S[nj][2] = ex2(S[nj][2] - m1);
            S[nj][3] = ex2(S[nj][3] - m1);
            rs0 += S[nj][0] + S[nj][1];
            rs1 += S[nj][2] + S[nj][3];
        }
        rs0 += __shfl_xor_sync(0xffffffffu, rs0, 1);
        rs0 += __shfl_xor_sync(0xffffffffu, rs0, 2);
        rs1 += __shfl_xor_sync(0xffffffffu, rs1, 1);
        rs1 += __shfl_xor_sync(0xffffffffu, rs1, 2);
        l0 += rs0;
        l1 += rs1;

        // ---- P (C-layout) -> fp16 A-frags, hi only ----
        uint32_t Ph[4][4];
        #pragma unroll
        for (int t = 0; t < 4; t++) {
            Ph[t][0] = pack2_f16(S[2 * t][0],     S[2 * t][1]);
            Ph[t][1] = pack2_f16(S[2 * t][2],     S[2 * t][3]);
            Ph[t][2] = pack2_f16(S[2 * t + 1][0], S[2 * t + 1][1]);
            Ph[t][3] = pack2_f16(S[2 * t + 1][2], S[2 * t + 1][3]);
        }

        // ---- O += Ph (Vh + Vl) via x4 trans ldmatrix ----
        #pragma unroll
        for (int t = 0; t < 4; t++) {
            #pragma unroll
            for (int njp = 0; njp < 4; njp++) {
                uint32_t vaddr = st + 1 * ATILE + (t * 16 + (lane & 15)) * ATLDB
                                 + njp * 32 + ((lane >> 4) << 4);
                uint32_t vh0, vh1, vh2, vh3, vl0, vl1, vl2, vl3;
                LDSM_X4_T(vh0, vh1, vh2, vh3, vaddr);
                LDSM_X4_T(vl0, vl1, vl2, vl3, vaddr + ATILE);
                MMA16816(O[njp * 2],     Ph[t][0], Ph[t][1], Ph[t][2], Ph[t][3], vh0, vh1);
                MMA16816(O[njp * 2 + 1], Ph[t][0], Ph[t][1], Ph[t][2], Ph[t][3], vh2, vh3);
                MMA16816(O[njp * 2],     Ph[t][0], Ph[t][1], Ph[t][2], Ph[t][3], vl0, vl1);
                MMA16816(O[njp * 2 + 1], Ph[t][0], Ph[t][1], Ph[t][2], Ph[t][3], vl2, vl3);
            }
        }
        // next iteration's sync orders stage reuse
    }

    // ---- epilogue: normalize, write fp16 hi (feeds proj GEMM A-side) ----
    float inv0 = 1.0f / l0, inv1 = 1.0f / l1;
    int row0 = qb * 128 + wm + (lane >> 2);
    int row1 = row0 + 8;
    size_t o0 = ((size_t)bb * SEQ + row0) * DIM + h * HDIM;
    size_t o1 = ((size_t)bb * SEQ + row1) * DIM + h * HDIM;
    #pragma unroll
    for (int nj = 0; nj < 8; nj++) {
        int col = nj * 8 + (lane & 3) * 2;
        *(uint32_t*)&g_ath[o0 + col] = pack2_f16(O[nj][0] * inv0, O[nj][1] * inv0);
        *(uint32_t*)&g_ath[o1 + col] = pack2_f16(O[nj][2] * inv1, O[nj][3] * inv1);
    }
}

// ---------------------------------------------------------------------------
extern "C" void kernel_launch(void* const* d_in, const int* in_sizes, int n_in,
                              void* d_out, int out_size)
{
    const float* x      = (const float*)d_in[0];
    const float* w_qkv  = (const float*)d_in[1];
    const float* b_qkv  = (const float*)d_in[2];
    const float* w_proj = (const float*)d_in[3];
    const float* b_proj = (const float*)d_in[4];
    float* out = (float*)d_out;

    cudaFuncSetAttribute(gemm_qkv_mma,  cudaFuncAttributeMaxDynamicSharedMemorySize, GEMM_SMEM_QKV);
    cudaFuncSetAttribute(gemm_proj_mma, cudaFuncAttributeMaxDynamicSharedMemorySize, GEMM_SMEM_QKV);
    cudaFuncSetAttribute(attn_mma,      cudaFuncAttributeMaxDynamicSharedMemorySize, ATT_SMEM);

    conv_split_all<<<(NCONV_TOTAL + 255) / 256, 256>>>(x, w_qkv, w_proj);
    gemm_qkv_mma<<<dim3(QKV_N / 128, MROWS / 128), 256, GEMM_SMEM_QKV>>>(b_qkv);
    attn_mma<<<dim3(BATCH * NHEAD, SEQ / 128), 256, ATT_SMEM>>>();
    gemm_proj_mma<<<dim3(DIM / 128, MROWS / 128), 256, GEMM_SMEM_QKV>>>(b_proj, out);
}

// round 16
// speedup vs baseline: 4.9338x; 1.0063x over previous
#include <cuda_runtime.h>
#include <cuda_fp16.h>
#include <cstdint>

// Problem constants
#define BATCH 8
#define SEQ 1024
#define DIM 768
#define NHEAD 12
#define HDIM 64
#define MROWS (BATCH * SEQ)          // 8192
#define QKV_N (3 * DIM)              // 2304
#define QKV_ELEMS (BATCH * NHEAD * SEQ * HDIM)

// log2(e)/8 folded into Q so softmax runs in exp2 domain
#define QSCALE (0.125f * 1.44269504088896f)

// Scratch (allocation-free rule: __device__ globals). fp16 mixed-precision:
// A-side + K keep HI only; GEMM B-side weights and V keep HI+LO.
__device__ __half g_xh[MROWS * DIM];
__device__ __half g_wqh[QKV_N * DIM], g_wql[QKV_N * DIM];
__device__ __half g_wph[DIM * DIM],   g_wpl[DIM * DIM];
__device__ __half g_qh[QKV_ELEMS];                        // [b,h,n,d], pre-scaled
__device__ __half g_kh[QKV_ELEMS];                        // hi only
__device__ __half g_vh[QKV_ELEMS], g_vl[QKV_ELEMS];
__device__ __half g_ath[MROWS * DIM];                     // attn out [b,n,h*d]

// ---------------------------------------------------------------------------
// PTX helpers (baseline PTX only — tcgen05 rejected by this toolchain's sm_103)
// ---------------------------------------------------------------------------
__device__ __forceinline__ uint32_t smem_to_u32(const void* p) {
    uint32_t a;
    asm("{ .reg .u64 t; cvta.to.shared.u64 t, %1; cvt.u32.u64 %0, t; }"
        : "=r"(a) : "l"(p));
    return a;
}

#define LDSM_X4(r0, r1, r2, r3, addr) \
    asm volatile("ldmatrix.sync.aligned.m8n8.x4.shared.b16 {%0,%1,%2,%3}, [%4];" \
        : "=r"(r0), "=r"(r1), "=r"(r2), "=r"(r3) : "r"(addr))
#define LDSM_X4_T(r0, r1, r2, r3, addr) \
    asm volatile("ldmatrix.sync.aligned.m8n8.x4.trans.shared.b16 {%0,%1,%2,%3}, [%4];" \
        : "=r"(r0), "=r"(r1), "=r"(r2), "=r"(r3) : "r"(addr))

// fp16 MMA, fp32 accumulate
#define MMA16816(d, a0, a1, a2, a3, b0, b1) \
    asm volatile("mma.sync.aligned.m16n8k16.row.col.f32.f16.f16.f32 " \
        "{%0,%1,%2,%3}, {%4,%5,%6,%7}, {%8,%9}, {%0,%1,%2,%3};" \
        : "+f"((d)[0]), "+f"((d)[1]), "+f"((d)[2]), "+f"((d)[3]) \
        : "r"(a0), "r"(a1), "r"(a2), "r"(a3), "r"(b0), "r"(b1))

#define CP16(dst, src) \
    asm volatile("cp.async.cg.shared.global [%0], [%1], 16;" \
        :: "r"(dst), "l"(src))
#define CP_COMMIT asm volatile("cp.async.commit_group;")
#define CP_WAIT1  asm volatile("cp.async.wait_group 1;")
#define CP_WAIT0  asm volatile("cp.async.wait_group 0;")

// MUFU exp2 (single EX2 instruction; scores already in log2 domain)
__device__ __forceinline__ float ex2(float x) {
    float r;
    asm("ex2.approx.ftz.f32 %0, %1;" : "=f"(r) : "f"(x));
    return r;
}

// fp16 pack helpers
__device__ __forceinline__ uint32_t pack2_f16(float a, float b) {
    __half2 h = __floats2half2_rn(a, b);
    return *reinterpret_cast<uint32_t*>(&h);
}
__device__ __forceinline__ void split2_f16(float a, float b,
                                           uint32_t& hi, uint32_t& lo) {
    __half2 h = __floats2half2_rn(a, b);
    float2 f = __half22float2(h);
    __half2 l = __floats2half2_rn(a - f.x, b - f.y);
    hi = *reinterpret_cast<uint32_t*>(&h);
    lo = *reinterpret_cast<uint32_t*>(&l);
}
__device__ __forceinline__ uint2 pack4_hi(float4 v) {
    return make_uint2(pack2_f16(v.x, v.y), pack2_f16(v.z, v.w));
}
__device__ __forceinline__ void split4_f16(float4 v, uint2& hi, uint2& lo) {
    uint32_t h0, l0, h1, l1;
    split2_f16(v.x, v.y, h0, l0);
    split2_f16(v.z, v.w, h1, l1);
    hi = make_uint2(h0, h1);
    lo = make_uint2(l0, l1);
}

// ---------------------------------------------------------------------------
// Merged pre-split kernel: x (hi only), w_qkv (hi+lo), w_proj (hi+lo).
// ---------------------------------------------------------------------------
#define NX4  (MROWS * DIM / 4)
#define NWQ4 (QKV_N * DIM / 4)
#define NWP4 (DIM * DIM / 4)
#define NCONV_TOTAL (NX4 + NWQ4 + NWP4)

__global__ void conv_split_all(const float* __restrict__ x,
                               const float* __restrict__ wq,
                               const float* __restrict__ wp)
{
    int i = blockIdx.x * blockDim.x + threadIdx.x;
    if (i < NX4) {
        ((uint2*)g_xh)[i] = pack4_hi(((const float4*)x)[i]);
    } else if (i < NX4 + NWQ4) {
        int j = i - NX4;
        uint2 hi, lo;
        split4_f16(((const float4*)wq)[j], hi, lo);
        ((uint2*)g_wqh)[j] = hi;
        ((uint2*)g_wql)[j] = lo;
    } else if (i < NCONV_TOTAL) {
        int j = i - NX4 - NWQ4;
        uint2 hi, lo;
        split4_f16(((const float4*)wp)[j], hi, lo);
        ((uint2*)g_wph)[j] = hi;
        ((uint2*)g_wpl)[j] = lo;
    }
}

// ---------------------------------------------------------------------------
// fp16 2-term GEMM: C = Ah·Bh + Ah·Bl. K=32 chunks, 3 smem stages (A|Bh|Bl),
// cp.async prefetch distance 2, ONE __syncthreads per chunk. MI=4 both GEMMs.
// R16: A-frag ldmatrix prefetched across mi (volatile asm blocks compiler
// scheduling, so the pipeline is written by hand).
// ---------------------------------------------------------------------------
#define KC2 32
#define NCH2 (DIM / KC2)
#define LDB2 80
#define TB2 (128 * LDB2)               // B tile: 10240 B

template<int MI>
__device__ __forceinline__ void f16_mainloop(
    const __half* __restrict__ Ah,
    const __half* __restrict__ Bh, const __half* __restrict__ Bl,
    int bm, int bn, uint32_t sb, float acc[MI][4][4])
{
    constexpr int TA   = MI * 32 * LDB2;     // A tile bytes (incl. row padding)
    constexpr int STG  = TA + 2 * TB2;       // stage bytes
    constexpr int NCHA = MI * 32 * 4;        // A DATA chunks (rows x 4x16B)

    const int tid  = threadIdx.x;
    const int lane = tid & 31;
    const int wid  = tid >> 5;
    const int wm   = (wid >> 2) * (MI * 16);
    const int wn   = (wid & 3) * 32;

    #pragma unroll
    for (int mi = 0; mi < MI; mi++)
        #pragma unroll
        for (int nj = 0; nj < 4; nj++)
            #pragma unroll
            for (int r = 0; r < 4; r++) acc[mi][nj][r] = 0.f;

    const uint32_t a_row  = (lane & 7) + ((lane >> 3) & 1) * 8;
    const uint32_t a_kb   = ((lane >> 4) & 1) * 16;
    const uint32_t kp_row = ((lane >> 4) << 3) + (lane & 7);
    const uint32_t kp_kb  = ((lane >> 3) & 1) << 4;

    auto issue = [&](int c) {
        int ko = c * KC2;
        uint32_t st = sb + (uint32_t)(c % 3) * STG;
        #pragma unroll
        for (int i = 0; i < NCHA / 256; i++) {
            int idx = tid + i * 256;
            int row = idx >> 2, col = idx & 3;
            CP16(st + row * LDB2 + col * 16,
                 Ah + (size_t)(bm + row) * DIM + ko + col * 8);
        }
        #pragma unroll
        for (int i = 0; i < 2; i++) {
            int idx = tid + i * 256;
            int row = idx >> 2, col = idx & 3;
            uint32_t doff = row * LDB2 + col * 16;
            size_t boff = (size_t)(bn + row) * DIM + ko + col * 8;
            CP16(st + TA + doff,       Bh + boff);
            CP16(st + TA + TB2 + doff, Bl + boff);
        }
        CP_COMMIT;
    };

    issue(0);
    issue(1);

    for (int c = 0; c < NCH2; c++) {
        if (c == NCH2 - 1) { CP_WAIT0; } else { CP_WAIT1; }
        __syncthreads();
        if (c + 2 < NCH2) issue(c + 2);
        uint32_t st = sb + (uint32_t)(c % 3) * STG;
        #pragma unroll
        for (int k16 = 0; k16 < 2; k16++) {
            const uint32_t kb = k16 * 32;
            uint32_t bh[2][4], bl[2][4];
            #pragma unroll
            for (int njp = 0; njp < 2; njp++) {
                uint32_t bd = st + TA + (wn + njp * 16 + kp_row) * LDB2 + kb + kp_kb;
                LDSM_X4(bh[njp][0], bh[njp][1], bh[njp][2], bh[njp][3], bd);
                LDSM_X4(bl[njp][0], bl[njp][1], bl[njp][2], bl[njp][3], bd + TB2);
            }
            // A-frag software pipeline: prefetch mi+1 before MMAs of mi
            uint32_t aP0, aP1, aP2, aP3;
            LDSM_X4(aP0, aP1, aP2, aP3, st + (wm + a_row) * LDB2 + kb + a_kb);
            #pragma unroll
            for (int mi = 0; mi < MI; mi++) {
                uint32_t a0 = aP0, a1 = aP1, a2 = aP2, a3 = aP3;
                if (mi + 1 < MI) {
                    uint32_t ad = st + (wm + (mi + 1) * 16 + a_row) * LDB2 + kb + a_kb;
                    LDSM_X4(aP0, aP1, aP2, aP3, ad);
                }
                #pragma unroll
                for (int njp = 0; njp < 2; njp++) {
                    MMA16816(acc[mi][njp * 2],     a0, a1, a2, a3, bh[njp][0], bh[njp][1]);
                    MMA16816(acc[mi][njp * 2 + 1], a0, a1, a2, a3, bh[njp][2], bh[njp][3]);
                    MMA16816(acc[mi][njp * 2],     a0, a1, a2, a3, bl[njp][0], bl[njp][1]);
                    MMA16816(acc[mi][njp * 2 + 1], a0, a1, a2, a3, bl[njp][2], bl[njp][3]);
                }
            }
        }
    }
}

#define GEMM_SMEM_QKV (3 * (128 * LDB2 + 2 * TB2))   // 92160 B (MI=4)

// GEMM 1: qkv = x @ w_qkv^T + b_qkv. Q: scaled hi. K: hi. V: hi+lo.
__global__ __launch_bounds__(256, 2)
void gemm_qkv_mma(const float* __restrict__ bias)
{
    extern __shared__ __align__(128) char smem[];
    const int bm = blockIdx.y * 128, bn = blockIdx.x * 128;
    float acc[4][4][4];
    f16_mainloop<4>(g_xh, g_wqh, g_wql, bm, bn, smem_to_u32(smem), acc);

    const int lane = threadIdx.x & 31;
    const int wid  = threadIdx.x >> 5;
    const int wm   = (wid >> 2) * 64;
    const int wn   = (wid & 3) * 32;
    const int s = blockIdx.x / 6;                 // 0=q, 1=k, 2=v
    __half* hb = (s == 0) ? g_qh : (s == 1) ? g_kh : g_vh;

    #pragma unroll
    for (int mi = 0; mi < 4; mi++) {
        int m0 = bm + wm + mi * 16 + (lane >> 2);
        #pragma unroll
        for (int nj = 0; nj < 4; nj++) {
            int o  = bn + wn + nj * 8 + (lane & 3) * 2;
            int rl = o - s * DIM;
            int h = rl >> 6, d = rl & 63;
            float b0 = bias[o], b1 = bias[o + 1];
            #pragma unroll
            for (int rr = 0; rr < 2; rr++) {
                int m  = m0 + rr * 8;
                int bb = m >> 10, nn = m & 1023;
                float v0 = acc[mi][nj][rr * 2 + 0] + b0;
                float v1 = acc[mi][nj][rr * 2 + 1] + b1;
                size_t idx = ((size_t)(bb * NHEAD + h) * SEQ + nn) * HDIM + d;
                if (s == 0) {
                    *(uint32_t*)&hb[idx] = pack2_f16(v0 * QSCALE, v1 * QSCALE);
                } else if (s == 1) {
                    *(uint32_t*)&hb[idx] = pack2_f16(v0, v1);
                } else {
                    uint32_t hi, lo;
                    split2_f16(v0, v1, hi, lo);
                    *(uint32_t*)&hb[idx] = hi;
                    *(uint32_t*)&g_vl[idx] = lo;
                }
            }
        }
    }
}

// GEMM 2: out = att @ w_proj^T + b_proj. MI=4.
__global__ __launch_bounds__(256, 2)
void gemm_proj_mma(const float* __restrict__ bias, float* __restrict__ out)
{
    extern __shared__ __align__(128) char smem[];
    const int bm = blockIdx.y * 128, bn = blockIdx.x * 128;
    float acc[4][4][4];
    f16_mainloop<4>(g_ath, g_wph, g_wpl, bm, bn, smem_to_u32(smem), acc);

    const int lane = threadIdx.x & 31;
    const int wid  = threadIdx.x >> 5;
    const int wm   = (wid >> 2) * 64;
    const int wn   = (wid & 3) * 32;

    #pragma unroll
    for (int mi = 0; mi < 4; mi++) {
        int m0 = bm + wm + mi * 16 + (lane >> 2);
        #pragma unroll
        for (int nj = 0; nj < 4; nj++) {
            int o = bn + wn + nj * 8 + (lane & 3) * 2;
            float b0 = bias[o], b1 = bias[o + 1];
            #pragma unroll
            for (int rr = 0; rr < 2; rr++) {
                int m = m0 + rr * 8;
                float2 v = make_float2(acc[mi][nj][rr * 2 + 0] + b0,
                                       acc[mi][nj][rr * 2 + 1] + b1);
                *(float2*)&out[(size_t)m * DIM + o] = v;
            }
        }
    }
}

// ---------------------------------------------------------------------------
// Flash attention: S = Qh·Kh, O += Ph·(Vh+Vl). exp2 via MUFU (ex2.approx).
// Stage = Kh|Vh|Vl, double-buffered cp.async, warp-voted rescale skip.
// R16: K and V ldmatrix software-pipelined (prefetch distance 1).
// ---------------------------------------------------------------------------
#define KB 64
#define ATLDB 144
#define ATILE (KB * ATLDB)             // 9216 per tile
#define ASTAGE (3 * ATILE)             // 27648 per stage (Kh|Vh|Vl)
#define ATT_SMEM (2 * ASTAGE)          // 55296 dynamic

__global__ __launch_bounds__(256, 2)
void attn_mma()
{
    extern __shared__ __align__(128) char smem[];
    const uint32_t sb = smem_to_u32(smem);
    const int tid  = threadIdx.x;
    const int lane = tid & 31;
    const int wid  = tid >> 5;
    const int wm   = wid * 16;
    const int bh   = blockIdx.x;
    const int bb   = bh / NHEAD;
    const int h    = bh - bb * NHEAD;
    const int qb   = blockIdx.y;

    const size_t headoff = (size_t)bh * SEQ * HDIM;
    const size_t qoff    = headoff + (size_t)qb * 128 * HDIM;

    // ---- Stage Q hi (128x64 fp16) ----
    {
        const uint4* qh4 = (const uint4*)(g_qh + qoff);
        #pragma unroll
        for (int i = 0; i < 4; i++) {
            int idx = tid + i * 256;
            int row = idx >> 3, c = idx & 7;
            *(uint4*)(smem + row * ATLDB + c * 16) = qh4[idx];
        }
    }
    __syncthreads();

    const uint32_t a_row  = (lane & 7) + ((lane >> 3) & 1) * 8;
    const uint32_t a_kb   = ((lane >> 4) & 1) * 16;
    const uint32_t kp_row = ((lane >> 4) << 3) + (lane & 7);
    const uint32_t kp_kb  = ((lane >> 3) & 1) << 4;

    uint32_t Qh[4][4];
    #pragma unroll
    for (int k = 0; k < 4; k++) {
        uint32_t ad = sb + (wm + a_row) * ATLDB + k * 32 + a_kb;
        LDSM_X4(Qh[k][0], Qh[k][1], Qh[k][2], Qh[k][3], ad);
    }
    __syncthreads();          // Q region about to be reused as K/V stage

    float O[8][4];
    #pragma unroll
    for (int nj = 0; nj < 8; nj++)
        #pragma unroll
        for (int r = 0; r < 4; r++) O[nj][r] = 0.f;
    float m0 = -1e30f, m1 = -1e30f, l0 = 0.f, l1 = 0.f;

    auto issue_kv = [&](int t) {
        uint32_t st = sb + (uint32_t)(t & 1) * ASTAGE;
        size_t base = headoff + (size_t)t * KB * HDIM;
        #pragma unroll
        for (int i = 0; i < 2; i++) {
            int idx = tid + i * 256;
            int row = idx >> 3, col = idx & 7;
            uint32_t doff = row * ATLDB + col * 16;
            size_t goff = base + row * HDIM + col * 8;
            CP16(st + 0 * ATILE + doff, g_kh + goff);
            CP16(st + 1 * ATILE + doff, g_vh + goff);
            CP16(st + 2 * ATILE + doff, g_vl + goff);
        }
        CP_COMMIT;
    };

    issue_kv(0);

    for (int tb = 0; tb < SEQ / KB; tb++) {
        CP_WAIT0;
        __syncthreads();
        if (tb + 1 < SEQ / KB) issue_kv(tb + 1);
        uint32_t st = sb + (uint32_t)(tb & 1) * ASTAGE;

        // ---- S = Qh Kh^T, K-frag prefetch pipeline (16 flat iterations) ----
        float S[8][4];
        #pragma unroll
        for (int nj = 0; nj < 8; nj++)
            #pragma unroll
            for (int r = 0; r < 4; r++) S[nj][r] = 0.f;

        {
            uint32_t kP0, kP1, kP2, kP3;
            LDSM_X4(kP0, kP1, kP2, kP3, st + kp_row * ATLDB + kp_kb);
            #pragma unroll
            for (int it = 0; it < 16; it++) {
                const int k = it >> 2, njp = it & 3;
                uint32_t c0 = kP0, c1 = kP1, c2 = kP2, c3 = kP3;
                if (it < 15) {
                    const int k2 = (it + 1) >> 2, njp2 = (it + 1) & 3;
                    uint32_t bd = st + (njp2 * 16 + kp_row) * ATLDB + k2 * 32 + kp_kb;
                    LDSM_X4(kP0, kP1, kP2, kP3, bd);
                }
                MMA16816(S[njp * 2],     Qh[k][0], Qh[k][1], Qh[k][2], Qh[k][3], c0, c1);
                MMA16816(S[njp * 2 + 1], Qh[k][0], Qh[k][1], Qh[k][2], Qh[k][3], c2, c3);
            }
        }

        // ---- online softmax in exp2 domain (MUFU exp), voted rescale skip ----
        float bm0 = S[0][0], bm1 = S[0][2];
        #pragma unroll
        for (int nj = 0; nj < 8; nj++) {
            bm0 = fmaxf(bm0, fmaxf(S[nj][0], S[nj][1]));
            bm1 = fmaxf(bm1, fmaxf(S[nj][2], S[nj][3]));
        }
        bm0 = fmaxf(bm0, __shfl_xor_sync(0xffffffffu, bm0, 1));
        bm0 = fmaxf(bm0, __shfl_xor_sync(0xffffffffu, bm0, 2));
        bm1 = fmaxf(bm1, __shfl_xor_sync(0xffffffffu, bm1, 1));
        bm1 = fmaxf(bm1, __shfl_xor_sync(0xffffffffu, bm1, 2));
        bool grew = (bm0 > m0) | (bm1 > m1);
        if (__any_sync(0xffffffffu, grew)) {
            float nm0 = fmaxf(m0, bm0), nm1 = fmaxf(m1, bm1);
            float c0 = ex2(m0 - nm0), c1 = ex2(m1 - nm1);
            m0 = nm0; m1 = nm1;
            l0 *= c0; l1 *= c1;
            #pragma unroll
            for (int nj = 0; nj < 8; nj++) {
                O[nj][0] *= c0; O[nj][1] *= c0;
                O[nj][2] *= c1; O[nj][3] *= c1;
            }
        }

        float rs0 = 0.f, rs1 = 0.f;
        #pragma unroll
        for (int nj = 0; nj < 8; nj++) {
            S[nj][0] = ex2(S[nj][0] - m0);
            S[nj][1] = ex2(S[nj][1] - m0);
            S[nj][2] = ex2(S[nj][2] - m1);
            S[nj][3] = ex2(S[nj][3] - m1);
            rs0 += S[nj][0] + S[nj][1];
            rs1 += S[nj][2] + S[nj][3];
        }
        rs0 += __shfl_xor_sync(0xffffffffu, rs0, 1);
        rs0 += __shfl_xor_sync(0xffffffffu, rs0, 2);
        rs1 += __shfl_xor_sync(0xffffffffu, rs1, 1);
        rs1 += __shfl_xor_sync(0xffffffffu, rs1, 2);
        l0 += rs0;
        l1 += rs1;

        // ---- P (C-layout) -> fp16 A-frags, hi only ----
        uint32_t Ph[4][4];
        #pragma unroll
        for (int t = 0; t < 4; t++) {
            Ph[t][0] = pack2_f16(S[2 * t][0],     S[2 * t][1]);
            Ph[t][1] = pack2_f16(S[2 * t][2],     S[2 * t][3]);
            Ph[t][2] = pack2_f16(S[2 * t + 1][0], S[2 * t + 1][1]);
            Ph[t][3] = pack2_f16(S[2 * t + 1][2], S[2 * t + 1][3]);
        }

        // ---- O += Ph (Vh + Vl), V-frag prefetch pipeline (16 flat iters) ----
        {
            auto vAddr = [&](int it) -> uint32_t {
                const int t = it >> 2, njp = it & 3;
                return st + 1 * ATILE + (t * 16 + (lane & 15)) * ATLDB
                       + njp * 32 + ((lane >> 4) << 4);
            };
            uint32_t vh0, vh1, vh2, vh3, vl0, vl1, vl2, vl3;
            {
                uint32_t va = vAddr(0);
                LDSM_X4_T(vh0, vh1, vh2, vh3, va);
                LDSM_X4_T(vl0, vl1, vl2, vl3, va + ATILE);
            }
            #pragma unroll
            for (int it = 0; it < 16; it++) {
                const int t = it >> 2, njp = it & 3;
                uint32_t h0 = vh0, h1 = vh1, h2 = vh2, h3 = vh3;
                uint32_t q0 = vl0, q1 = vl1, q2 = vl2, q3 = vl3;
                if (it < 15) {
                    uint32_t va = vAddr(it + 1);
                    LDSM_X4_T(vh0, vh1, vh2, vh3, va);
                    LDSM_X4_T(vl0, vl1, vl2, vl3, va + ATILE);
                }
                MMA16816(O[njp * 2],     Ph[t][0], Ph[t][1], Ph[t][2], Ph[t][3], h0, h1);
                MMA16816(O[njp * 2 + 1], Ph[t][0], Ph[t][1], Ph[t][2], Ph[t][3], h2, h3);
                MMA16816(O[njp * 2],     Ph[t][0], Ph[t][1], Ph[t][2], Ph[t][3], q0, q1);
                MMA16816(O[njp * 2 + 1], Ph[t][0], Ph[t][1], Ph[t][2], Ph[t][3], q2, q3);
            }
        }
        // next iteration's sync orders stage reuse
    }

    // ---- epilogue: normalize, write fp16 hi (feeds proj GEMM A-side) ----
    float inv0 = 1.0f / l0, inv1 = 1.0f / l1;
    int row0 = qb * 128 + wm + (lane >> 2);
    int row1 = row0 + 8;
    size_t o0 = ((size_t)bb * SEQ + row0) * DIM + h * HDIM;
    size_t o1 = ((size_t)bb * SEQ + row1) * DIM + h * HDIM;
    #pragma unroll
    for (int nj = 0; nj < 8; nj++) {
        int col = nj * 8 + (lane & 3) * 2;
        *(uint32_t*)&g_ath[o0 + col] = pack2_f16(O[nj][0] * inv0, O[nj][1] * inv0);
        *(uint32_t*)&g_ath[o1 + col] = pack2_f16(O[nj][2] * inv1, O[nj][3] * inv1);
    }
}

// ---------------------------------------------------------------------------
extern "C" void kernel_launch(void* const* d_in, const int* in_sizes, int n_in,
                              void* d_out, int out_size)
{
    const float* x      = (const float*)d_in[0];
    const float* w_qkv  = (const float*)d_in[1];
    const float* b_qkv  = (const float*)d_in[2];
    const float* w_proj = (const float*)d_in[3];
    const float* b_proj = (const float*)d_in[4];
    float* out = (float*)d_out;

    cudaFuncSetAttribute(gemm_qkv_mma,  cudaFuncAttributeMaxDynamicSharedMemorySize, GEMM_SMEM_QKV);
    cudaFuncSetAttribute(gemm_proj_mma, cudaFuncAttributeMaxDynamicSharedMemorySize, GEMM_SMEM_QKV);
    cudaFuncSetAttribute(attn_mma,      cudaFuncAttributeMaxDynamicSharedMemorySize, ATT_SMEM);

    conv_split_all<<<(NCONV_TOTAL + 255) / 256, 256>>>(x, w_qkv, w_proj);
    gemm_qkv_mma<<<dim3(QKV_N / 128, MROWS / 128), 256, GEMM_SMEM_QKV>>>(b_qkv);
    attn_mma<<<dim3(BATCH * NHEAD, SEQ / 128), 256, ATT_SMEM>>>();
    gemm_proj_mma<<<dim3(DIM / 128, MROWS / 128), 256, GEMM_SMEM_QKV>>>(b_proj, out);
}

// round 17
// speedup vs baseline: 6.6090x; 1.3395x over previous
#include <cuda_runtime.h>
#include <cuda_fp16.h>
#include <cstdint>

// Problem constants
#define BATCH 8
#define SEQ 1024
#define DIM 768
#define NHEAD 12
#define HDIM 64
#define MROWS (BATCH * SEQ)          // 8192
#define QKV_N (3 * DIM)              // 2304
#define QKV_ELEMS (BATCH * NHEAD * SEQ * HDIM)

// log2(e)/8 folded into Q so softmax runs in exp2 domain
#define QSCALE (0.125f * 1.44269504088896f)

// Scratch (allocation-free rule: __device__ globals). fp16 everywhere;
// only V keeps a lo residual (refines the attention P·V pass).
__device__ __half g_xh[MROWS * DIM];
__device__ __half g_wqh[QKV_N * DIM];
__device__ __half g_wph[DIM * DIM];
__device__ __half g_qh[QKV_ELEMS];                        // [b,h,n,d], pre-scaled
__device__ __half g_kh[QKV_ELEMS];                        // hi only
__device__ __half g_vh[QKV_ELEMS], g_vl[QKV_ELEMS];
__device__ __half g_ath[MROWS * DIM];                     // attn out [b,n,h*d]

// ---------------------------------------------------------------------------
// PTX helpers (baseline PTX only — tcgen05 rejected by this toolchain's sm_103)
// ---------------------------------------------------------------------------
__device__ __forceinline__ uint32_t smem_to_u32(const void* p) {
    uint32_t a;
    asm("{ .reg .u64 t; cvta.to.shared.u64 t, %1; cvt.u32.u64 %0, t; }"
        : "=r"(a) : "l"(p));
    return a;
}

#define LDSM_X4(r0, r1, r2, r3, addr) \
    asm volatile("ldmatrix.sync.aligned.m8n8.x4.shared.b16 {%0,%1,%2,%3}, [%4];" \
        : "=r"(r0), "=r"(r1), "=r"(r2), "=r"(r3) : "r"(addr))
#define LDSM_X4_T(r0, r1, r2, r3, addr) \
    asm volatile("ldmatrix.sync.aligned.m8n8.x4.trans.shared.b16 {%0,%1,%2,%3}, [%4];" \
        : "=r"(r0), "=r"(r1), "=r"(r2), "=r"(r3) : "r"(addr))

// fp16 MMA, fp32 accumulate
#define MMA16816(d, a0, a1, a2, a3, b0, b1) \
    asm volatile("mma.sync.aligned.m16n8k16.row.col.f32.f16.f16.f32 " \
        "{%0,%1,%2,%3}, {%4,%5,%6,%7}, {%8,%9}, {%0,%1,%2,%3};" \
        : "+f"((d)[0]), "+f"((d)[1]), "+f"((d)[2]), "+f"((d)[3]) \
        : "r"(a0), "r"(a1), "r"(a2), "r"(a3), "r"(b0), "r"(b1))

#define CP16(dst, src) \
    asm volatile("cp.async.cg.shared.global [%0], [%1], 16;" \
        :: "r"(dst), "l"(src))
#define CP_COMMIT asm volatile("cp.async.commit_group;")
#define CP_WAIT1  asm volatile("cp.async.wait_group 1;")
#define CP_WAIT0  asm volatile("cp.async.wait_group 0;")

// MUFU exp2 (single EX2 instruction; scores already in log2 domain)
__device__ __forceinline__ float ex2(float x) {
    float r;
    asm("ex2.approx.ftz.f32 %0, %1;" : "=f"(r) : "f"(x));
    return r;
}

// fp16 pack helpers
__device__ __forceinline__ uint32_t pack2_f16(float a, float b) {
    __half2 h = __floats2half2_rn(a, b);
    return *reinterpret_cast<uint32_t*>(&h);
}
__device__ __forceinline__ void split2_f16(float a, float b,
                                           uint32_t& hi, uint32_t& lo) {
    __half2 h = __floats2half2_rn(a, b);
    float2 f = __half22float2(h);
    __half2 l = __floats2half2_rn(a - f.x, b - f.y);
    hi = *reinterpret_cast<uint32_t*>(&h);
    lo = *reinterpret_cast<uint32_t*>(&l);
}
__device__ __forceinline__ uint2 pack4_hi(float4 v) {
    return make_uint2(pack2_f16(v.x, v.y), pack2_f16(v.z, v.w));
}

// ---------------------------------------------------------------------------
// Pre-convert kernel: x, w_qkv, w_proj -> fp16 hi (no lo needed for 1-term).
// Output globals referenced in device code only (host-shadow bug, R5/R6).
// ---------------------------------------------------------------------------
#define NX4  (MROWS * DIM / 4)
#define NWQ4 (QKV_N * DIM / 4)
#define NWP4 (DIM * DIM / 4)
#define NCONV_TOTAL (NX4 + NWQ4 + NWP4)

__global__ void conv_all(const float* __restrict__ x,
                         const float* __restrict__ wq,
                         const float* __restrict__ wp)
{
    int i = blockIdx.x * blockDim.x + threadIdx.x;
    if (i < NX4) {
        ((uint2*)g_xh)[i] = pack4_hi(((const float4*)x)[i]);
    } else if (i < NX4 + NWQ4) {
        int j = i - NX4;
        ((uint2*)g_wqh)[j] = pack4_hi(((const float4*)wq)[j]);
    } else if (i < NCONV_TOTAL) {
        int j = i - NX4 - NWQ4;
        ((uint2*)g_wph)[j] = pack4_hi(((const float4*)wp)[j]);
    }
}

// ---------------------------------------------------------------------------
// fp16 1-term GEMM: C = Ah·Bh. K=32 chunks, 3 smem stages (A|B), cp.async
// prefetch distance 2, ONE __syncthreads per chunk. MI=4 (128x128) both GEMMs.
// (R17: GEMM lo terms dropped per error budget — MMA count halves.)
// ---------------------------------------------------------------------------
#define KC2 32
#define NCH2 (DIM / KC2)
#define LDB2 80
#define TB2 (128 * LDB2)               // B tile: 10240 B

template<int MI>
__device__ __forceinline__ void f16_mainloop(
    const __half* __restrict__ Ah, const __half* __restrict__ Bh,
    int bm, int bn, uint32_t sb, float acc[MI][4][4])
{
    constexpr int TA   = MI * 32 * LDB2;     // A tile bytes (incl. row padding)
    constexpr int STG  = TA + TB2;           // stage bytes (A|B)
    constexpr int NCHA = MI * 32 * 4;        // A DATA chunks (rows x 4x16B)

    const int tid  = threadIdx.x;
    const int lane = tid & 31;
    const int wid  = tid >> 5;
    const int wm   = (wid >> 2) * (MI * 16);
    const int wn   = (wid & 3) * 32;

    #pragma unroll
    for (int mi = 0; mi < MI; mi++)
        #pragma unroll
        for (int nj = 0; nj < 4; nj++)
            #pragma unroll
            for (int r = 0; r < 4; r++) acc[mi][nj][r] = 0.f;

    const uint32_t a_row  = (lane & 7) + ((lane >> 3) & 1) * 8;
    const uint32_t a_kb   = ((lane >> 4) & 1) * 16;
    const uint32_t kp_row = ((lane >> 4) << 3) + (lane & 7);
    const uint32_t kp_kb  = ((lane >> 3) & 1) << 4;

    auto issue = [&](int c) {
        int ko = c * KC2;
        uint32_t st = sb + (uint32_t)(c % 3) * STG;
        #pragma unroll
        for (int i = 0; i < NCHA / 256; i++) {
            int idx = tid + i * 256;
            int row = idx >> 2, col = idx & 3;
            CP16(st + row * LDB2 + col * 16,
                 Ah + (size_t)(bm + row) * DIM + ko + col * 8);
        }
        #pragma unroll
        for (int i = 0; i < 2; i++) {
            int idx = tid + i * 256;
            int row = idx >> 2, col = idx & 3;
            CP16(st + TA + row * LDB2 + col * 16,
                 Bh + (size_t)(bn + row) * DIM + ko + col * 8);
        }
        CP_COMMIT;
    };

    issue(0);
    issue(1);

    for (int c = 0; c < NCH2; c++) {
        if (c == NCH2 - 1) { CP_WAIT0; } else { CP_WAIT1; }
        __syncthreads();
        if (c + 2 < NCH2) issue(c + 2);
        uint32_t st = sb + (uint32_t)(c % 3) * STG;
        #pragma unroll
        for (int k16 = 0; k16 < 2; k16++) {
            const uint32_t kb = k16 * 32;
            uint32_t bh[2][4];
            #pragma unroll
            for (int njp = 0; njp < 2; njp++) {
                uint32_t bd = st + TA + (wn + njp * 16 + kp_row) * LDB2 + kb + kp_kb;
                LDSM_X4(bh[njp][0], bh[njp][1], bh[njp][2], bh[njp][3], bd);
            }
            // A-frag software pipeline: prefetch mi+1 before MMAs of mi
            uint32_t aP0, aP1, aP2, aP3;
            LDSM_X4(aP0, aP1, aP2, aP3, st + (wm + a_row) * LDB2 + kb + a_kb);
            #pragma unroll
            for (int mi = 0; mi < MI; mi++) {
                uint32_t a0 = aP0, a1 = aP1, a2 = aP2, a3 = aP3;
                if (mi + 1 < MI) {
                    uint32_t ad = st + (wm + (mi + 1) * 16 + a_row) * LDB2 + kb + a_kb;
                    LDSM_X4(aP0, aP1, aP2, aP3, ad);
                }
                #pragma unroll
                for (int njp = 0; njp < 2; njp++) {
                    MMA16816(acc[mi][njp * 2],     a0, a1, a2, a3, bh[njp][0], bh[njp][1]);
                    MMA16816(acc[mi][njp * 2 + 1], a0, a1, a2, a3, bh[njp][2], bh[njp][3]);
                }
            }
        }
    }
}

#define GEMM_SMEM (3 * (128 * LDB2 + TB2))   // 61440 B (MI=4, 1-term)

// GEMM 1: qkv = x @ w_qkv^T + b_qkv. Q: scaled hi. K: hi. V: hi+lo split.
__global__ __launch_bounds__(256, 2)
void gemm_qkv_mma(const float* __restrict__ bias)
{
    extern __shared__ __align__(128) char smem[];
    const int bm = blockIdx.y * 128, bn = blockIdx.x * 128;
    float acc[4][4][4];
    f16_mainloop<4>(g_xh, g_wqh, bm, bn, smem_to_u32(smem), acc);

    const int lane = threadIdx.x & 31;
    const int wid  = threadIdx.x >> 5;
    const int wm   = (wid >> 2) * 64;
    const int wn   = (wid & 3) * 32;
    const int s = blockIdx.x / 6;                 // 0=q, 1=k, 2=v
    __half* hb = (s == 0) ? g_qh : (s == 1) ? g_kh : g_vh;

    #pragma unroll
    for (int mi = 0; mi < 4; mi++) {
        int m0 = bm + wm + mi * 16 + (lane >> 2);
        #pragma unroll
        for (int nj = 0; nj < 4; nj++) {
            int o  = bn + wn + nj * 8 + (lane & 3) * 2;
            int rl = o - s * DIM;
            int h = rl >> 6, d = rl & 63;
            float b0 = bias[o], b1 = bias[o + 1];
            #pragma unroll
            for (int rr = 0; rr < 2; rr++) {
                int m  = m0 + rr * 8;
                int bb = m >> 10, nn = m & 1023;
                float v0 = acc[mi][nj][rr * 2 + 0] + b0;
                float v1 = acc[mi][nj][rr * 2 + 1] + b1;
                size_t idx = ((size_t)(bb * NHEAD + h) * SEQ + nn) * HDIM + d;
                if (s == 0) {
                    *(uint32_t*)&hb[idx] = pack2_f16(v0 * QSCALE, v1 * QSCALE);
                } else if (s == 1) {
                    *(uint32_t*)&hb[idx] = pack2_f16(v0, v1);
                } else {
                    uint32_t hi, lo;
                    split2_f16(v0, v1, hi, lo);
                    *(uint32_t*)&hb[idx] = hi;
                    *(uint32_t*)&g_vl[idx] = lo;
                }
            }
        }
    }
}

// GEMM 2: out = att @ w_proj^T + b_proj. MI=4, 1-term.
__global__ __launch_bounds__(256, 2)
void gemm_proj_mma(const float* __restrict__ bias, float* __restrict__ out)
{
    extern __shared__ __align__(128) char smem[];
    const int bm = blockIdx.y * 128, bn = blockIdx.x * 128;
    float acc[4][4][4];
    f16_mainloop<4>(g_ath, g_wph, bm, bn, smem_to_u32(smem), acc);

    const int lane = threadIdx.x & 31;
    const int wid  = threadIdx.x >> 5;
    const int wm   = (wid >> 2) * 64;
    const int wn   = (wid & 3) * 32;

    #pragma unroll
    for (int mi = 0; mi < 4; mi++) {
        int m0 = bm + wm + mi * 16 + (lane >> 2);
        #pragma unroll
        for (int nj = 0; nj < 4; nj++) {
            int o = bn + wn + nj * 8 + (lane & 3) * 2;
            float b0 = bias[o], b1 = bias[o + 1];
            #pragma unroll
            for (int rr = 0; rr < 2; rr++) {
                int m = m0 + rr * 8;
                float2 v = make_float2(acc[mi][nj][rr * 2 + 0] + b0,
                                       acc[mi][nj][rr * 2 + 1] + b1);
                *(float2*)&out[(size_t)m * DIM + o] = v;
            }
        }
    }
}

// ---------------------------------------------------------------------------
// Flash attention: S = Qh·Kh, O += Ph·(Vh+Vl). exp2 via MUFU (ex2.approx).
// Stage = Kh|Vh|Vl, double-buffered cp.async, warp-voted rescale skip.
// (R14/R16-validated: ~123 us.)
// ---------------------------------------------------------------------------
#define KB 64
#define ATLDB 144
#define ATILE (KB * ATLDB)             // 9216 per tile
#define ASTAGE (3 * ATILE)             // 27648 per stage (Kh|Vh|Vl)
#define ATT_SMEM (2 * ASTAGE)          // 55296 dynamic

__global__ __launch_bounds__(256, 2)
void attn_mma()
{
    extern __shared__ __align__(128) char smem[];
    const uint32_t sb = smem_to_u32(smem);
    const int tid  = threadIdx.x;
    const int lane = tid & 31;
    const int wid  = tid >> 5;
    const int wm   = wid * 16;
    const int bh   = blockIdx.x;
    const int bb   = bh / NHEAD;
    const int h    = bh - bb * NHEAD;
    const int qb   = blockIdx.y;

    const size_t headoff = (size_t)bh * SEQ * HDIM;
    const size_t qoff    = headoff + (size_t)qb * 128 * HDIM;

    // ---- Stage Q hi (128x64 fp16) ----
    {
        const uint4* qh4 = (const uint4*)(g_qh + qoff);
        #pragma unroll
        for (int i = 0; i < 4; i++) {
            int idx = tid + i * 256;
            int row = idx >> 3, c = idx & 7;
            *(uint4*)(smem + row * ATLDB + c * 16) = qh4[idx];
        }
    }
    __syncthreads();

    const uint32_t a_row  = (lane & 7) + ((lane >> 3) & 1) * 8;
    const uint32_t a_kb   = ((lane >> 4) & 1) * 16;
    const uint32_t kp_row = ((lane >> 4) << 3) + (lane & 7);
    const uint32_t kp_kb  = ((lane >> 3) & 1) << 4;

    uint32_t Qh[4][4];
    #pragma unroll
    for (int k = 0; k < 4; k++) {
        uint32_t ad = sb + (wm + a_row) * ATLDB + k * 32 + a_kb;
        LDSM_X4(Qh[k][0], Qh[k][1], Qh[k][2], Qh[k][3], ad);
    }
    __syncthreads();          // Q region about to be reused as K/V stage

    float O[8][4];
    #pragma unroll
    for (int nj = 0; nj < 8; nj++)
        #pragma unroll
        for (int r = 0; r < 4; r++) O[nj][r] = 0.f;
    float m0 = -1e30f, m1 = -1e30f, l0 = 0.f, l1 = 0.f;

    auto issue_kv = [&](int t) {
        uint32_t st = sb + (uint32_t)(t & 1) * ASTAGE;
        size_t base = headoff + (size_t)t * KB * HDIM;
        #pragma unroll
        for (int i = 0; i < 2; i++) {
            int idx = tid + i * 256;
            int row = idx >> 3, col = idx & 7;
            uint32_t doff = row * ATLDB + col * 16;
            size_t goff = base + row * HDIM + col * 8;
            CP16(st + 0 * ATILE + doff, g_kh + goff);
            CP16(st + 1 * ATILE + doff, g_vh + goff);
            CP16(st + 2 * ATILE + doff, g_vl + goff);
        }
        CP_COMMIT;
    };

    issue_kv(0);

    for (int tb = 0; tb < SEQ / KB; tb++) {
        CP_WAIT0;
        __syncthreads();
        if (tb + 1 < SEQ / KB) issue_kv(tb + 1);
        uint32_t st = sb + (uint32_t)(tb & 1) * ASTAGE;

        // ---- S = Qh Kh^T, K-frag prefetch pipeline (16 flat iterations) ----
        float S[8][4];
        #pragma unroll
        for (int nj = 0; nj < 8; nj++)
            #pragma unroll
            for (int r = 0; r < 4; r++) S[nj][r] = 0.f;

        {
            uint32_t kP0, kP1, kP2, kP3;
            LDSM_X4(kP0, kP1, kP2, kP3, st + kp_row * ATLDB + kp_kb);
            #pragma unroll
            for (int it = 0; it < 16; it++) {
                const int k = it >> 2, njp = it & 3;
                uint32_t c0 = kP0, c1 = kP1, c2 = kP2, c3 = kP3;
                if (it < 15) {
                    const int k2 = (it + 1) >> 2, njp2 = (it + 1) & 3;
                    uint32_t bd = st + (njp2 * 16 + kp_row) * ATLDB + k2 * 32 + kp_kb;
                    LDSM_X4(kP0, kP1, kP2, kP3, bd);
                }
                MMA16816(S[njp * 2],     Qh[k][0], Qh[k][1], Qh[k][2], Qh[k][3], c0, c1);
                MMA16816(S[njp * 2 + 1], Qh[k][0], Qh[k][1], Qh[k][2], Qh[k][3], c2, c3);
            }
        }

        // ---- online softmax in exp2 domain (MUFU exp), voted rescale skip ----
        float bm0 = S[0][0], bm1 = S[0][2];
        #pragma unroll
        for (int nj = 0; nj < 8; nj++) {
            bm0 = fmaxf(bm0, fmaxf(S[nj][0], S[nj][1]));
            bm1 = fmaxf(bm1, fmaxf(S[nj][2], S[nj][3]));
        }
        bm0 = fmaxf(bm0, __shfl_xor_sync(0xffffffffu, bm0, 1));
        bm0 = fmaxf(bm0, __shfl_xor_sync(0xffffffffu, bm0, 2));
        bm1 = fmaxf(bm1, __shfl_xor_sync(0xffffffffu, bm1, 1));
        bm1 = fmaxf(bm1, __shfl_xor_sync(0xffffffffu, bm1, 2));
        bool grew = (bm0 > m0) | (bm1 > m1);
        if (__any_sync(0xffffffffu, grew)) {
            float nm0 = fmaxf(m0, bm0), nm1 = fmaxf(m1, bm1);
            float c0 = ex2(m0 - nm0), c1 = ex2(m1 - nm1);
            m0 = nm0; m1 = nm1;
            l0 *= c0; l1 *= c1;
            #pragma unroll
            for (int nj = 0; nj < 8; nj++) {
                O[nj][0] *= c0; O[nj][1] *= c0;
                O[nj][2] *= c1; O[nj][3] *= c1;
            }
        }

        float rs0 = 0.f, rs1 = 0.f;
        #pragma unroll
        for (int nj = 0; nj < 8; nj++) {
            S[nj][0] = ex2(S[nj][0] - m0);
            S[nj][1] = ex2(S[nj][1] - m0);
            S[nj][2] = ex2(S[nj][2] - m1);
            S[nj][3] = ex2(S[nj][3] - m1);
            rs0 += S[nj][0] + S[nj][1];
            rs1 += S[nj][2] + S[nj][3];
        }
        rs0 += __shfl_xor_sync(0xffffffffu, rs0, 1);
        rs0 += __shfl_xor_sync(0xffffffffu, rs0, 2);
        rs1 += __shfl_xor_sync(0xffffffffu, rs1, 1);
        rs1 += __shfl_xor_sync(0xffffffffu, rs1, 2);
        l0 += rs0;
        l1 += rs1;

        // ---- P (C-layout) -> fp16 A-frags, hi only ----
        uint32_t Ph[4][4];
        #pragma unroll
        for (int t = 0; t < 4; t++) {
            Ph[t][0] = pack2_f16(S[2 * t][0],     S[2 * t][1]);
            Ph[t][1] = pack2_f16(S[2 * t][2],     S[2 * t][3]);
            Ph[t][2] = pack2_f16(S[2 * t + 1][0], S[2 * t + 1][1]);
            Ph[t][3] = pack2_f16(S[2 * t + 1][2], S[2 * t + 1][3]);
        }

        // ---- O += Ph (Vh + Vl), V-frag prefetch pipeline (16 flat iters) ----
        {
            auto vAddr = [&](int it) -> uint32_t {
                const int t = it >> 2, njp = it & 3;
                return st + 1 * ATILE + (t * 16 + (lane & 15)) * ATLDB
                       + njp * 32 + ((lane >> 4) << 4);
            };
            uint32_t vh0, vh1, vh2, vh3, vl0, vl1, vl2, vl3;
            {
                uint32_t va = vAddr(0);
                LDSM_X4_T(vh0, vh1, vh2, vh3, va);
                LDSM_X4_T(vl0, vl1, vl2, vl3, va + ATILE);
            }
            #pragma unroll
            for (int it = 0; it < 16; it++) {
                const int t = it >> 2, njp = it & 3;
                uint32_t h0 = vh0, h1 = vh1, h2 = vh2, h3 = vh3;
                uint32_t q0 = vl0, q1 = vl1, q2 = vl2, q3 = vl3;
                if (it < 15) {
                    uint32_t va = vAddr(it + 1);
                    LDSM_X4_T(vh0, vh1, vh2, vh3, va);
                    LDSM_X4_T(vl0, vl1, vl2, vl3, va + ATILE);
                }
                MMA16816(O[njp * 2],     Ph[t][0], Ph[t][1], Ph[t][2], Ph[t][3], h0, h1);
                MMA16816(O[njp * 2 + 1], Ph[t][0], Ph[t][1], Ph[t][2], Ph[t][3], h2, h3);
                MMA16816(O[njp * 2],     Ph[t][0], Ph[t][1], Ph[t][2], Ph[t][3], q0, q1);
                MMA16816(O[njp * 2 + 1], Ph[t][0], Ph[t][1], Ph[t][2], Ph[t][3], q2, q3);
            }
        }
        // next iteration's sync orders stage reuse
    }

    // ---- epilogue: normalize, write fp16 hi (feeds proj GEMM A-side) ----
    float inv0 = 1.0f / l0, inv1 = 1.0f / l1;
    int row0 = qb * 128 + wm + (lane >> 2);
    int row1 = row0 + 8;
    size_t o0 = ((size_t)bb * SEQ + row0) * DIM + h * HDIM;
    size_t o1 = ((size_t)bb * SEQ + row1) * DIM + h * HDIM;
    #pragma unroll
    for (int nj = 0; nj < 8; nj++) {
        int col = nj * 8 + (lane & 3) * 2;
        *(uint32_t*)&g_ath[o0 + col] = pack2_f16(O[nj][0] * inv0, O[nj][1] * inv0);
        *(uint32_t*)&g_ath[o1 + col] = pack2_f16(O[nj][2] * inv1, O[nj][3] * inv1);
    }
}

// ---------------------------------------------------------------------------
extern "C" void kernel_launch(void* const* d_in, const int* in_sizes, int n_in,
                              void* d_out, int out_size)
{
    const float* x      = (const float*)d_in[0];
    const float* w_qkv  = (const float*)d_in[1];
    const float* b_qkv  = (const float*)d_in[2];
    const float* w_proj = (const float*)d_in[3];
    const float* b_proj = (const float*)d_in[4];
    float* out = (float*)d_out;

    cudaFuncSetAttribute(gemm_qkv_mma,  cudaFuncAttributeMaxDynamicSharedMemorySize, GEMM_SMEM);
    cudaFuncSetAttribute(gemm_proj_mma, cudaFuncAttributeMaxDynamicSharedMemorySize, GEMM_SMEM);
    cudaFuncSetAttribute(attn_mma,      cudaFuncAttributeMaxDynamicSharedMemorySize, ATT_SMEM);

    conv_all<<<(NCONV_TOTAL + 255) / 256, 256>>>(x, w_qkv, w_proj);
    gemm_qkv_mma<<<dim3(QKV_N / 128, MROWS / 128), 256, GEMM_SMEM>>>(b_qkv);
    attn_mma<<<dim3(BATCH * NHEAD, SEQ / 128), 256, ATT_SMEM>>>();
    gemm_proj_mma<<<dim3(DIM / 128, MROWS / 128), 256, GEMM_SMEM>>>(b_proj, out);
}